// round 4
// baseline (speedup 1.0000x reference)
#include <cuda_runtime.h>
#include <math.h>
#include <stdint.h>

#define D 256
#define HW 4096
#define NQ 300
#define NP 8
#define KP1 2304
#define NLAY 6

// ---------------- scratch (device globals; no allocation) ----------------
__device__ float g_Wc[D * 512];
__device__ float g_biasc[D];
__device__ float g_W2[D * 512];          // folded (w_lat . Wc)
__device__ float g_b2v[D];               // b_lat + w_lat@biasc
__device__ float g_fh[64 * D];           // pos table (row part) @ w_lat
__device__ float g_gw[64 * D];           // pos table (col part) @ w_lat
__device__ float g_wt[KP1 * D];          // conv weights [o][tap*256+c]
__device__ float g_wbig[NLAY * 768 * D]; // [l][n(768)][k]: [w_b1 | w_r1 | Wq[l]]
__device__ float g_bbig[NLAY * 768];
__device__ float g_xin[2 * HW * 512];    // transposed stageA input
__device__ float g_y[2 * HW * D];        // fused stageA+lateral out
__device__ float g_f0[2 * HW * D];       // conv feature map (channel-last)
__device__ float g_q[2 * NQ * D];
__device__ float g_big[2 * NQ * 768];    // [hb | h1 | qp]
__device__ float g_ref[2 * NQ * NP * 2];
__device__ float g_pvm[2 * NQ * D];
__device__ float g_kv[2 * NQ * D];
__device__ float g_ao[2 * NQ * D];
__device__ float g_boxes[2 * NQ * 4];

// ---------------- tf32 helpers ----------------
__device__ __forceinline__ uint32_t f2tf32(float f) {
    uint32_t u;
    asm("cvt.rna.tf32.f32 %0, %1;" : "=r"(u) : "f"(f));
    return u;
}
__device__ __forceinline__ void split_tf32(float v, uint32_t& hi, uint32_t& lo) {
    hi = f2tf32(v);
    float r = v - __uint_as_float(hi);
    lo = f2tf32(r);
}
__device__ __forceinline__ void mma_tf32(float* c, const uint32_t* a, const uint32_t* b) {
    asm volatile(
        "mma.sync.aligned.m16n8k8.row.col.f32.tf32.tf32.f32 "
        "{%0,%1,%2,%3},{%4,%5,%6,%7},{%8,%9},{%0,%1,%2,%3};"
        : "+f"(c[0]), "+f"(c[1]), "+f"(c[2]), "+f"(c[3])
        : "r"(a[0]), "r"(a[1]), "r"(a[2]), "r"(a[3]), "r"(b[0]), "r"(b[1]));
}

// ---------------- cp.async helpers ----------------
__device__ __forceinline__ void cp16(void* dst, const void* src, int bytes) {
    uint32_t d = (uint32_t)__cvta_generic_to_shared(dst);
    asm volatile("cp.async.ca.shared.global [%0], [%1], 16, %2;\n" ::"r"(d), "l"(src), "r"(bytes));
}
__device__ __forceinline__ void cp_commit() { asm volatile("cp.async.commit_group;\n"); }
__device__ __forceinline__ void cp_wait1() { asm volatile("cp.async.wait_group 1;\n"); }
__device__ __forceinline__ void cp_wait0() { asm volatile("cp.async.wait_group 0;\n"); }

// ---------------- pipelined tensor-core GEMM ----------------
// C[M,ldc-strided] = epi(alpha*A[M,K] @ W[N,K]^T + bias)
// mode 0: A row-major. mode 1: implicit im2col from g_y. mode 2: implicit bilinear sampling from g_f0.
// act: 0 none, 1 relu, 2 relu n<512, 3 relu n<256. pos: +fh/gw/b2 tables. epi 1: relu + mean over p -> g_pvm.
__global__ void __launch_bounds__(256, 2)
tc_gemm2(const float* __restrict__ A, const float* __restrict__ W,
         const float* __restrict__ bias, float* __restrict__ C,
         int M, int N, int K, float alpha, int act, int accum, int mode, int pos,
         int epi, int ldc) {
    __shared__ float sA[2][128][20];
    __shared__ float sB[2][64][20];
    int m0 = blockIdx.x * 128, n0 = blockIdx.y * 64;
    int tid = threadIdx.x;
    int warp = tid >> 5, lane = tid & 31;
    int wm = warp >> 1, wn = warp & 1;
    int g = lane >> 2, r = lane & 3;
    float acc[2][4][4] = {};
    int nk = K >> 4;

    // mode-2 per-thread row state (rows tid>>2 and tid>>2+64, fixed)
    float rx_r[2], ry_r[2];
    const float* fb_r[2];
    if (mode == 2) {
#pragma unroll
        for (int t = 0; t < 2; t++) {
            int m = m0 + (tid >> 2) + t * 64;
            if (m < M) {
                rx_r[t] = g_ref[2 * m];
                ry_r[t] = g_ref[2 * m + 1];
                int b = m / (NQ * NP);
                fb_r[t] = g_f0 + (long long)b * HW * D;
            } else {
                rx_r[t] = 0.5f; ry_r[t] = 0.5f; fb_r[t] = g_f0;
            }
        }
    }

    auto loadAsync = [&](int s, int k0) {
        if (mode != 2) {
#pragma unroll
            for (int t = 0; t < 2; t++) {
                int idx = tid + t * 256;
                int row = idx >> 2, j = idx & 3;
                int m = m0 + row;
                const float* src = A;
                int bytes = 0;
                if (mode == 0) {
                    if (m < M) { src = A + (long long)m * K + k0 + j * 4; bytes = 16; }
                } else {
                    int tap = k0 >> 8;
                    int dy = tap / 3 - 1, dx = tap % 3 - 1;
                    int h = (m >> 6) & 63, w = m & 63;
                    int hh = h + dy, ww = w + dx;
                    if ((unsigned)hh < 64u && (unsigned)ww < 64u) {
                        src = A + ((long long)(m + dy * 64 + dx)) * 256 + (k0 & 255) + j * 4;
                        bytes = 16;
                    }
                }
                cp16(&sA[s][row][j * 4], src, bytes);
            }
        }
        {
            int row = tid >> 2, j = tid & 3;
            int n = n0 + row;
            const float* src = W;
            int bytes = 0;
            if (n < N) { src = W + (long long)n * K + k0 + j * 4; bytes = 16; }
            cp16(&sB[s][row][j * 4], src, bytes);
        }
        cp_commit();
    };

    auto fillA2 = [&](int s, int k0) {
        int row0 = tid >> 2, j = tid & 3;
        int c0 = (k0 & 255) + j * 4;
        int tap = k0 >> 8;
        int dy = tap / 3, dx = tap % 3;  // 0..2
#pragma unroll
        for (int t = 0; t < 2; t++) {
            int row = row0 + t * 64;
            int m = m0 + row;
            float o0 = 0.f, o1 = 0.f, o2 = 0.f, o3 = 0.f;
            if (m < M) {
                float gy = ry_r[t] * 2.f - 1.f + (float)(dy - 1) * (2.f / 64.f);
                float yy = fminf(fmaxf((gy + 1.f) * 0.5f * 63.f, 0.f), 63.f);
                float y0f = floorf(yy);
                int y0 = (int)y0f;
                float wy = yy - y0f;
                int y1 = min(y0 + 1, 63);
                float gx = rx_r[t] * 2.f - 1.f + (float)(dx - 1) * (2.f / 64.f);
                float xx = fminf(fmaxf((gx + 1.f) * 0.5f * 63.f, 0.f), 63.f);
                float x0f = floorf(xx);
                int x0 = (int)x0f;
                float wx = xx - x0f;
                int x1 = min(x0 + 1, 63);
                const float* fb = fb_r[t];
                float4 v00 = *(const float4*)(fb + ((y0 << 6) + x0) * D + c0);
                float4 v01 = *(const float4*)(fb + ((y0 << 6) + x1) * D + c0);
                float4 v10 = *(const float4*)(fb + ((y1 << 6) + x0) * D + c0);
                float4 v11 = *(const float4*)(fb + ((y1 << 6) + x1) * D + c0);
                float w00 = (1.f - wx) * (1.f - wy), w01 = wx * (1.f - wy);
                float w10 = (1.f - wx) * wy, w11 = wx * wy;
                o0 = v00.x * w00 + v01.x * w01 + v10.x * w10 + v11.x * w11;
                o1 = v00.y * w00 + v01.y * w01 + v10.y * w10 + v11.y * w11;
                o2 = v00.z * w00 + v01.z * w01 + v10.z * w10 + v11.z * w11;
                o3 = v00.w * w00 + v01.w * w01 + v10.w * w10 + v11.w * w11;
            }
            sA[s][row][j * 4 + 0] = o0;
            sA[s][row][j * 4 + 1] = o1;
            sA[s][row][j * 4 + 2] = o2;
            sA[s][row][j * 4 + 3] = o3;
        }
    };

    loadAsync(0, 0);
    if (mode == 2) fillA2(0, 0);
    for (int kt = 0; kt < nk; kt++) {
        int cur = kt & 1;
        if (kt + 1 < nk) { loadAsync(cur ^ 1, (kt + 1) << 4); cp_wait1(); }
        else cp_wait0();
        __syncthreads();
#pragma unroll
        for (int ks = 0; ks < 2; ks++) {
            int kb = ks * 8;
            uint32_t ah[2][4], al[2][4], bh[4][2], bl[4][2];
#pragma unroll
            for (int mt = 0; mt < 2; mt++) {
                int rb = wm * 32 + mt * 16;
                split_tf32(sA[cur][rb + g][kb + r], ah[mt][0], al[mt][0]);
                split_tf32(sA[cur][rb + g + 8][kb + r], ah[mt][1], al[mt][1]);
                split_tf32(sA[cur][rb + g][kb + r + 4], ah[mt][2], al[mt][2]);
                split_tf32(sA[cur][rb + g + 8][kb + r + 4], ah[mt][3], al[mt][3]);
            }
#pragma unroll
            for (int nt = 0; nt < 4; nt++) {
                int cb = wn * 32 + nt * 8;
                split_tf32(sB[cur][cb + g][kb + r], bh[nt][0], bl[nt][0]);
                split_tf32(sB[cur][cb + g][kb + r + 4], bh[nt][1], bl[nt][1]);
            }
#pragma unroll
            for (int mt = 0; mt < 2; mt++)
#pragma unroll
                for (int nt = 0; nt < 4; nt++) {
                    mma_tf32(acc[mt][nt], ah[mt], bh[nt]);
                    mma_tf32(acc[mt][nt], al[mt], bh[nt]);
                    mma_tf32(acc[mt][nt], ah[mt], bl[nt]);
                }
        }
        if (mode == 2 && kt + 1 < nk) fillA2(cur ^ 1, (kt + 1) << 4);
        __syncthreads();
    }

    if (epi == 1) {
        // relu + mean over p (8 rows = g lanes) -> g_pvm
#pragma unroll
        for (int mt = 0; mt < 2; mt++) {
            int rbase = m0 + wm * 32 + mt * 16;
#pragma unroll
            for (int nt = 0; nt < 4; nt++) {
                int n = n0 + wn * 32 + nt * 8 + 2 * r;
#pragma unroll
                for (int e = 0; e < 4; e++) {
                    int nn = n + (e & 1);
                    float v = fmaxf(acc[mt][nt][e] + bias[nn], 0.f);
                    v += __shfl_xor_sync(0xffffffffu, v, 4);
                    v += __shfl_xor_sync(0xffffffffu, v, 8);
                    v += __shfl_xor_sync(0xffffffffu, v, 16);
                    if (g == 0) {
                        int q = (rbase >> 3) + ((e >= 2) ? 1 : 0);
                        if (q < 2 * NQ) g_pvm[q * D + nn] = v * 0.125f;
                    }
                }
            }
        }
        return;
    }
#pragma unroll
    for (int mt = 0; mt < 2; mt++) {
        int rbase = m0 + wm * 32 + mt * 16;
#pragma unroll
        for (int nt = 0; nt < 4; nt++) {
            int cbase = n0 + wn * 32 + nt * 8 + 2 * r;
#pragma unroll
            for (int e = 0; e < 4; e++) {
                int m = rbase + g + ((e >= 2) ? 8 : 0);
                int n = cbase + (e & 1);
                if (m < M && n < N) {
                    float v = acc[mt][nt][e] * alpha;
                    if (bias) v += bias[n];
                    if (act == 1 || (act == 2 && n < 512) || (act == 3 && n < 256))
                        v = fmaxf(v, 0.f);
                    if (pos) {
                        int hw = m & 4095;
                        int h = hw >> 6, w = hw & 63;
                        v += g_fh[h * D + n] + g_gw[w * D + n] + g_b2v[n];
                    }
                    if (accum) C[(long long)m * ldc + n] += v;
                    else       C[(long long)m * ldc + n] = v;
                }
            }
        }
    }
}

// ---------------- prep kernels ----------------
__global__ void prep_wc(const float* __restrict__ w_tf, const float* __restrict__ b_tf,
                        const float* __restrict__ w_in, const float* __restrict__ b_in) {
    int idx = blockIdx.x * blockDim.x + threadIdx.x;
    if (idx < 4 * D * 128) {
        int s = idx >> 15;
        int rr = idx & 32767;
        int n = rr >> 7;
        int i = rr & 127;
        float acc = 0.f;
        for (int c = 0; c < 128; c++) {
            const float* w3 = w_tf + (c * 128 + i) * 3;
            float coeff;
            if (s == 0)      coeff = w3[0] + w3[1];
            else if (s == 3) coeff = w3[1] + w3[2];
            else             coeff = w3[0] + w3[1] + w3[2];
            acc += w_in[n * 128 + c] * coeff;
        }
        g_Wc[n * 512 + s * 128 + i] = 0.25f * acc;
    }
    if (idx < D) {
        float a = b_in[idx];
        for (int c = 0; c < 128; c++) a += w_in[idx * 128 + c] * b_tf[c];
        g_biasc[idx] = a;
    }
}

// fold lateral: W2[o][k] = sum_c w_lat0[o][c] * Wc[c][k]
__global__ void prep_W2(const float* __restrict__ w_lat) {
    int idx = blockIdx.x * blockDim.x + threadIdx.x;
    if (idx >= D * 512) return;
    int o = idx >> 9, k = idx & 511;
    float s = 0.f;
    for (int c = 0; c < 256; c++) s += w_lat[o * 256 + c] * g_Wc[c * 512 + k];
    g_W2[idx] = s;
}

// pos tables: fh[h][o] = py(h)@w_lat_rowpart ; gw[w][o] = px(w)@w_lat_colpart ; b2v
__global__ void prep_tables(const float* __restrict__ w_lat, const float* __restrict__ b_lat) {
    int h = blockIdx.x;   // 64
    int o = threadIdx.x;  // 256
    float sf = 0.f, sg = 0.f;
    for (int c = 0; c < 128; c++) {
        int i = c >> 1;
        float fl = (float)(i >> 1);
        float dimt = exp2f(fl * 0.415241011861f);  // 10000^(fl/32)
        float arg = (float)(h + 1) * (6.2831853071795864769f / (64.f + 1e-6f)) / dimt;
        float val = (c & 1) ? cosf(arg) : sinf(arg);
        sf += val * w_lat[o * 256 + c];
        sg += val * w_lat[o * 256 + 128 + c];
    }
    g_fh[h * D + o] = sf;
    g_gw[h * D + o] = sg;
    if (h == 0) {
        float b = b_lat[o];
        for (int c = 0; c < 256; c++) b += w_lat[o * 256 + c] * g_biasc[c];
        g_b2v[o] = b;
    }
}

__global__ void prep_wt(const float* __restrict__ w_sm) {
    int idx = blockIdx.x * blockDim.x + threadIdx.x;
    if (idx >= KP1 * D) return;
    int o = idx / KP1;
    int rr = idx % KP1;
    int tap = rr >> 8;
    int c = rr & 255;
    g_wt[idx] = w_sm[(o * D + c) * 9 + tap];
}

__global__ void prep_wbig(const float* __restrict__ w_b1, const float* __restrict__ b_b1,
                          const float* __restrict__ w_r1, const float* __restrict__ b_r1,
                          const float* __restrict__ Wq, const float* __restrict__ bq) {
    int idx = blockIdx.x * blockDim.x + threadIdx.x;
    if (idx < NLAY * 768 * D) {
        int l = idx / (768 * D);
        int rr = idx % (768 * D);
        int n = rr >> 8;
        int k = rr & 255;
        float v;
        if (n < 256)      v = w_b1[n * 256 + k];
        else if (n < 512) v = w_r1[(n - 256) * 256 + k];
        else              v = Wq[(l * 256 + (n - 512)) * 256 + k];
        g_wbig[idx] = v;
    }
    if (idx < NLAY * 768) {
        int l = idx / 768, n = idx % 768;
        g_bbig[idx] = (n < 256) ? b_b1[n] : ((n < 512) ? b_r1[n - 256] : bq[l * 256 + n - 512]);
    }
}

// transpose feat [b][512][4096] -> g_xin [b][4096][512]
__global__ void transposeA(const float* __restrict__ feat) {
    __shared__ float t[32][33];
    int b = blockIdx.z;
    int hw0 = blockIdx.x * 32, k0 = blockIdx.y * 32;
    const float* src = feat + (long long)b * 512 * HW;
    float* dst = g_xin + (long long)b * HW * 512;
    int tx = threadIdx.x, ty = threadIdx.y;
#pragma unroll
    for (int j = 0; j < 4; j++)
        t[ty + j * 8][tx] = src[(long long)(k0 + ty + j * 8) * HW + hw0 + tx];
    __syncthreads();
#pragma unroll
    for (int j = 0; j < 4; j++)
        dst[(long long)(hw0 + ty + j * 8) * 512 + k0 + tx] = t[tx][ty + j * 8];
}

// ---------------- decoder small kernels ----------------
__global__ void init_q(const float* __restrict__ qe, const float* __restrict__ qp) {
    int idx = blockIdx.x * blockDim.x + threadIdx.x;
    if (idx >= 2 * NQ * D) return;
    int qd = idx % (NQ * D);
    g_q[idx] = qe[qd] + qp[qd];
}

__global__ void init_boxes(const float* __restrict__ pbi) {
    int idx = blockIdx.x * blockDim.x + threadIdx.x;
    if (idx < 2 * NQ * 4) g_boxes[idx] = pbi[idx];
}

__global__ void roref_kernel(const float* __restrict__ w_r2, const float* __restrict__ b_r2) {
    int bq = blockIdx.x;
    int tid = threadIdx.x;  // 128
    __shared__ float hrow[256];
    __shared__ float ro[16];
    hrow[tid] = g_big[bq * 768 + 256 + tid];
    hrow[tid + 128] = g_big[bq * 768 + 256 + tid + 128];
    __syncthreads();
    int warp = tid >> 5, lane = tid & 31;
#pragma unroll
    for (int jj = 0; jj < 4; jj++) {
        int j = warp * 4 + jj;
        float s = 0.f;
        for (int k = lane; k < 256; k += 32) s += hrow[k] * w_r2[j * 256 + k];
#pragma unroll
        for (int o = 16; o; o >>= 1) s += __shfl_xor_sync(0xffffffffu, s, o);
        if (lane == 0) ro[j] = tanhf(s + b_r2[j]);
    }
    __syncthreads();
    if (tid < 8) {
        float bx = g_boxes[bq * 4 + 0], by = g_boxes[bq * 4 + 1];
        float rx = fminf(fmaxf(bx + 0.5f * ro[2 * tid + 0], 0.f), 1.f);
        float ry = fminf(fmaxf(by + 0.5f * ro[2 * tid + 1], 0.f), 1.f);
        g_ref[(bq * 8 + tid) * 2 + 0] = rx;
        g_ref[(bq * 8 + tid) * 2 + 1] = ry;
    }
}

// ---------------- fused attention ----------------
__global__ void attn_kernel() {
    __shared__ float qs[8][260];
    __shared__ float kvs[16][264];
    __shared__ float tr[8][528];
    int b = blockIdx.y, qt = blockIdx.x;
    int tid = threadIdx.x;
    int warp = tid >> 5, lane = tid & 31;
    const float* kvb = g_kv + (long long)b * NQ * D;
#pragma unroll
    for (int i = 0; i < 8; i++) {
        int idx = tid + i * 256;
        int qi = idx >> 8, c = idx & 255;
        int q = qt * 8 + qi;
        qs[qi][c] = (q < NQ) ? g_big[((long long)b * NQ + q) * 768 + 512 + c] : 0.f;
    }
    float sc[19];
#pragma unroll
    for (int kt = 0; kt < 19; kt++) {
        __syncthreads();
#pragma unroll
        for (int i = 0; i < 16; i++) {
            int idx = tid + i * 256;
            int j = idx >> 8, c = idx & 255;
            int key = kt * 16 + j;
            kvs[j][c] = (key < NQ) ? kvb[(long long)key * D + c] : 0.f;
        }
        __syncthreads();
        float p[16] = {};
#pragma unroll
        for (int i = 0; i < 8; i++) {
            float qv = qs[warp][i * 32 + lane];
#pragma unroll
            for (int j = 0; j < 16; j++) p[j] += qv * kvs[j][i * 32 + lane];
        }
#pragma unroll
        for (int j = 0; j < 16; j++) tr[warp][j * 33 + lane] = p[j];
        __syncwarp();
        if (lane < 16) {
            float s = 0.f;
#pragma unroll
            for (int x = 0; x < 32; x++) s += tr[warp][lane * 33 + x];
            sc[kt] = (kt * 16 + lane < NQ) ? s * 0.0625f : -1e30f;
        }
        __syncwarp();
    }
    float m = -1e30f;
    if (lane < 16) {
#pragma unroll
        for (int kt = 0; kt < 19; kt++) m = fmaxf(m, sc[kt]);
    }
#pragma unroll
    for (int o = 16; o; o >>= 1) m = fmaxf(m, __shfl_xor_sync(0xffffffffu, m, o));
    float sum = 0.f;
    if (lane < 16) {
#pragma unroll
        for (int kt = 0; kt < 19; kt++) {
            float e = expf(sc[kt] - m);
            sc[kt] = e;
            sum += e;
        }
    }
#pragma unroll
    for (int o = 16; o; o >>= 1) sum += __shfl_xor_sync(0xffffffffu, sum, o);
    float inv = 1.f / sum;
    if (lane < 16) {
#pragma unroll
        for (int kt = 0; kt < 19; kt++) tr[warp][kt * 16 + lane] = sc[kt] * inv;
    }
    __syncwarp();
    float out[8] = {};
#pragma unroll
    for (int kt = 0; kt < 19; kt++) {
        __syncthreads();
#pragma unroll
        for (int i = 0; i < 16; i++) {
            int idx = tid + i * 256;
            int j = idx >> 8, c = idx & 255;
            int key = kt * 16 + j;
            kvs[j][c] = (key < NQ) ? kvb[(long long)key * D + c] : 0.f;
        }
        __syncthreads();
#pragma unroll
        for (int j = 0; j < 16; j++) {
            float a = tr[warp][kt * 16 + j];
#pragma unroll
            for (int i = 0; i < 8; i++) out[i] += a * kvs[j][i * 32 + lane];
        }
    }
    int q = qt * 8 + warp;
    if (q < NQ) {
#pragma unroll
        for (int i = 0; i < 8; i++)
            g_ao[((long long)b * NQ + q) * D + i * 32 + lane] = out[i];
    }
}

__global__ void boxupd_kernel(const float* __restrict__ w_b2, const float* __restrict__ b_b2) {
    int bq = blockIdx.x;
    int tid = threadIdx.x;  // 128
    __shared__ float hrow[256];
    hrow[tid] = g_big[bq * 768 + tid];
    hrow[tid + 128] = g_big[bq * 768 + tid + 128];
    __syncthreads();
    int warp = tid >> 5, lane = tid & 31;
    float s = 0.f;
    for (int k = lane; k < 256; k += 32) s += hrow[k] * w_b2[warp * 256 + k];
#pragma unroll
    for (int o = 16; o; o >>= 1) s += __shfl_xor_sync(0xffffffffu, s, o);
    if (lane == 0) {
        float delta = 1.f / (1.f + expf(-(s + b_b2[warp])));
        float nb = g_boxes[bq * 4 + warp] + 0.1f * tanhf(delta - 0.5f);
        g_boxes[bq * 4 + warp] = fminf(fmaxf(nb, 0.f), 1.f);
    }
}

__global__ void cls_kernel(const float* __restrict__ w_cls, const float* __restrict__ b_cls,
                           float* __restrict__ out) {
    int bq = blockIdx.x;
    int lane = threadIdx.x;  // 32
    float s = 0.f;
    for (int k = lane; k < 256; k += 32) s += g_q[bq * 256 + k] * w_cls[k];
#pragma unroll
    for (int o = 16; o; o >>= 1) s += __shfl_xor_sync(0xffffffffu, s, o);
    if (lane == 0) out[bq] = s + b_cls[0];
}

__global__ void copy_boxes(float* __restrict__ out) {
    int idx = blockIdx.x * blockDim.x + threadIdx.x;
    if (idx < 2 * NQ * 4) out[600 + idx] = g_boxes[idx];
}

// ---------------- host ----------------
static void gemm(const float* A, const float* W, const float* bias, float* C,
                 int M, int N, int K, float alpha, int act, int accum, int mode, int pos,
                 int epi, int ldc) {
    dim3 grid((M + 127) / 128, (N + 63) / 64);
    tc_gemm2<<<grid, 256>>>(A, W, bias, C, M, N, K, alpha, act, accum, mode, pos, epi, ldc);
}

extern "C" void kernel_launch(void* const* d_in, const int* in_sizes, int n_in,
                              void* d_out, int out_size) {
    const float* feat   = (const float*)d_in[0];
    const float* pbi    = (const float*)d_in[1];
    const float* w_tf   = (const float*)d_in[2];
    const float* b_tf   = (const float*)d_in[3];
    const float* w_in   = (const float*)d_in[4];
    const float* b_in   = (const float*)d_in[5];
    const float* w_lat  = (const float*)d_in[6];
    const float* b_lat  = (const float*)d_in[7];
    const float* w_sm   = (const float*)d_in[8];
    const float* b_sm   = (const float*)d_in[9];
    const float* q_embed= (const float*)d_in[10];
    const float* q_pos  = (const float*)d_in[11];
    const float* bqv    = (const float*)d_in[13];
    const float* Wq     = (const float*)d_in[12];
    const float* Wo     = (const float*)d_in[14];
    const float* bo     = (const float*)d_in[15];
    const float* Wp1    = (const float*)d_in[16];
    const float* bp1    = (const float*)d_in[17];
    const float* Wp2    = (const float*)d_in[18];
    const float* bp2    = (const float*)d_in[19];
    const float* w_r1   = (const float*)d_in[20];
    const float* b_r1   = (const float*)d_in[21];
    const float* w_r2   = (const float*)d_in[22];
    const float* b_r2   = (const float*)d_in[23];
    const float* w_b1   = (const float*)d_in[24];
    const float* b_b1   = (const float*)d_in[25];
    const float* w_b2   = (const float*)d_in[26];
    const float* b_b2   = (const float*)d_in[27];
    const float* w_cls  = (const float*)d_in[28];
    const float* b_cls  = (const float*)d_in[29];
    float* out = (float*)d_out;

    float *p_W2, *p_wt, *p_wbig, *p_bbig, *p_xin, *p_y, *p_f0;
    float *p_q, *p_big, *p_pvm, *p_kv, *p_ao;
    cudaGetSymbolAddress((void**)&p_W2, g_W2);
    cudaGetSymbolAddress((void**)&p_wt, g_wt);
    cudaGetSymbolAddress((void**)&p_wbig, g_wbig);
    cudaGetSymbolAddress((void**)&p_bbig, g_bbig);
    cudaGetSymbolAddress((void**)&p_xin, g_xin);
    cudaGetSymbolAddress((void**)&p_y, g_y);
    cudaGetSymbolAddress((void**)&p_f0, g_f0);
    cudaGetSymbolAddress((void**)&p_q, g_q);
    cudaGetSymbolAddress((void**)&p_big, g_big);
    cudaGetSymbolAddress((void**)&p_pvm, g_pvm);
    cudaGetSymbolAddress((void**)&p_kv, g_kv);
    cudaGetSymbolAddress((void**)&p_ao, g_ao);

    // backbone (only scale-1 FPN branch is live)
    prep_wc<<<(4 * D * 128 + 255) / 256, 256>>>(w_tf, b_tf, w_in, b_in);
    prep_wt<<<(KP1 * D + 255) / 256, 256>>>(w_sm);
    prep_wbig<<<(NLAY * 768 * D + 255) / 256, 256>>>(w_b1, b_b1, w_r1, b_r1, Wq, bqv);
    prep_W2<<<(D * 512 + 255) / 256, 256>>>(w_lat);
    prep_tables<<<64, 256>>>(w_lat, b_lat);
    transposeA<<<dim3(128, 16, 2), dim3(32, 8)>>>(feat);
    // fused stageA + lateral (+pos tables)
    gemm(p_xin, p_W2, nullptr, p_y, 2 * HW, D, 512, 1.f, 0, 0, 0, 1 /*pos*/, 0, D);
    // conv 3x3 (implicit im2col)
    gemm(p_y, p_wt, b_sm, p_f0, 2 * HW, D, KP1, 1.f, 0, 0, 1, 0, 0, D);

    init_q<<<(2 * NQ * D + 255) / 256, 256>>>(q_embed, q_pos);
    init_boxes<<<(2 * NQ * 4 + 255) / 256, 256>>>(pbi);

    // pre-loop: h1,qp for layer 0 into g_big cols 256..767
    gemm(p_q, p_wbig + 256 * D, p_bbig + 256, p_big + 256,
         2 * NQ, 512, D, 1.f, 3 /*relu n<256*/, 0, 0, 0, 0, 768);

    for (int l = 0; l < NLAY; l++) {
        roref_kernel<<<2 * NQ, 128>>>(w_r2, b_r2);
        // fused: sample + Wp1 + relu + mean_p  -> g_pvm
        gemm(p_f0, Wp1 + (long long)l * D * KP1, bp1 + l * D, nullptr,
             2 * NQ * NP, D, KP1, 1.f, 0, 0, 2 /*sample*/, 0, 1 /*mean epi*/, D);
        gemm(p_pvm, Wp2 + (long long)l * D * D, bp2 + l * D, p_kv,
             2 * NQ, D, D, 1.f, 0, 0, 0, 0, 0, D);
        attn_kernel<<<dim3(38, 2), 256>>>();
        gemm(p_ao, Wo + (long long)l * D * D, bo + l * D, p_q,
             2 * NQ, D, D, 1.f, 0, 1 /*accum*/, 0, 0, 0, D);
        if (l < NLAY - 1) {
            // [hb | h1(l+1) | qp(l+1)]
            gemm(p_q, p_wbig + (long long)(l + 1) * 768 * D, p_bbig + (l + 1) * 768, p_big,
                 2 * NQ, 768, D, 1.f, 2 /*relu n<512*/, 0, 0, 0, 0, 768);
        } else {
            gemm(p_q, p_wbig, p_bbig, p_big, 2 * NQ, 256, D, 1.f, 1, 0, 0, 0, 0, 768);
        }
        boxupd_kernel<<<2 * NQ, 128>>>(w_b2, b_b2);
    }

    cls_kernel<<<2 * NQ, 32>>>(w_cls, b_cls, out);
    copy_boxes<<<(2 * NQ * 4 + 255) / 256, 256>>>(out);
}

// round 5
// speedup vs baseline: 1.2029x; 1.2029x over previous
#include <cuda_runtime.h>
#include <cuda_bf16.h>
#include <math.h>
#include <stdint.h>

#define D 256
#define HW 4096
#define NQ 300
#define NP 8
#define KP1 2304
#define NLAY 6

typedef __nv_bfloat16 bf16;

// plane strides
#define S_XIN ((long long)2 * HW * 512)
#define S_Y   ((long long)2 * HW * 256)
#define S_FLAT ((long long)2 * NQ * NP * KP1)
#define S_PVM ((long long)2 * NQ * 256)
#define S_Q   ((long long)2 * NQ * 256)
#define S_AO  ((long long)2 * NQ * 256)
#define S_W2  ((long long)256 * 512)
#define S_WT  ((long long)256 * KP1)
#define S_WP1 ((long long)NLAY * 256 * KP1)
#define S_WP2 ((long long)NLAY * 256 * 256)
#define S_WO  ((long long)NLAY * 256 * 256)
#define S_WBIG ((long long)NLAY * 768 * 256)

// ---------------- scratch (device globals; no allocation) ----------------
__device__ float g_Wc[D * 512];
__device__ float g_biasc[D];
__device__ float g_W2[D * 512];
__device__ float g_b2v[D];
__device__ float g_fh[64 * D];
__device__ float g_gw[64 * D];
__device__ float g_wt[KP1 * D];
__device__ float g_wbig[NLAY * 768 * D];
__device__ float g_bbig[NLAY * 768];
// bf16 split planes (hi at offset 0, lo at +stride)
__device__ bf16 g_W2s[2 * S_W2];
__device__ bf16 g_wts[2 * S_WT];
__device__ bf16 g_Wp1s[2 * S_WP1];
__device__ bf16 g_Wp2s[2 * S_WP2];
__device__ bf16 g_Wos[2 * S_WO];
__device__ bf16 g_wbigs[2 * S_WBIG];
__device__ bf16 g_xins[2 * S_XIN];
__device__ bf16 g_ys[2 * S_Y];
__device__ bf16 g_flats[2 * S_FLAT];
__device__ bf16 g_pvms[2 * S_PVM];
__device__ bf16 g_qs[2 * S_Q];
__device__ bf16 g_aos[2 * S_AO];
// fp32 tensors
__device__ float g_f0[2 * HW * D];
__device__ float g_q[2 * NQ * D];
__device__ float g_big[2 * NQ * 768];
__device__ float g_ref[2 * NQ * NP * 2];
__device__ float g_kv[2 * NQ * D];
__device__ float g_boxes[2 * NQ * 4];

__device__ __forceinline__ void wsplit(bf16* h, bf16* l, float v) {
    bf16 hh = __float2bfloat16(v);
    *h = hh;
    *l = __float2bfloat16(v - __bfloat162float(hh));
}

__device__ __forceinline__ void mma_bf16(float* c, const uint32_t* a, const uint32_t* b) {
    asm volatile(
        "mma.sync.aligned.m16n8k16.row.col.f32.bf16.bf16.f32 "
        "{%0,%1,%2,%3},{%4,%5,%6,%7},{%8,%9},{%0,%1,%2,%3};"
        : "+f"(c[0]), "+f"(c[1]), "+f"(c[2]), "+f"(c[3])
        : "r"(a[0]), "r"(a[1]), "r"(a[2]), "r"(a[3]), "r"(b[0]), "r"(b[1]));
}

__device__ __forceinline__ void cp16(void* dst, const void* src, int bytes) {
    uint32_t d = (uint32_t)__cvta_generic_to_shared(dst);
    asm volatile("cp.async.ca.shared.global [%0], [%1], 16, %2;\n" ::"r"(d), "l"(src), "r"(bytes));
}
__device__ __forceinline__ void cp_commit() { asm volatile("cp.async.commit_group;\n"); }
__device__ __forceinline__ void cp_wait1() { asm volatile("cp.async.wait_group 1;\n"); }
__device__ __forceinline__ void cp_wait0() { asm volatile("cp.async.wait_group 0;\n"); }

// ---------------- bf16x3 tensor-core GEMM ----------------
// C = epi(A @ W^T + bias), A/W given as bf16 hi/lo planes (lo at +sA/+sW).
// mode 0: A row-major. mode 1: implicit 3x3 im2col from g_ys layout.
// act: 0 none, 1 relu, 2 relu n<512. pos: add pos tables. 
// epi: 0 store fp32 C; 1 relu+mean_p -> split OS; 2 accum C + split OS; 3 split OS only.
__global__ void __launch_bounds__(256, 2)
tc_gemm3(const bf16* __restrict__ A, long long sA,
         const bf16* __restrict__ W, long long sW,
         const float* __restrict__ bias, float* __restrict__ C, int ldc,
         bf16* __restrict__ OS, long long sOS,
         int M, int N, int K, int act, int accum, int mode, int pos, int epi) {
    __shared__ uint32_t sAh[2][128][12], sAl[2][128][12];
    __shared__ uint32_t sBh[2][64][12], sBl[2][64][12];
    int m0 = blockIdx.x * 128, n0 = blockIdx.y * 64;
    int tid = threadIdx.x;
    int warp = tid >> 5, lane = tid & 31;
    int wm = warp >> 1, wn = warp & 1;
    int g = lane >> 2, r = lane & 3;
    float acc[2][4][4] = {};
    int nk = K >> 4;

    auto load = [&](int s, int k0) {
        {   // A: 2 planes, each thread does one row-chunk in both planes
            int row = tid >> 1, ch = tid & 1;
            int m = m0 + row;
            const bf16 *srcH = A, *srcL = A;
            int bytes = 0;
            if (mode == 0) {
                if (m < M) {
                    long long off = (long long)m * K + k0 + ch * 8;
                    srcH = A + off; srcL = A + sA + off;
                    bytes = 16;
                }
            } else {
                int tap = k0 >> 8;
                int dy = tap / 3 - 1, dx = tap % 3 - 1;
                int h = (m >> 6) & 63, w = m & 63;
                int hh = h + dy, ww = w + dx;
                if (m < M && (unsigned)hh < 64u && (unsigned)ww < 64u) {
                    long long off = (long long)(m + dy * 64 + dx) * 256 + (k0 & 255) + ch * 8;
                    srcH = A + off; srcL = A + sA + off;
                    bytes = 16;
                }
            }
            cp16(&sAh[s][row][ch * 4], srcH, bytes);
            cp16(&sAl[s][row][ch * 4], srcL, bytes);
        }
        {   // B: 256 threads cover 64 rows x 2 chunks x 2 planes
            int p = tid >> 7;
            int row = (tid >> 1) & 63, ch = tid & 1;
            int n = n0 + row;
            const bf16* src = W;
            int bytes = 0;
            if (n < N) {
                src = W + (long long)p * sW + (long long)n * K + k0 + ch * 8;
                bytes = 16;
            }
            if (p) cp16(&sBl[s][row][ch * 4], src, bytes);
            else   cp16(&sBh[s][row][ch * 4], src, bytes);
        }
        cp_commit();
    };

    load(0, 0);
    for (int kt = 0; kt < nk; kt++) {
        int cur = kt & 1;
        if (kt + 1 < nk) { load(cur ^ 1, (kt + 1) << 4); cp_wait1(); }
        else cp_wait0();
        __syncthreads();
        uint32_t ah[2][4], al[2][4], bh[4][2], bl[4][2];
#pragma unroll
        for (int mt = 0; mt < 2; mt++) {
            int rb = wm * 32 + mt * 16;
            ah[mt][0] = sAh[cur][rb + g][r];
            ah[mt][1] = sAh[cur][rb + g + 8][r];
            ah[mt][2] = sAh[cur][rb + g][r + 4];
            ah[mt][3] = sAh[cur][rb + g + 8][r + 4];
            al[mt][0] = sAl[cur][rb + g][r];
            al[mt][1] = sAl[cur][rb + g + 8][r];
            al[mt][2] = sAl[cur][rb + g][r + 4];
            al[mt][3] = sAl[cur][rb + g + 8][r + 4];
        }
#pragma unroll
        for (int nt = 0; nt < 4; nt++) {
            int cb = wn * 32 + nt * 8;
            bh[nt][0] = sBh[cur][cb + g][r];
            bh[nt][1] = sBh[cur][cb + g][r + 4];
            bl[nt][0] = sBl[cur][cb + g][r];
            bl[nt][1] = sBl[cur][cb + g][r + 4];
        }
#pragma unroll
        for (int mt = 0; mt < 2; mt++)
#pragma unroll
            for (int nt = 0; nt < 4; nt++) {
                mma_bf16(acc[mt][nt], ah[mt], bh[nt]);
                mma_bf16(acc[mt][nt], al[mt], bh[nt]);
                mma_bf16(acc[mt][nt], ah[mt], bl[nt]);
            }
        __syncthreads();
    }

    if (epi == 1) {  // relu + mean over 8 points -> split OS
#pragma unroll
        for (int mt = 0; mt < 2; mt++) {
            int rbase = m0 + wm * 32 + mt * 16;
#pragma unroll
            for (int nt = 0; nt < 4; nt++) {
                int n = n0 + wn * 32 + nt * 8 + 2 * r;
#pragma unroll
                for (int e = 0; e < 4; e++) {
                    int nn = n + (e & 1);
                    float v = fmaxf(acc[mt][nt][e] + bias[nn], 0.f);
                    v += __shfl_xor_sync(0xffffffffu, v, 4);
                    v += __shfl_xor_sync(0xffffffffu, v, 8);
                    v += __shfl_xor_sync(0xffffffffu, v, 16);
                    if (g == 0) {
                        int q = (rbase >> 3) + ((e >= 2) ? 1 : 0);
                        if (q < 2 * NQ) {
                            long long o = (long long)q * 256 + nn;
                            wsplit(OS + o, OS + sOS + o, v * 0.125f);
                        }
                    }
                }
            }
        }
        return;
    }
#pragma unroll
    for (int mt = 0; mt < 2; mt++) {
        int rbase = m0 + wm * 32 + mt * 16;
#pragma unroll
        for (int nt = 0; nt < 4; nt++) {
            int cbase = n0 + wn * 32 + nt * 8 + 2 * r;
#pragma unroll
            for (int e = 0; e < 4; e++) {
                int m = rbase + g + ((e >= 2) ? 8 : 0);
                int n = cbase + (e & 1);
                if (m < M && n < N) {
                    float v = acc[mt][nt][e];
                    if (bias) v += bias[n];
                    if (act == 1 || (act == 2 && n < 512)) v = fmaxf(v, 0.f);
                    if (pos) {
                        int hw = m & 4095;
                        v += g_fh[(hw >> 6) * D + n] + g_gw[(hw & 63) * D + n] + g_b2v[n];
                    }
                    if (epi == 3) {
                        long long o = (long long)m * N + n;
                        wsplit(OS + o, OS + sOS + o, v);
                    } else {
                        if (accum) v += C[(long long)m * ldc + n];
                        C[(long long)m * ldc + n] = v;
                        if (epi == 2) {
                            long long o = (long long)m * N + n;
                            wsplit(OS + o, OS + sOS + o, v);
                        }
                    }
                }
            }
        }
    }
}

// ---------------- prep kernels ----------------
__global__ void prep_wc(const float* __restrict__ w_tf, const float* __restrict__ b_tf,
                        const float* __restrict__ w_in, const float* __restrict__ b_in) {
    int idx = blockIdx.x * blockDim.x + threadIdx.x;
    if (idx < 4 * D * 128) {
        int s = idx >> 15;
        int rr = idx & 32767;
        int n = rr >> 7;
        int i = rr & 127;
        float acc = 0.f;
        for (int c = 0; c < 128; c++) {
            const float* w3 = w_tf + (c * 128 + i) * 3;
            float coeff;
            if (s == 0)      coeff = w3[0] + w3[1];
            else if (s == 3) coeff = w3[1] + w3[2];
            else             coeff = w3[0] + w3[1] + w3[2];
            acc += w_in[n * 128 + c] * coeff;
        }
        g_Wc[n * 512 + s * 128 + i] = 0.25f * acc;
    }
    if (idx < D) {
        float a = b_in[idx];
        for (int c = 0; c < 128; c++) a += w_in[idx * 128 + c] * b_tf[c];
        g_biasc[idx] = a;
    }
}

__global__ void prep_W2(const float* __restrict__ w_lat) {
    int idx = blockIdx.x * blockDim.x + threadIdx.x;
    if (idx >= D * 512) return;
    int o = idx >> 9, k = idx & 511;
    float s = 0.f;
#pragma unroll 4
    for (int c = 0; c < 256; c++) s += w_lat[o * 256 + c] * g_Wc[c * 512 + k];
    g_W2[idx] = s;
}

__global__ void prep_tables(const float* __restrict__ w_lat, const float* __restrict__ b_lat) {
    int h = blockIdx.x;
    int o = threadIdx.x;
    float sf = 0.f, sg = 0.f;
    for (int c = 0; c < 128; c++) {
        int i = c >> 1;
        float fl = (float)(i >> 1);
        float dimt = exp2f(fl * 0.415241011861f);
        float arg = (float)(h + 1) * (6.2831853071795864769f / (64.f + 1e-6f)) / dimt;
        float val = (c & 1) ? cosf(arg) : sinf(arg);
        sf += val * w_lat[o * 256 + c];
        sg += val * w_lat[o * 256 + 128 + c];
    }
    g_fh[h * D + o] = sf;
    g_gw[h * D + o] = sg;
    if (h == 0) {
        float b = b_lat[o];
        for (int c = 0; c < 256; c++) b += w_lat[o * 256 + c] * g_biasc[c];
        g_b2v[o] = b;
    }
}

__global__ void prep_wt(const float* __restrict__ w_sm) {
    int idx = blockIdx.x * blockDim.x + threadIdx.x;
    if (idx >= KP1 * D) return;
    int o = idx / KP1;
    int rr = idx % KP1;
    g_wt[idx] = w_sm[(o * D + (rr & 255)) * 9 + (rr >> 8)];
}

__global__ void prep_wbig(const float* __restrict__ w_b1, const float* __restrict__ b_b1,
                          const float* __restrict__ w_r1, const float* __restrict__ b_r1,
                          const float* __restrict__ Wq, const float* __restrict__ bq) {
    int idx = blockIdx.x * blockDim.x + threadIdx.x;
    if (idx < NLAY * 768 * D) {
        int l = idx / (768 * D);
        int rr = idx % (768 * D);
        int n = rr >> 8;
        int k = rr & 255;
        float v;
        if (n < 256)      v = w_b1[n * 256 + k];
        else if (n < 512) v = w_r1[(n - 256) * 256 + k];
        else              v = Wq[(l * 256 + (n - 512)) * 256 + k];
        g_wbig[idx] = v;
    }
    if (idx < NLAY * 768) {
        int l = idx / 768, n = idx % 768;
        g_bbig[idx] = (n < 256) ? b_b1[n] : ((n < 512) ? b_r1[n - 256] : bq[l * 256 + n - 512]);
    }
}

__global__ void splitk(const float* __restrict__ src, bf16* __restrict__ h,
                       bf16* __restrict__ l, int n) {
    int i = blockIdx.x * blockDim.x + threadIdx.x;
    if (i < n) {
        float v = src[i];
        bf16 hh = __float2bfloat16(v);
        h[i] = hh;
        l[i] = __float2bfloat16(v - __bfloat162float(hh));
    }
}

// transpose feat [b][512][4096] -> split planes [b*4096][512]
__global__ void transposeA(const float* __restrict__ feat) {
    __shared__ float t[32][33];
    int b = blockIdx.z;
    int hw0 = blockIdx.x * 32, k0 = blockIdx.y * 32;
    const float* src = feat + (long long)b * 512 * HW;
    int tx = threadIdx.x, ty = threadIdx.y;
#pragma unroll
    for (int j = 0; j < 4; j++)
        t[ty + j * 8][tx] = src[(long long)(k0 + ty + j * 8) * HW + hw0 + tx];
    __syncthreads();
#pragma unroll
    for (int j = 0; j < 4; j++) {
        long long o = (long long)(b * HW + hw0 + ty + j * 8) * 512 + k0 + tx;
        wsplit(g_xins + o, g_xins + S_XIN + o, t[tx][ty + j * 8]);
    }
}

// ---------------- decoder small kernels ----------------
__global__ void init_q(const float* __restrict__ qe, const float* __restrict__ qp) {
    int idx = blockIdx.x * blockDim.x + threadIdx.x;
    if (idx >= 2 * NQ * D) return;
    int qd = idx % (NQ * D);
    float v = qe[qd] + qp[qd];
    g_q[idx] = v;
    wsplit(g_qs + idx, g_qs + S_Q + idx, v);
}

__global__ void init_boxes(const float* __restrict__ pbi) {
    int idx = blockIdx.x * blockDim.x + threadIdx.x;
    if (idx < 2 * NQ * 4) g_boxes[idx] = pbi[idx];
}

__global__ void roref_kernel(const float* __restrict__ w_r2, const float* __restrict__ b_r2) {
    int bq = blockIdx.x;
    int tid = threadIdx.x;
    __shared__ float hrow[256];
    __shared__ float ro[16];
    hrow[tid] = g_big[bq * 768 + 256 + tid];
    hrow[tid + 128] = g_big[bq * 768 + 256 + tid + 128];
    __syncthreads();
    int warp = tid >> 5, lane = tid & 31;
#pragma unroll
    for (int jj = 0; jj < 4; jj++) {
        int j = warp * 4 + jj;
        float s = 0.f;
        for (int k = lane; k < 256; k += 32) s += hrow[k] * w_r2[j * 256 + k];
#pragma unroll
        for (int o = 16; o; o >>= 1) s += __shfl_xor_sync(0xffffffffu, s, o);
        if (lane == 0) ro[j] = tanhf(s + b_r2[j]);
    }
    __syncthreads();
    if (tid < 8) {
        float bx = g_boxes[bq * 4 + 0], by = g_boxes[bq * 4 + 1];
        float rx = fminf(fmaxf(bx + 0.5f * ro[2 * tid + 0], 0.f), 1.f);
        float ry = fminf(fmaxf(by + 0.5f * ro[2 * tid + 1], 0.f), 1.f);
        g_ref[(bq * 8 + tid) * 2 + 0] = rx;
        g_ref[(bq * 8 + tid) * 2 + 1] = ry;
    }
}

// bilinear-sample 3x3 patch x 256 ch per (b,q,p) -> split planes of g_flats
__global__ void sample_kernel() {
    int bqp = blockIdx.x;      // 4800
    int c = threadIdx.x;       // 256
    int b = bqp / (NQ * NP);
    float rx = g_ref[bqp * 2 + 0];
    float ry = g_ref[bqp * 2 + 1];
    const float* f = g_f0 + (long long)b * HW * D;
    long long base = (long long)bqp * KP1;
#pragma unroll
    for (int cy = 0; cy < 3; cy++) {
        float gy = ry * 2.f - 1.f + (float)(cy - 1) * (2.f / 64.f);
        float yy = fminf(fmaxf((gy + 1.f) * 0.5f * 63.f, 0.f), 63.f);
        float y0f = floorf(yy);
        int y0 = (int)y0f;
        float wy = yy - y0f;
        int y1 = min(y0 + 1, 63);
#pragma unroll
        for (int cx = 0; cx < 3; cx++) {
            float gx = rx * 2.f - 1.f + (float)(cx - 1) * (2.f / 64.f);
            float xx = fminf(fmaxf((gx + 1.f) * 0.5f * 63.f, 0.f), 63.f);
            float x0f = floorf(xx);
            int x0 = (int)x0f;
            float wx = xx - x0f;
            int x1 = min(x0 + 1, 63);
            float v00 = f[((y0 << 6) + x0) * D + c];
            float v01 = f[((y0 << 6) + x1) * D + c];
            float v10 = f[((y1 << 6) + x0) * D + c];
            float v11 = f[((y1 << 6) + x1) * D + c];
            float v = v00 * (1.f - wx) * (1.f - wy) + v01 * wx * (1.f - wy)
                    + v10 * (1.f - wx) * wy + v11 * wx * wy;
            long long o = base + (cy * 3 + cx) * D + c;
            wsplit(g_flats + o, g_flats + S_FLAT + o, v);
        }
    }
}

// ---------------- fused attention ----------------
__global__ void attn_kernel() {
    __shared__ float qs[8][260];
    __shared__ float kvs[16][264];
    __shared__ float tr[8][528];
    int b = blockIdx.y, qt = blockIdx.x;
    int tid = threadIdx.x;
    int warp = tid >> 5, lane = tid & 31;
    const float* kvb = g_kv + (long long)b * NQ * D;
#pragma unroll
    for (int i = 0; i < 8; i++) {
        int idx = tid + i * 256;
        int qi = idx >> 8, c = idx & 255;
        int q = qt * 8 + qi;
        qs[qi][c] = (q < NQ) ? g_big[((long long)b * NQ + q) * 768 + 512 + c] : 0.f;
    }
    float sc[19];
#pragma unroll
    for (int kt = 0; kt < 19; kt++) {
        __syncthreads();
#pragma unroll
        for (int i = 0; i < 16; i++) {
            int idx = tid + i * 256;
            int j = idx >> 8, c = idx & 255;
            int key = kt * 16 + j;
            kvs[j][c] = (key < NQ) ? kvb[(long long)key * D + c] : 0.f;
        }
        __syncthreads();
        float p[16] = {};
#pragma unroll
        for (int i = 0; i < 8; i++) {
            float qv = qs[warp][i * 32 + lane];
#pragma unroll
            for (int j = 0; j < 16; j++) p[j] += qv * kvs[j][i * 32 + lane];
        }
#pragma unroll
        for (int j = 0; j < 16; j++) tr[warp][j * 33 + lane] = p[j];
        __syncwarp();
        if (lane < 16) {
            float s = 0.f;
#pragma unroll
            for (int x = 0; x < 32; x++) s += tr[warp][lane * 33 + x];
            sc[kt] = (kt * 16 + lane < NQ) ? s * 0.0625f : -1e30f;
        }
        __syncwarp();
    }
    float m = -1e30f;
    if (lane < 16) {
#pragma unroll
        for (int kt = 0; kt < 19; kt++) m = fmaxf(m, sc[kt]);
    }
#pragma unroll
    for (int o = 16; o; o >>= 1) m = fmaxf(m, __shfl_xor_sync(0xffffffffu, m, o));
    float sum = 0.f;
    if (lane < 16) {
#pragma unroll
        for (int kt = 0; kt < 19; kt++) {
            float e = expf(sc[kt] - m);
            sc[kt] = e;
            sum += e;
        }
    }
#pragma unroll
    for (int o = 16; o; o >>= 1) sum += __shfl_xor_sync(0xffffffffu, sum, o);
    float inv = 1.f / sum;
    if (lane < 16) {
#pragma unroll
        for (int kt = 0; kt < 19; kt++) tr[warp][kt * 16 + lane] = sc[kt] * inv;
    }
    __syncwarp();
    float out[8] = {};
#pragma unroll
    for (int kt = 0; kt < 19; kt++) {
        __syncthreads();
#pragma unroll
        for (int i = 0; i < 16; i++) {
            int idx = tid + i * 256;
            int j = idx >> 8, c = idx & 255;
            int key = kt * 16 + j;
            kvs[j][c] = (key < NQ) ? kvb[(long long)key * D + c] : 0.f;
        }
        __syncthreads();
#pragma unroll
        for (int j = 0; j < 16; j++) {
            float a = tr[warp][kt * 16 + j];
#pragma unroll
            for (int i = 0; i < 8; i++) out[i] += a * kvs[j][i * 32 + lane];
        }
    }
    int q = qt * 8 + warp;
    if (q < NQ) {
#pragma unroll
        for (int i = 0; i < 8; i++) {
            long long o = ((long long)b * NQ + q) * D + i * 32 + lane;
            wsplit(g_aos + o, g_aos + S_AO + o, out[i]);
        }
    }
}

__global__ void boxupd_kernel(const float* __restrict__ w_b2, const float* __restrict__ b_b2) {
    int bq = blockIdx.x;
    int tid = threadIdx.x;
    __shared__ float hrow[256];
    hrow[tid] = g_big[bq * 768 + tid];
    hrow[tid + 128] = g_big[bq * 768 + tid + 128];
    __syncthreads();
    int warp = tid >> 5, lane = tid & 31;
    float s = 0.f;
    for (int k = lane; k < 256; k += 32) s += hrow[k] * w_b2[warp * 256 + k];
#pragma unroll
    for (int o = 16; o; o >>= 1) s += __shfl_xor_sync(0xffffffffu, s, o);
    if (lane == 0) {
        float delta = 1.f / (1.f + expf(-(s + b_b2[warp])));
        float nb = g_boxes[bq * 4 + warp] + 0.1f * tanhf(delta - 0.5f);
        g_boxes[bq * 4 + warp] = fminf(fmaxf(nb, 0.f), 1.f);
    }
}

__global__ void cls_kernel(const float* __restrict__ w_cls, const float* __restrict__ b_cls,
                           float* __restrict__ out) {
    int bq = blockIdx.x;
    int lane = threadIdx.x;
    float s = 0.f;
    for (int k = lane; k < 256; k += 32) s += g_q[bq * 256 + k] * w_cls[k];
#pragma unroll
    for (int o = 16; o; o >>= 1) s += __shfl_xor_sync(0xffffffffu, s, o);
    if (lane == 0) out[bq] = s + b_cls[0];
}

__global__ void copy_boxes(float* __restrict__ out) {
    int idx = blockIdx.x * blockDim.x + threadIdx.x;
    if (idx < 2 * NQ * 4) out[600 + idx] = g_boxes[idx];
}

// ---------------- host ----------------
static void gemm3(const bf16* A, long long sA, const bf16* W, long long sW,
                  const float* bias, float* C, int ldc, bf16* OS, long long sOS,
                  int M, int N, int K, int act, int accum, int mode, int pos, int epi) {
    dim3 grid((M + 127) / 128, (N + 63) / 64);
    tc_gemm3<<<grid, 256>>>(A, sA, W, sW, bias, C, ldc, OS, sOS,
                            M, N, K, act, accum, mode, pos, epi);
}

extern "C" void kernel_launch(void* const* d_in, const int* in_sizes, int n_in,
                              void* d_out, int out_size) {
    const float* feat   = (const float*)d_in[0];
    const float* pbi    = (const float*)d_in[1];
    const float* w_tf   = (const float*)d_in[2];
    const float* b_tf   = (const float*)d_in[3];
    const float* w_in   = (const float*)d_in[4];
    const float* b_in   = (const float*)d_in[5];
    const float* w_lat  = (const float*)d_in[6];
    const float* b_lat  = (const float*)d_in[7];
    const float* w_sm   = (const float*)d_in[8];
    const float* b_sm   = (const float*)d_in[9];
    const float* q_embed= (const float*)d_in[10];
    const float* q_pos  = (const float*)d_in[11];
    const float* Wq     = (const float*)d_in[12];
    const float* bqv    = (const float*)d_in[13];
    const float* Wo     = (const float*)d_in[14];
    const float* bo     = (const float*)d_in[15];
    const float* Wp1    = (const float*)d_in[16];
    const float* bp1    = (const float*)d_in[17];
    const float* Wp2    = (const float*)d_in[18];
    const float* bp2    = (const float*)d_in[19];
    const float* w_r1   = (const float*)d_in[20];
    const float* b_r1   = (const float*)d_in[21];
    const float* w_r2   = (const float*)d_in[22];
    const float* b_r2   = (const float*)d_in[23];
    const float* w_b1   = (const float*)d_in[24];
    const float* b_b1   = (const float*)d_in[25];
    const float* w_b2   = (const float*)d_in[26];
    const float* b_b2   = (const float*)d_in[27];
    const float* w_cls  = (const float*)d_in[28];
    const float* b_cls  = (const float*)d_in[29];
    float* out = (float*)d_out;

    float *p_W2, *p_wt, *p_wbig, *p_bbig, *p_f0, *p_q, *p_big, *p_kv;
    bf16 *p_W2s, *p_wts, *p_Wp1s, *p_Wp2s, *p_Wos, *p_wbigs;
    bf16 *p_xins, *p_ys, *p_flats, *p_pvms, *p_qs, *p_aos;
    cudaGetSymbolAddress((void**)&p_W2, g_W2);
    cudaGetSymbolAddress((void**)&p_wt, g_wt);
    cudaGetSymbolAddress((void**)&p_wbig, g_wbig);
    cudaGetSymbolAddress((void**)&p_bbig, g_bbig);
    cudaGetSymbolAddress((void**)&p_f0, g_f0);
    cudaGetSymbolAddress((void**)&p_q, g_q);
    cudaGetSymbolAddress((void**)&p_big, g_big);
    cudaGetSymbolAddress((void**)&p_kv, g_kv);
    cudaGetSymbolAddress((void**)&p_W2s, g_W2s);
    cudaGetSymbolAddress((void**)&p_wts, g_wts);
    cudaGetSymbolAddress((void**)&p_Wp1s, g_Wp1s);
    cudaGetSymbolAddress((void**)&p_Wp2s, g_Wp2s);
    cudaGetSymbolAddress((void**)&p_Wos, g_Wos);
    cudaGetSymbolAddress((void**)&p_wbigs, g_wbigs);
    cudaGetSymbolAddress((void**)&p_xins, g_xins);
    cudaGetSymbolAddress((void**)&p_ys, g_ys);
    cudaGetSymbolAddress((void**)&p_flats, g_flats);
    cudaGetSymbolAddress((void**)&p_pvms, g_pvms);
    cudaGetSymbolAddress((void**)&p_qs, g_qs);
    cudaGetSymbolAddress((void**)&p_aos, g_aos);

    // ---- prep ----
    prep_wc<<<(4 * D * 128 + 255) / 256, 256>>>(w_tf, b_tf, w_in, b_in);
    prep_wt<<<(KP1 * D + 255) / 256, 256>>>(w_sm);
    prep_wbig<<<(NLAY * 768 * D + 255) / 256, 256>>>(w_b1, b_b1, w_r1, b_r1, Wq, bqv);
    prep_W2<<<(D * 512 + 255) / 256, 256>>>(w_lat);
    prep_tables<<<64, 256>>>(w_lat, b_lat);
    // splits
    splitk<<<(int)((S_W2 + 255) / 256), 256>>>(p_W2, p_W2s, p_W2s + S_W2, (int)S_W2);
    splitk<<<(int)((S_WT + 255) / 256), 256>>>(p_wt, p_wts, p_wts + S_WT, (int)S_WT);
    splitk<<<(int)((S_WP1 + 255) / 256), 256>>>(Wp1, p_Wp1s, p_Wp1s + S_WP1, (int)S_WP1);
    splitk<<<(int)((S_WP2 + 255) / 256), 256>>>(Wp2, p_Wp2s, p_Wp2s + S_WP2, (int)S_WP2);
    splitk<<<(int)((S_WO + 255) / 256), 256>>>(Wo, p_Wos, p_Wos + S_WO, (int)S_WO);
    splitk<<<(int)((S_WBIG + 255) / 256), 256>>>(p_wbig, p_wbigs, p_wbigs + S_WBIG, (int)S_WBIG);
    transposeA<<<dim3(128, 16, 2), dim3(32, 8)>>>(feat);

    // ---- backbone ----
    // fused stageA + lateral + pos -> split g_ys
    gemm3(p_xins, S_XIN, p_W2s, S_W2, nullptr, nullptr, 256, p_ys, S_Y,
          2 * HW, 256, 512, 0, 0, 0, 1, 3);
    // conv 3x3 (implicit im2col) -> fp32 g_f0
    gemm3(p_ys, S_Y, p_wts, S_WT, b_sm, p_f0, 256, nullptr, 0,
          2 * HW, 256, KP1, 0, 0, 1, 0, 0);

    init_q<<<(2 * NQ * D + 255) / 256, 256>>>(q_embed, q_pos);
    init_boxes<<<(2 * NQ * 4 + 255) / 256, 256>>>(pbi);

    // pre-loop: h1,qp for layer 0 -> g_big cols 256..767
    gemm3(p_qs, S_Q, p_wbigs + 256 * 256, S_WBIG, p_bbig + 256, p_big + 256, 768,
          nullptr, 0, 2 * NQ, 512, 256, 2, 0, 0, 0, 0);

    for (int l = 0; l < NLAY; l++) {
        roref_kernel<<<2 * NQ, 128>>>(w_r2, b_r2);
        sample_kernel<<<2 * NQ * NP, 256>>>();
        // Wp1 + relu + mean_p -> split g_pvms
        gemm3(p_flats, S_FLAT, p_Wp1s + (long long)l * 256 * KP1, S_WP1, bp1 + l * D,
              nullptr, 256, p_pvms, S_PVM, 2 * NQ * NP, 256, KP1, 0, 0, 0, 0, 1);
        // Wp2 -> fp32 g_kv
        gemm3(p_pvms, S_PVM, p_Wp2s + (long long)l * 256 * 256, S_WP2, bp2 + l * D,
              p_kv, 256, nullptr, 0, 2 * NQ, 256, 256, 0, 0, 0, 0, 0);
        attn_kernel<<<dim3(38, 2), 256>>>();
        // Wo: accum into g_q + split mirror g_qs
        gemm3(p_aos, S_AO, p_Wos + (long long)l * 256 * 256, S_WO, bo + l * D,
              p_q, 256, p_qs, S_Q, 2 * NQ, 256, 256, 0, 1, 0, 0, 2);
        if (l < NLAY - 1) {
            gemm3(p_qs, S_Q, p_wbigs + (long long)(l + 1) * 768 * 256, S_WBIG,
                  p_bbig + (l + 1) * 768, p_big, 768, nullptr, 0,
                  2 * NQ, 768, 256, 2, 0, 0, 0, 0);
        } else {
            gemm3(p_qs, S_Q, p_wbigs, S_WBIG, p_bbig, p_big, 768, nullptr, 0,
                  2 * NQ, 256, 256, 1, 0, 0, 0, 0);
        }
        boxupd_kernel<<<2 * NQ, 128>>>(w_b2, b_b2);
    }

    cls_kernel<<<2 * NQ, 32>>>(w_cls, b_cls, out);
    copy_boxes<<<(2 * NQ * 4 + 255) / 256, 256>>>(out);
}

// round 6
// speedup vs baseline: 1.2942x; 1.0759x over previous
#include <cuda_runtime.h>
#include <cuda_bf16.h>
#include <math.h>
#include <stdint.h>

#define D 256
#define HW 4096
#define NQ 300
#define NP 8
#define KP1 2304
#define NLAY 6

typedef __nv_bfloat16 bf16;

// plane strides
#define S_XIN ((long long)2 * HW * 512)
#define S_Y   ((long long)2 * HW * 256)
#define S_FLAT ((long long)2 * NQ * NP * KP1)
#define S_PVM ((long long)2 * NQ * 256)
#define S_Q   ((long long)2 * NQ * 256)
#define S_AO  ((long long)2 * NQ * 256)
#define S_W2  ((long long)256 * 512)
#define S_WT  ((long long)256 * KP1)
#define S_WP1 ((long long)NLAY * 256 * KP1)
#define S_WP2 ((long long)NLAY * 256 * 256)
#define S_WO  ((long long)NLAY * 256 * 256)
#define S_WBIG ((long long)NLAY * 768 * 256)

// ---------------- scratch (device globals; no allocation) ----------------
__device__ float g_Wc[D * 512];
__device__ float g_biasc[D];
__device__ float g_W2[D * 512];
__device__ float g_b2v[D];
__device__ float g_fh[64 * D];
__device__ float g_gw[64 * D];
__device__ float g_wt[KP1 * D];
__device__ float g_wbig[NLAY * 768 * D];
__device__ float g_bbig[NLAY * 768];
// bf16 split planes (hi at offset 0, lo at +stride)
__device__ bf16 g_W2s[2 * S_W2];
__device__ bf16 g_wts[2 * S_WT];
__device__ bf16 g_Wp1s[2 * S_WP1];
__device__ bf16 g_Wp2s[2 * S_WP2];
__device__ bf16 g_Wos[2 * S_WO];
__device__ bf16 g_wbigs[2 * S_WBIG];
__device__ bf16 g_xins[2 * S_XIN];
__device__ bf16 g_ys[2 * S_Y];
__device__ bf16 g_flats[2 * S_FLAT];
__device__ bf16 g_pvms[2 * S_PVM];
__device__ bf16 g_qs[2 * S_Q];
__device__ bf16 g_aos[2 * S_AO];
// fp32 tensors
__device__ float g_f0[2 * HW * D];
__device__ float g_q[2 * NQ * D];
__device__ float g_big[2 * NQ * 768];
__device__ float g_ref[2 * NQ * NP * 2];
__device__ float g_kv[2 * NQ * D];
__device__ float g_boxes[2 * NQ * 4];

__device__ __forceinline__ void wsplit(bf16* h, bf16* l, float v) {
    bf16 hh = __float2bfloat16(v);
    *h = hh;
    *l = __float2bfloat16(v - __bfloat162float(hh));
}

__device__ __forceinline__ void mma_bf16(float* c, const uint32_t* a, const uint32_t* b) {
    asm volatile(
        "mma.sync.aligned.m16n8k16.row.col.f32.bf16.bf16.f32 "
        "{%0,%1,%2,%3},{%4,%5,%6,%7},{%8,%9},{%0,%1,%2,%3};"
        : "+f"(c[0]), "+f"(c[1]), "+f"(c[2]), "+f"(c[3])
        : "r"(a[0]), "r"(a[1]), "r"(a[2]), "r"(a[3]), "r"(b[0]), "r"(b[1]));
}

__device__ __forceinline__ void cp16(void* dst, const void* src, int bytes) {
    uint32_t d = (uint32_t)__cvta_generic_to_shared(dst);
    asm volatile("cp.async.ca.shared.global [%0], [%1], 16, %2;\n" ::"r"(d), "l"(src), "r"(bytes));
}
__device__ __forceinline__ void cp_commit() { asm volatile("cp.async.commit_group;\n"); }
__device__ __forceinline__ void cp_wait2() { asm volatile("cp.async.wait_group 2;\n"); }
__device__ __forceinline__ void cp_wait1() { asm volatile("cp.async.wait_group 1;\n"); }
__device__ __forceinline__ void cp_wait0() { asm volatile("cp.async.wait_group 0;\n"); }

// ---------------- bf16x3 tensor-core GEMM, 3-stage cp.async pipeline ----------------
// C = epi(A @ W^T + bias), A/W given as bf16 hi/lo planes (lo at +sA/+sW).
// mode 0: A row-major. mode 1: implicit 3x3 im2col from g_ys layout.
// act: 0 none, 1 relu, 2 relu n<512.  pos: add pos tables.
// epi: 0 store fp32 C; 1 relu+mean_p -> split OS; 2 accum C + split OS; 3 split OS only.
template <int MT>
__global__ void __launch_bounds__(256, 2)
tc_gemm3(const bf16* __restrict__ A, long long sA,
         const bf16* __restrict__ W, long long sW,
         const float* __restrict__ bias, float* __restrict__ C, int ldc,
         bf16* __restrict__ OS, long long sOS,
         int M, int N, int K, int act, int accum, int mode, int pos, int epi) {
    constexpr int MSUB = MT / 4;      // rows per warp-group (32 or 16)
    constexpr int NMT = MT / 64;      // m-subtiles per warp (2 or 1)
    __shared__ uint32_t sAh[3][MT][12], sAl[3][MT][12];
    __shared__ uint32_t sBh[3][64][12], sBl[3][64][12];
    int m0 = blockIdx.x * MT, n0 = blockIdx.y * 64;
    int tid = threadIdx.x;
    int warp = tid >> 5, lane = tid & 31;
    int wm = warp >> 1, wn = warp & 1;
    int g = lane >> 2, r = lane & 3;
    float acc[NMT][4][4] = {};
    int nk = K >> 4;

    auto load = [&](int s, int k0) {
        // ---- A tile ----
        if (MT == 128) {
            int row = tid >> 1, ch = tid & 1;
            int m = m0 + row;
            long long off = 0;
            int bytes = 0;
            if (mode == 0) {
                if (m < M) { off = (long long)m * K + k0 + ch * 8; bytes = 16; }
            } else {
                int tap = k0 >> 8;
                int dy = tap / 3 - 1, dx = tap % 3 - 1;
                int h = (m >> 6) & 63, w = m & 63;
                int hh = h + dy, ww = w + dx;
                if (m < M && (unsigned)hh < 64u && (unsigned)ww < 64u) {
                    off = (long long)(m + dy * 64 + dx) * 256 + (k0 & 255) + ch * 8;
                    bytes = 16;
                }
            }
            cp16(&sAh[s][row][ch * 4], A + off, bytes);
            cp16(&sAl[s][row][ch * 4], A + sA + off, bytes);
        } else {
            int p = tid >> 7;
            int row = (tid >> 1) & 63, ch = tid & 1;
            int m = m0 + row;
            long long off = 0;
            int bytes = 0;
            if (m < M) { off = (long long)m * K + k0 + ch * 8; bytes = 16; }
            if (p) cp16(&sAl[s][row][ch * 4], A + sA + off, bytes);
            else   cp16(&sAh[s][row][ch * 4], A + off, bytes);
        }
        // ---- B tile ----
        {
            int p = tid >> 7;
            int row = (tid >> 1) & 63, ch = tid & 1;
            int n = n0 + row;
            const bf16* src = W;
            int bytes = 0;
            if (n < N) {
                src = W + (long long)p * sW + (long long)n * K + k0 + ch * 8;
                bytes = 16;
            }
            if (p) cp16(&sBl[s][row][ch * 4], src, bytes);
            else   cp16(&sBh[s][row][ch * 4], src, bytes);
        }
        cp_commit();
    };

    load(0, 0);
    if (nk > 1) load(1, 16);
    for (int kt = 0; kt < nk; kt++) {
        int cur = kt % 3;
        if (kt + 2 < nk) { load((kt + 2) % 3, (kt + 2) << 4); cp_wait2(); }
        else if (kt + 1 < nk) cp_wait1();
        else cp_wait0();
        __syncthreads();
        uint32_t ah[NMT][4], al[NMT][4], bh[4][2], bl[4][2];
#pragma unroll
        for (int mt = 0; mt < NMT; mt++) {
            int rb = wm * MSUB + mt * 16;
            ah[mt][0] = sAh[cur][rb + g][r];
            ah[mt][1] = sAh[cur][rb + g + 8][r];
            ah[mt][2] = sAh[cur][rb + g][r + 4];
            ah[mt][3] = sAh[cur][rb + g + 8][r + 4];
            al[mt][0] = sAl[cur][rb + g][r];
            al[mt][1] = sAl[cur][rb + g + 8][r];
            al[mt][2] = sAl[cur][rb + g][r + 4];
            al[mt][3] = sAl[cur][rb + g + 8][r + 4];
        }
#pragma unroll
        for (int nt = 0; nt < 4; nt++) {
            int cb = wn * 32 + nt * 8;
            bh[nt][0] = sBh[cur][cb + g][r];
            bh[nt][1] = sBh[cur][cb + g][r + 4];
            bl[nt][0] = sBl[cur][cb + g][r];
            bl[nt][1] = sBl[cur][cb + g][r + 4];
        }
#pragma unroll
        for (int mt = 0; mt < NMT; mt++)
#pragma unroll
            for (int nt = 0; nt < 4; nt++) {
                mma_bf16(acc[mt][nt], ah[mt], bh[nt]);
                mma_bf16(acc[mt][nt], al[mt], bh[nt]);
                mma_bf16(acc[mt][nt], ah[mt], bl[nt]);
            }
        __syncthreads();
    }

    if (epi == 1) {  // relu + mean over 8 points -> split OS
#pragma unroll
        for (int mt = 0; mt < NMT; mt++) {
            int rbase = m0 + wm * MSUB + mt * 16;
#pragma unroll
            for (int nt = 0; nt < 4; nt++) {
                int n = n0 + wn * 32 + nt * 8 + 2 * r;
#pragma unroll
                for (int e = 0; e < 4; e++) {
                    int nn = n + (e & 1);
                    float v = fmaxf(acc[mt][nt][e] + bias[nn], 0.f);
                    v += __shfl_xor_sync(0xffffffffu, v, 4);
                    v += __shfl_xor_sync(0xffffffffu, v, 8);
                    v += __shfl_xor_sync(0xffffffffu, v, 16);
                    if (g == 0) {
                        int q = (rbase >> 3) + ((e >= 2) ? 1 : 0);
                        if (q < 2 * NQ) {
                            long long o = (long long)q * 256 + nn;
                            wsplit(OS + o, OS + sOS + o, v * 0.125f);
                        }
                    }
                }
            }
        }
        return;
    }
#pragma unroll
    for (int mt = 0; mt < NMT; mt++) {
        int rbase = m0 + wm * MSUB + mt * 16;
#pragma unroll
        for (int nt = 0; nt < 4; nt++) {
            int cbase = n0 + wn * 32 + nt * 8 + 2 * r;
#pragma unroll
            for (int e = 0; e < 4; e++) {
                int m = rbase + g + ((e >= 2) ? 8 : 0);
                int n = cbase + (e & 1);
                if (m < M && n < N) {
                    float v = acc[mt][nt][e];
                    if (bias) v += bias[n];
                    if (act == 1 || (act == 2 && n < 512)) v = fmaxf(v, 0.f);
                    if (pos) {
                        int hw = m & 4095;
                        v += g_fh[(hw >> 6) * D + n] + g_gw[(hw & 63) * D + n] + g_b2v[n];
                    }
                    if (epi == 3) {
                        long long o = (long long)m * N + n;
                        wsplit(OS + o, OS + sOS + o, v);
                    } else {
                        if (accum) v += C[(long long)m * ldc + n];
                        C[(long long)m * ldc + n] = v;
                        if (epi == 2) {
                            long long o = (long long)m * N + n;
                            wsplit(OS + o, OS + sOS + o, v);
                        }
                    }
                }
            }
        }
    }
}

// ---------------- prep kernels ----------------
__global__ void prep_wc(const float* __restrict__ w_tf, const float* __restrict__ b_tf,
                        const float* __restrict__ w_in, const float* __restrict__ b_in) {
    int idx = blockIdx.x * blockDim.x + threadIdx.x;
    if (idx < 4 * D * 128) {
        int s = idx >> 15;
        int rr = idx & 32767;
        int n = rr >> 7;
        int i = rr & 127;
        float acc = 0.f;
        for (int c = 0; c < 128; c++) {
            const float* w3 = w_tf + (c * 128 + i) * 3;
            float coeff;
            if (s == 0)      coeff = w3[0] + w3[1];
            else if (s == 3) coeff = w3[1] + w3[2];
            else             coeff = w3[0] + w3[1] + w3[2];
            acc += w_in[n * 128 + c] * coeff;
        }
        g_Wc[n * 512 + s * 128 + i] = 0.25f * acc;
    }
    if (idx < D) {
        float a = b_in[idx];
        for (int c = 0; c < 128; c++) a += w_in[idx * 128 + c] * b_tf[c];
        g_biasc[idx] = a;
    }
}

// W2[o][k] = sum_c w_lat[o][c] * Wc[c][k]  (vectorized over k)
__global__ void prep_W2(const float* __restrict__ w_lat) {
    int gid = blockIdx.x * blockDim.x + threadIdx.x;  // 32768
    if (gid >= 32768) return;
    int o = gid >> 7;
    int k4 = (gid & 127) << 2;
    float a0 = 0.f, a1 = 0.f, a2 = 0.f, a3 = 0.f;
    const float4* wc = (const float4*)g_Wc;
#pragma unroll 4
    for (int c = 0; c < 256; c++) {
        float wl = __ldg(w_lat + o * 256 + c);
        float4 v = wc[(c * 512 + k4) >> 2];
        a0 += wl * v.x; a1 += wl * v.y; a2 += wl * v.z; a3 += wl * v.w;
    }
    float4 r = make_float4(a0, a1, a2, a3);
    ((float4*)g_W2)[gid] = r;
}

__global__ void prep_tables(const float* __restrict__ w_lat, const float* __restrict__ b_lat) {
    int h = blockIdx.x;
    int o = threadIdx.x;
    float sf = 0.f, sg = 0.f;
    for (int c = 0; c < 128; c++) {
        int i = c >> 1;
        float fl = (float)(i >> 1);
        float dimt = exp2f(fl * 0.415241011861f);
        float arg = (float)(h + 1) * (6.2831853071795864769f / (64.f + 1e-6f)) / dimt;
        float val = (c & 1) ? cosf(arg) : sinf(arg);
        sf += val * w_lat[o * 256 + c];
        sg += val * w_lat[o * 256 + 128 + c];
    }
    g_fh[h * D + o] = sf;
    g_gw[h * D + o] = sg;
    if (h == 0) {
        float b = b_lat[o];
        for (int c = 0; c < 256; c++) b += w_lat[o * 256 + c] * g_biasc[c];
        g_b2v[o] = b;
    }
}

__global__ void prep_wt(const float* __restrict__ w_sm) {
    int idx = blockIdx.x * blockDim.x + threadIdx.x;
    if (idx >= KP1 * D) return;
    int o = idx / KP1;
    int rr = idx % KP1;
    g_wt[idx] = w_sm[(o * D + (rr & 255)) * 9 + (rr >> 8)];
}

__global__ void prep_wbig(const float* __restrict__ w_b1, const float* __restrict__ b_b1,
                          const float* __restrict__ w_r1, const float* __restrict__ b_r1,
                          const float* __restrict__ Wq, const float* __restrict__ bq) {
    int idx = blockIdx.x * blockDim.x + threadIdx.x;
    if (idx < NLAY * 768 * D) {
        int l = idx / (768 * D);
        int rr = idx % (768 * D);
        int n = rr >> 8;
        int k = rr & 255;
        float v;
        if (n < 256)      v = w_b1[n * 256 + k];
        else if (n < 512) v = w_r1[(n - 256) * 256 + k];
        else              v = Wq[(l * 256 + (n - 512)) * 256 + k];
        g_wbig[idx] = v;
    }
    if (idx < NLAY * 768) {
        int l = idx / 768, n = idx % 768;
        g_bbig[idx] = (n < 256) ? b_b1[n] : ((n < 512) ? b_r1[n - 256] : bq[l * 256 + n - 512]);
    }
}

__global__ void splitk(const float* __restrict__ src, bf16* __restrict__ h,
                       bf16* __restrict__ l, int n) {
    int i = blockIdx.x * blockDim.x + threadIdx.x;
    if (i < n) {
        float v = src[i];
        bf16 hh = __float2bfloat16(v);
        h[i] = hh;
        l[i] = __float2bfloat16(v - __bfloat162float(hh));
    }
}

// transpose feat [b][512][4096] -> split planes [b*4096][512]
__global__ void transposeA(const float* __restrict__ feat) {
    __shared__ float t[32][33];
    int b = blockIdx.z;
    int hw0 = blockIdx.x * 32, k0 = blockIdx.y * 32;
    const float* src = feat + (long long)b * 512 * HW;
    int tx = threadIdx.x, ty = threadIdx.y;
#pragma unroll
    for (int j = 0; j < 4; j++)
        t[ty + j * 8][tx] = src[(long long)(k0 + ty + j * 8) * HW + hw0 + tx];
    __syncthreads();
#pragma unroll
    for (int j = 0; j < 4; j++) {
        long long o = (long long)(b * HW + hw0 + ty + j * 8) * 512 + k0 + tx;
        wsplit(g_xins + o, g_xins + S_XIN + o, t[tx][ty + j * 8]);
    }
}

// ---------------- decoder small kernels ----------------
__global__ void init_q(const float* __restrict__ qe, const float* __restrict__ qp) {
    int idx = blockIdx.x * blockDim.x + threadIdx.x;
    if (idx >= 2 * NQ * D) return;
    int qd = idx % (NQ * D);
    float v = qe[qd] + qp[qd];
    g_q[idx] = v;
    wsplit(g_qs + idx, g_qs + S_Q + idx, v);
}

__global__ void init_boxes(const float* __restrict__ pbi) {
    int idx = blockIdx.x * blockDim.x + threadIdx.x;
    if (idx < 2 * NQ * 4) g_boxes[idx] = pbi[idx];
}

__global__ void roref_kernel(const float* __restrict__ w_r2, const float* __restrict__ b_r2) {
    int bq = blockIdx.x;
    int tid = threadIdx.x;
    __shared__ float hrow[256];
    __shared__ float ro[16];
    hrow[tid] = g_big[bq * 768 + 256 + tid];
    hrow[tid + 128] = g_big[bq * 768 + 256 + tid + 128];
    __syncthreads();
    int warp = tid >> 5, lane = tid & 31;
#pragma unroll
    for (int jj = 0; jj < 4; jj++) {
        int j = warp * 4 + jj;
        float s = 0.f;
        for (int k = lane; k < 256; k += 32) s += hrow[k] * w_r2[j * 256 + k];
#pragma unroll
        for (int o = 16; o; o >>= 1) s += __shfl_xor_sync(0xffffffffu, s, o);
        if (lane == 0) ro[j] = tanhf(s + b_r2[j]);
    }
    __syncthreads();
    if (tid < 8) {
        float bx = g_boxes[bq * 4 + 0], by = g_boxes[bq * 4 + 1];
        float rx = fminf(fmaxf(bx + 0.5f * ro[2 * tid + 0], 0.f), 1.f);
        float ry = fminf(fmaxf(by + 0.5f * ro[2 * tid + 1], 0.f), 1.f);
        g_ref[(bq * 8 + tid) * 2 + 0] = rx;
        g_ref[(bq * 8 + tid) * 2 + 1] = ry;
    }
}

// bilinear-sample 3x3 patch x 256 ch per (b,q,p) -> split planes of g_flats
__global__ void sample_kernel() {
    int bqp = blockIdx.x;      // 4800
    int c = threadIdx.x;       // 256
    int b = bqp / (NQ * NP);
    float rx = g_ref[bqp * 2 + 0];
    float ry = g_ref[bqp * 2 + 1];
    const float* f = g_f0 + (long long)b * HW * D;
    long long base = (long long)bqp * KP1;
#pragma unroll
    for (int cy = 0; cy < 3; cy++) {
        float gy = ry * 2.f - 1.f + (float)(cy - 1) * (2.f / 64.f);
        float yy = fminf(fmaxf((gy + 1.f) * 0.5f * 63.f, 0.f), 63.f);
        float y0f = floorf(yy);
        int y0 = (int)y0f;
        float wy = yy - y0f;
        int y1 = min(y0 + 1, 63);
#pragma unroll
        for (int cx = 0; cx < 3; cx++) {
            float gx = rx * 2.f - 1.f + (float)(cx - 1) * (2.f / 64.f);
            float xx = fminf(fmaxf((gx + 1.f) * 0.5f * 63.f, 0.f), 63.f);
            float x0f = floorf(xx);
            int x0 = (int)x0f;
            float wx = xx - x0f;
            int x1 = min(x0 + 1, 63);
            float v00 = f[((y0 << 6) + x0) * D + c];
            float v01 = f[((y0 << 6) + x1) * D + c];
            float v10 = f[((y1 << 6) + x0) * D + c];
            float v11 = f[((y1 << 6) + x1) * D + c];
            float v = v00 * (1.f - wx) * (1.f - wy) + v01 * wx * (1.f - wy)
                    + v10 * (1.f - wx) * wy + v11 * wx * wy;
            long long o = base + (cy * 3 + cx) * D + c;
            wsplit(g_flats + o, g_flats + S_FLAT + o, v);
        }
    }
}

// ---------------- fused attention ----------------
__global__ void attn_kernel() {
    __shared__ float qs[8][260];
    __shared__ float kvs[16][264];
    __shared__ float tr[8][528];
    int b = blockIdx.y, qt = blockIdx.x;
    int tid = threadIdx.x;
    int warp = tid >> 5, lane = tid & 31;
    const float* kvb = g_kv + (long long)b * NQ * D;
#pragma unroll
    for (int i = 0; i < 8; i++) {
        int idx = tid + i * 256;
        int qi = idx >> 8, c = idx & 255;
        int q = qt * 8 + qi;
        qs[qi][c] = (q < NQ) ? g_big[((long long)b * NQ + q) * 768 + 512 + c] : 0.f;
    }
    float sc[19];
#pragma unroll
    for (int kt = 0; kt < 19; kt++) {
        __syncthreads();
#pragma unroll
        for (int i = 0; i < 16; i++) {
            int idx = tid + i * 256;
            int j = idx >> 8, c = idx & 255;
            int key = kt * 16 + j;
            kvs[j][c] = (key < NQ) ? kvb[(long long)key * D + c] : 0.f;
        }
        __syncthreads();
        float p[16] = {};
#pragma unroll
        for (int i = 0; i < 8; i++) {
            float qv = qs[warp][i * 32 + lane];
#pragma unroll
            for (int j = 0; j < 16; j++) p[j] += qv * kvs[j][i * 32 + lane];
        }
#pragma unroll
        for (int j = 0; j < 16; j++) tr[warp][j * 33 + lane] = p[j];
        __syncwarp();
        if (lane < 16) {
            float s = 0.f;
#pragma unroll
            for (int x = 0; x < 32; x++) s += tr[warp][lane * 33 + x];
            sc[kt] = (kt * 16 + lane < NQ) ? s * 0.0625f : -1e30f;
        }
        __syncwarp();
    }
    float m = -1e30f;
    if (lane < 16) {
#pragma unroll
        for (int kt = 0; kt < 19; kt++) m = fmaxf(m, sc[kt]);
    }
#pragma unroll
    for (int o = 16; o; o >>= 1) m = fmaxf(m, __shfl_xor_sync(0xffffffffu, m, o));
    float sum = 0.f;
    if (lane < 16) {
#pragma unroll
        for (int kt = 0; kt < 19; kt++) {
            float e = expf(sc[kt] - m);
            sc[kt] = e;
            sum += e;
        }
    }
#pragma unroll
    for (int o = 16; o; o >>= 1) sum += __shfl_xor_sync(0xffffffffu, sum, o);
    float inv = 1.f / sum;
    if (lane < 16) {
#pragma unroll
        for (int kt = 0; kt < 19; kt++) tr[warp][kt * 16 + lane] = sc[kt] * inv;
    }
    __syncwarp();
    float out[8] = {};
#pragma unroll
    for (int kt = 0; kt < 19; kt++) {
        __syncthreads();
#pragma unroll
        for (int i = 0; i < 16; i++) {
            int idx = tid + i * 256;
            int j = idx >> 8, c = idx & 255;
            int key = kt * 16 + j;
            kvs[j][c] = (key < NQ) ? kvb[(long long)key * D + c] : 0.f;
        }
        __syncthreads();
#pragma unroll
        for (int j = 0; j < 16; j++) {
            float a = tr[warp][kt * 16 + j];
#pragma unroll
            for (int i = 0; i < 8; i++) out[i] += a * kvs[j][i * 32 + lane];
        }
    }
    int q = qt * 8 + warp;
    if (q < NQ) {
#pragma unroll
        for (int i = 0; i < 8; i++) {
            long long o = ((long long)b * NQ + q) * D + i * 32 + lane;
            wsplit(g_aos + o, g_aos + S_AO + o, out[i]);
        }
    }
}

__global__ void boxupd_kernel(const float* __restrict__ w_b2, const float* __restrict__ b_b2) {
    int bq = blockIdx.x;
    int tid = threadIdx.x;
    __shared__ float hrow[256];
    hrow[tid] = g_big[bq * 768 + tid];
    hrow[tid + 128] = g_big[bq * 768 + tid + 128];
    __syncthreads();
    int warp = tid >> 5, lane = tid & 31;
    float s = 0.f;
    for (int k = lane; k < 256; k += 32) s += hrow[k] * w_b2[warp * 256 + k];
#pragma unroll
    for (int o = 16; o; o >>= 1) s += __shfl_xor_sync(0xffffffffu, s, o);
    if (lane == 0) {
        float delta = 1.f / (1.f + expf(-(s + b_b2[warp])));
        float nb = g_boxes[bq * 4 + warp] + 0.1f * tanhf(delta - 0.5f);
        g_boxes[bq * 4 + warp] = fminf(fmaxf(nb, 0.f), 1.f);
    }
}

__global__ void cls_kernel(const float* __restrict__ w_cls, const float* __restrict__ b_cls,
                           float* __restrict__ out) {
    int bq = blockIdx.x;
    int lane = threadIdx.x;
    float s = 0.f;
    for (int k = lane; k < 256; k += 32) s += g_q[bq * 256 + k] * w_cls[k];
#pragma unroll
    for (int o = 16; o; o >>= 1) s += __shfl_xor_sync(0xffffffffu, s, o);
    if (lane == 0) out[bq] = s + b_cls[0];
}

__global__ void copy_boxes(float* __restrict__ out) {
    int idx = blockIdx.x * blockDim.x + threadIdx.x;
    if (idx < 2 * NQ * 4) out[600 + idx] = g_boxes[idx];
}

// ---------------- host ----------------
static void gemm3(int MT, const bf16* A, long long sA, const bf16* W, long long sW,
                  const float* bias, float* C, int ldc, bf16* OS, long long sOS,
                  int M, int N, int K, int act, int accum, int mode, int pos, int epi) {
    dim3 grid((M + MT - 1) / MT, (N + 63) / 64);
    if (MT == 128)
        tc_gemm3<128><<<grid, 256>>>(A, sA, W, sW, bias, C, ldc, OS, sOS,
                                     M, N, K, act, accum, mode, pos, epi);
    else
        tc_gemm3<64><<<grid, 256>>>(A, sA, W, sW, bias, C, ldc, OS, sOS,
                                    M, N, K, act, accum, mode, pos, epi);
}

extern "C" void kernel_launch(void* const* d_in, const int* in_sizes, int n_in,
                              void* d_out, int out_size) {
    const float* feat   = (const float*)d_in[0];
    const float* pbi    = (const float*)d_in[1];
    const float* w_tf   = (const float*)d_in[2];
    const float* b_tf   = (const float*)d_in[3];
    const float* w_in   = (const float*)d_in[4];
    const float* b_in   = (const float*)d_in[5];
    const float* w_lat  = (const float*)d_in[6];
    const float* b_lat  = (const float*)d_in[7];
    const float* w_sm   = (const float*)d_in[8];
    const float* b_sm   = (const float*)d_in[9];
    const float* q_embed= (const float*)d_in[10];
    const float* q_pos  = (const float*)d_in[11];
    const float* Wq     = (const float*)d_in[12];
    const float* bqv    = (const float*)d_in[13];
    const float* Wo     = (const float*)d_in[14];
    const float* bo     = (const float*)d_in[15];
    const float* Wp1    = (const float*)d_in[16];
    const float* bp1    = (const float*)d_in[17];
    const float* Wp2    = (const float*)d_in[18];
    const float* bp2    = (const float*)d_in[19];
    const float* w_r1   = (const float*)d_in[20];
    const float* b_r1   = (const float*)d_in[21];
    const float* w_r2   = (const float*)d_in[22];
    const float* b_r2   = (const float*)d_in[23];
    const float* w_b1   = (const float*)d_in[24];
    const float* b_b1   = (const float*)d_in[25];
    const float* w_b2   = (const float*)d_in[26];
    const float* b_b2   = (const float*)d_in[27];
    const float* w_cls  = (const float*)d_in[28];
    const float* b_cls  = (const float*)d_in[29];
    float* out = (float*)d_out;

    float *p_W2, *p_wt, *p_wbig, *p_bbig, *p_f0, *p_q, *p_big, *p_kv;
    bf16 *p_W2s, *p_wts, *p_Wp1s, *p_Wp2s, *p_Wos, *p_wbigs;
    bf16 *p_xins, *p_ys, *p_flats, *p_pvms, *p_qs, *p_aos;
    cudaGetSymbolAddress((void**)&p_W2, g_W2);
    cudaGetSymbolAddress((void**)&p_wt, g_wt);
    cudaGetSymbolAddress((void**)&p_wbig, g_wbig);
    cudaGetSymbolAddress((void**)&p_bbig, g_bbig);
    cudaGetSymbolAddress((void**)&p_f0, g_f0);
    cudaGetSymbolAddress((void**)&p_q, g_q);
    cudaGetSymbolAddress((void**)&p_big, g_big);
    cudaGetSymbolAddress((void**)&p_kv, g_kv);
    cudaGetSymbolAddress((void**)&p_W2s, g_W2s);
    cudaGetSymbolAddress((void**)&p_wts, g_wts);
    cudaGetSymbolAddress((void**)&p_Wp1s, g_Wp1s);
    cudaGetSymbolAddress((void**)&p_Wp2s, g_Wp2s);
    cudaGetSymbolAddress((void**)&p_Wos, g_Wos);
    cudaGetSymbolAddress((void**)&p_wbigs, g_wbigs);
    cudaGetSymbolAddress((void**)&p_xins, g_xins);
    cudaGetSymbolAddress((void**)&p_ys, g_ys);
    cudaGetSymbolAddress((void**)&p_flats, g_flats);
    cudaGetSymbolAddress((void**)&p_pvms, g_pvms);
    cudaGetSymbolAddress((void**)&p_qs, g_qs);
    cudaGetSymbolAddress((void**)&p_aos, g_aos);

    // ---- prep ----
    prep_wc<<<(4 * D * 128 + 255) / 256, 256>>>(w_tf, b_tf, w_in, b_in);
    prep_wt<<<(KP1 * D + 255) / 256, 256>>>(w_sm);
    prep_wbig<<<(NLAY * 768 * D + 255) / 256, 256>>>(w_b1, b_b1, w_r1, b_r1, Wq, bqv);
    prep_W2<<<128, 256>>>(w_lat);
    prep_tables<<<64, 256>>>(w_lat, b_lat);
    splitk<<<(int)((S_W2 + 255) / 256), 256>>>(p_W2, p_W2s, p_W2s + S_W2, (int)S_W2);
    splitk<<<(int)((S_WT + 255) / 256), 256>>>(p_wt, p_wts, p_wts + S_WT, (int)S_WT);
    splitk<<<(int)((S_WP1 + 255) / 256), 256>>>(Wp1, p_Wp1s, p_Wp1s + S_WP1, (int)S_WP1);
    splitk<<<(int)((S_WP2 + 255) / 256), 256>>>(Wp2, p_Wp2s, p_Wp2s + S_WP2, (int)S_WP2);
    splitk<<<(int)((S_WO + 255) / 256), 256>>>(Wo, p_Wos, p_Wos + S_WO, (int)S_WO);
    splitk<<<(int)((S_WBIG + 255) / 256), 256>>>(p_wbig, p_wbigs, p_wbigs + S_WBIG, (int)S_WBIG);
    transposeA<<<dim3(128, 16, 2), dim3(32, 8)>>>(feat);

    // ---- backbone ----
    gemm3(128, p_xins, S_XIN, p_W2s, S_W2, nullptr, nullptr, 256, p_ys, S_Y,
          2 * HW, 256, 512, 0, 0, 0, 1, 3);
    gemm3(128, p_ys, S_Y, p_wts, S_WT, b_sm, p_f0, 256, nullptr, 0,
          2 * HW, 256, KP1, 0, 0, 1, 0, 0);

    init_q<<<(2 * NQ * D + 255) / 256, 256>>>(q_embed, q_pos);
    init_boxes<<<(2 * NQ * 4 + 255) / 256, 256>>>(pbi);

    // pre-loop: h1,qp for layer 0 -> g_big cols 256..767
    gemm3(64, p_qs, S_Q, p_wbigs + 256 * 256, S_WBIG, p_bbig + 256, p_big + 256, 768,
          nullptr, 0, 2 * NQ, 512, 256, 2, 0, 0, 0, 0);

    for (int l = 0; l < NLAY; l++) {
        roref_kernel<<<2 * NQ, 128>>>(w_r2, b_r2);
        sample_kernel<<<2 * NQ * NP, 256>>>();
        gemm3(128, p_flats, S_FLAT, p_Wp1s + (long long)l * 256 * KP1, S_WP1, bp1 + l * D,
              nullptr, 256, p_pvms, S_PVM, 2 * NQ * NP, 256, KP1, 0, 0, 0, 0, 1);
        gemm3(64, p_pvms, S_PVM, p_Wp2s + (long long)l * 256 * 256, S_WP2, bp2 + l * D,
              p_kv, 256, nullptr, 0, 2 * NQ, 256, 256, 0, 0, 0, 0, 0);
        attn_kernel<<<dim3(38, 2), 256>>>();
        gemm3(64, p_aos, S_AO, p_Wos + (long long)l * 256 * 256, S_WO, bo + l * D,
              p_q, 256, p_qs, S_Q, 2 * NQ, 256, 256, 0, 1, 0, 0, 2);
        if (l < NLAY - 1) {
            gemm3(64, p_qs, S_Q, p_wbigs + (long long)(l + 1) * 768 * 256, S_WBIG,
                  p_bbig + (l + 1) * 768, p_big, 768, nullptr, 0,
                  2 * NQ, 768, 256, 2, 0, 0, 0, 0);
        } else {
            gemm3(64, p_qs, S_Q, p_wbigs, S_WBIG, p_bbig, p_big, 768, nullptr, 0,
                  2 * NQ, 256, 256, 1, 0, 0, 0, 0);
        }
        boxupd_kernel<<<2 * NQ, 128>>>(w_b2, b_b2);
    }

    cls_kernel<<<2 * NQ, 32>>>(w_cls, b_cls, out);
    copy_boxes<<<(2 * NQ * 4 + 255) / 256, 256>>>(out);
}

// round 7
// speedup vs baseline: 1.3422x; 1.0370x over previous
#include <cuda_runtime.h>
#include <cuda_bf16.h>
#include <math.h>
#include <stdint.h>

#define D 256
#define HW 4096
#define NQ 300
#define NP 8
#define KP1 2304
#define NLAY 6

typedef __nv_bfloat16 bf16;

// plane strides
#define S_XIN ((long long)2 * HW * 512)
#define S_Y   ((long long)2 * HW * 256)
#define S_FLAT ((long long)2 * NQ * NP * KP1)
#define S_PVM ((long long)2 * NQ * 256)
#define S_Q   ((long long)2 * NQ * 256)
#define S_AO  ((long long)2 * NQ * 256)
#define S_W2  ((long long)256 * 512)
#define S_WT  ((long long)256 * KP1)
#define S_WP1 ((long long)NLAY * 256 * KP1)
#define S_WP2 ((long long)NLAY * 256 * 256)
#define S_WO  ((long long)NLAY * 256 * 256)
#define S_WBIG ((long long)NLAY * 768 * 256)
#define S_WCT ((long long)512 * 256)
#define S_WLAT ((long long)256 * 256)

// ---------------- scratch (device globals; no allocation) ----------------
__device__ float g_biasc[D];
__device__ float g_b2v[D];
__device__ float g_fh[64 * D];
__device__ float g_gw[64 * D];
__device__ float g_bbig[NLAY * 768];
// bf16 split planes (hi at 0, lo at +stride)
__device__ bf16 g_WcTs[2 * S_WCT];
__device__ bf16 g_wlats[2 * S_WLAT];
__device__ bf16 g_W2s[2 * S_W2];
__device__ bf16 g_wts[2 * S_WT];
__device__ bf16 g_Wp1s[2 * S_WP1];
__device__ bf16 g_Wp2s[2 * S_WP2];
__device__ bf16 g_Wos[2 * S_WO];
__device__ bf16 g_wbigs[2 * S_WBIG];
__device__ bf16 g_xins[2 * S_XIN];
__device__ bf16 g_ys[2 * S_Y];
__device__ bf16 g_flats[2 * S_FLAT];
__device__ bf16 g_pvms[2 * S_PVM];
__device__ bf16 g_qs[2 * S_Q];
__device__ bf16 g_aos[2 * S_AO];
// fp32 tensors
__device__ float g_f0[2 * HW * D];
__device__ float g_q[2 * NQ * D];
__device__ float g_big[2 * NQ * 768];   // [hb | h1 | qp]
__device__ float g_kv[2 * NQ * D];
__device__ float g_boxes[2 * NQ * 4];

__device__ __forceinline__ void wsplit(bf16* h, bf16* l, float v) {
    bf16 hh = __float2bfloat16(v);
    *h = hh;
    *l = __float2bfloat16(v - __bfloat162float(hh));
}

__device__ __forceinline__ void mma_bf16(float* c, const uint32_t* a, const uint32_t* b) {
    asm volatile(
        "mma.sync.aligned.m16n8k16.row.col.f32.bf16.bf16.f32 "
        "{%0,%1,%2,%3},{%4,%5,%6,%7},{%8,%9},{%0,%1,%2,%3};"
        : "+f"(c[0]), "+f"(c[1]), "+f"(c[2]), "+f"(c[3])
        : "r"(a[0]), "r"(a[1]), "r"(a[2]), "r"(a[3]), "r"(b[0]), "r"(b[1]));
}

__device__ __forceinline__ void cp16(void* dst, const void* src, int bytes) {
    uint32_t d = (uint32_t)__cvta_generic_to_shared(dst);
    asm volatile("cp.async.ca.shared.global [%0], [%1], 16, %2;\n" ::"r"(d), "l"(src), "r"(bytes));
}
__device__ __forceinline__ void cp_commit() { asm volatile("cp.async.commit_group;\n"); }
__device__ __forceinline__ void cp_wait2() { asm volatile("cp.async.wait_group 2;\n"); }
__device__ __forceinline__ void cp_wait1() { asm volatile("cp.async.wait_group 1;\n"); }
__device__ __forceinline__ void cp_wait0() { asm volatile("cp.async.wait_group 0;\n"); }

// ---------------- bf16x3 tensor-core GEMM, 3-stage cp.async pipeline ----------------
// act: 0 none, 1 relu, 2 relu n<512, 3 relu n<256.  pos: add pos tables.
// epi: 0 fp32 C; 1 relu+mean_p -> split OS; 2 accum C + split OS; 3 split OS only.
template <int MT>
__global__ void __launch_bounds__(256, 2)
tc_gemm3(const bf16* __restrict__ A, long long sA,
         const bf16* __restrict__ W, long long sW,
         const float* __restrict__ bias, float* __restrict__ C, int ldc,
         bf16* __restrict__ OS, long long sOS,
         int M, int N, int K, int act, int accum, int mode, int pos, int epi) {
    constexpr int MSUB = MT / 4;
    constexpr int NMT = MT / 64;
    __shared__ uint32_t sAh[3][MT][12], sAl[3][MT][12];
    __shared__ uint32_t sBh[3][64][12], sBl[3][64][12];
    int m0 = blockIdx.x * MT, n0 = blockIdx.y * 64;
    int tid = threadIdx.x;
    int warp = tid >> 5, lane = tid & 31;
    int wm = warp >> 1, wn = warp & 1;
    int g = lane >> 2, r = lane & 3;
    float acc[NMT][4][4] = {};
    int nk = K >> 4;

    auto load = [&](int s, int k0) {
        if (MT == 128) {
            int row = tid >> 1, ch = tid & 1;
            int m = m0 + row;
            long long off = 0;
            int bytes = 0;
            if (mode == 0) {
                if (m < M) { off = (long long)m * K + k0 + ch * 8; bytes = 16; }
            } else {
                int tap = k0 >> 8;
                int dy = tap / 3 - 1, dx = tap % 3 - 1;
                int h = (m >> 6) & 63, w = m & 63;
                int hh = h + dy, ww = w + dx;
                if (m < M && (unsigned)hh < 64u && (unsigned)ww < 64u) {
                    off = (long long)(m + dy * 64 + dx) * 256 + (k0 & 255) + ch * 8;
                    bytes = 16;
                }
            }
            cp16(&sAh[s][row][ch * 4], A + off, bytes);
            cp16(&sAl[s][row][ch * 4], A + sA + off, bytes);
        } else {
            int p = tid >> 7;
            int row = (tid >> 1) & 63, ch = tid & 1;
            int m = m0 + row;
            long long off = 0;
            int bytes = 0;
            if (m < M) { off = (long long)m * K + k0 + ch * 8; bytes = 16; }
            if (p) cp16(&sAl[s][row][ch * 4], A + sA + off, bytes);
            else   cp16(&sAh[s][row][ch * 4], A + off, bytes);
        }
        {
            int p = tid >> 7;
            int row = (tid >> 1) & 63, ch = tid & 1;
            int n = n0 + row;
            const bf16* src = W;
            int bytes = 0;
            if (n < N) {
                src = W + (long long)p * sW + (long long)n * K + k0 + ch * 8;
                bytes = 16;
            }
            if (p) cp16(&sBl[s][row][ch * 4], src, bytes);
            else   cp16(&sBh[s][row][ch * 4], src, bytes);
        }
        cp_commit();
    };

    load(0, 0);
    if (nk > 1) load(1, 16);
    for (int kt = 0; kt < nk; kt++) {
        int cur = kt % 3;
        if (kt + 2 < nk) { load((kt + 2) % 3, (kt + 2) << 4); cp_wait2(); }
        else if (kt + 1 < nk) cp_wait1();
        else cp_wait0();
        __syncthreads();
        uint32_t ah[NMT][4], al[NMT][4], bh[4][2], bl[4][2];
#pragma unroll
        for (int mt = 0; mt < NMT; mt++) {
            int rb = wm * MSUB + mt * 16;
            ah[mt][0] = sAh[cur][rb + g][r];
            ah[mt][1] = sAh[cur][rb + g + 8][r];
            ah[mt][2] = sAh[cur][rb + g][r + 4];
            ah[mt][3] = sAh[cur][rb + g + 8][r + 4];
            al[mt][0] = sAl[cur][rb + g][r];
            al[mt][1] = sAl[cur][rb + g + 8][r];
            al[mt][2] = sAl[cur][rb + g][r + 4];
            al[mt][3] = sAl[cur][rb + g + 8][r + 4];
        }
#pragma unroll
        for (int nt = 0; nt < 4; nt++) {
            int cb = wn * 32 + nt * 8;
            bh[nt][0] = sBh[cur][cb + g][r];
            bh[nt][1] = sBh[cur][cb + g][r + 4];
            bl[nt][0] = sBl[cur][cb + g][r];
            bl[nt][1] = sBl[cur][cb + g][r + 4];
        }
#pragma unroll
        for (int mt = 0; mt < NMT; mt++)
#pragma unroll
            for (int nt = 0; nt < 4; nt++) {
                mma_bf16(acc[mt][nt], ah[mt], bh[nt]);
                mma_bf16(acc[mt][nt], al[mt], bh[nt]);
                mma_bf16(acc[mt][nt], ah[mt], bl[nt]);
            }
        __syncthreads();
    }

    if (epi == 1) {
#pragma unroll
        for (int mt = 0; mt < NMT; mt++) {
            int rbase = m0 + wm * MSUB + mt * 16;
#pragma unroll
            for (int nt = 0; nt < 4; nt++) {
                int n = n0 + wn * 32 + nt * 8 + 2 * r;
#pragma unroll
                for (int e = 0; e < 4; e++) {
                    int nn = n + (e & 1);
                    float v = fmaxf(acc[mt][nt][e] + bias[nn], 0.f);
                    v += __shfl_xor_sync(0xffffffffu, v, 4);
                    v += __shfl_xor_sync(0xffffffffu, v, 8);
                    v += __shfl_xor_sync(0xffffffffu, v, 16);
                    if (g == 0) {
                        int q = (rbase >> 3) + ((e >= 2) ? 1 : 0);
                        if (q < 2 * NQ) {
                            long long o = (long long)q * 256 + nn;
                            wsplit(OS + o, OS + sOS + o, v * 0.125f);
                        }
                    }
                }
            }
        }
        return;
    }
#pragma unroll
    for (int mt = 0; mt < NMT; mt++) {
        int rbase = m0 + wm * MSUB + mt * 16;
#pragma unroll
        for (int nt = 0; nt < 4; nt++) {
            int cbase = n0 + wn * 32 + nt * 8 + 2 * r;
#pragma unroll
            for (int e = 0; e < 4; e++) {
                int m = rbase + g + ((e >= 2) ? 8 : 0);
                int n = cbase + (e & 1);
                if (m < M && n < N) {
                    float v = acc[mt][nt][e];
                    if (bias) v += bias[n];
                    if (act == 1 || (act == 2 && n < 512) || (act == 3 && n < 256))
                        v = fmaxf(v, 0.f);
                    if (pos) {
                        int hw = m & 4095;
                        v += g_fh[(hw >> 6) * D + n] + g_gw[(hw & 63) * D + n] + g_b2v[n];
                    }
                    if (epi == 3) {
                        long long o = (long long)m * N + n;
                        wsplit(OS + o, OS + sOS + o, v);
                    } else {
                        if (accum) v += C[(long long)m * ldc + n];
                        C[(long long)m * ldc + n] = v;
                        if (epi == 2) {
                            long long o = (long long)m * N + n;
                            wsplit(OS + o, OS + sOS + o, v);
                        }
                    }
                }
            }
        }
    }
}

// ---------------- prep kernels ----------------
// combined temporal-conv+mean+proj weight, stored TRANSPOSED + split: WcT[k(512)][n(256)]
__global__ void prep_wc(const float* __restrict__ w_tf, const float* __restrict__ b_tf,
                        const float* __restrict__ w_in, const float* __restrict__ b_in) {
    int idx = blockIdx.x * blockDim.x + threadIdx.x;
    if (idx < 4 * D * 128) {
        int s = idx >> 15;
        int rr = idx & 32767;
        int n = rr >> 7;
        int i = rr & 127;
        float acc = 0.f;
        for (int c = 0; c < 128; c++) {
            const float* w3 = w_tf + (c * 128 + i) * 3;
            float coeff;
            if (s == 0)      coeff = w3[0] + w3[1];
            else if (s == 3) coeff = w3[1] + w3[2];
            else             coeff = w3[0] + w3[1] + w3[2];
            acc += w_in[n * 128 + c] * coeff;
        }
        long long o = (long long)(s * 128 + i) * 256 + n;
        wsplit(g_WcTs + o, g_WcTs + S_WCT + o, 0.25f * acc);
    }
    if (idx < D) {
        float a = b_in[idx];
        for (int c = 0; c < 128; c++) a += w_in[idx * 128 + c] * b_tf[c];
        g_biasc[idx] = a;
    }
}

__global__ void prep_tables(const float* __restrict__ w_lat, const float* __restrict__ b_lat) {
    int h = blockIdx.x;
    int o = threadIdx.x;
    float sf = 0.f, sg = 0.f;
    for (int c = 0; c < 128; c++) {
        int i = c >> 1;
        float fl = (float)(i >> 1);
        float dimt = exp2f(fl * 0.415241011861f);
        float arg = (float)(h + 1) * (6.2831853071795864769f / (64.f + 1e-6f)) / dimt;
        float val = (c & 1) ? cosf(arg) : sinf(arg);
        sf += val * w_lat[o * 256 + c];
        sg += val * w_lat[o * 256 + 128 + c];
    }
    g_fh[h * D + o] = sf;
    g_gw[h * D + o] = sg;
    if (h == 0) {
        float b = b_lat[o];
        for (int c = 0; c < 256; c++) b += w_lat[o * 256 + c] * g_biasc[c];
        g_b2v[o] = b;
    }
}

// conv weights [o][tap*256+c] split bf16
__global__ void prep_wt(const float* __restrict__ w_sm) {
    int idx = blockIdx.x * blockDim.x + threadIdx.x;
    if (idx >= KP1 * D) return;
    int o = idx / KP1;
    int rr = idx % KP1;
    float v = w_sm[(o * D + (rr & 255)) * 9 + (rr >> 8)];
    wsplit(g_wts + idx, g_wts + S_WT + idx, v);
}

__global__ void prep_wbig(const float* __restrict__ w_b1, const float* __restrict__ b_b1,
                          const float* __restrict__ w_r1, const float* __restrict__ b_r1,
                          const float* __restrict__ Wq, const float* __restrict__ bq) {
    int idx = blockIdx.x * blockDim.x + threadIdx.x;
    if (idx < NLAY * 768 * D) {
        int l = idx / (768 * D);
        int rr = idx % (768 * D);
        int n = rr >> 8;
        int k = rr & 255;
        float v;
        if (n < 256)      v = w_b1[n * 256 + k];
        else if (n < 512) v = w_r1[(n - 256) * 256 + k];
        else              v = Wq[(l * 256 + (n - 512)) * 256 + k];
        wsplit(g_wbigs + idx, g_wbigs + S_WBIG + idx, v);
    }
    if (idx < NLAY * 768) {
        int l = idx / 768, n = idx % 768;
        g_bbig[idx] = (n < 256) ? b_b1[n] : ((n < 512) ? b_r1[n - 256] : bq[l * 256 + n - 512]);
    }
}

// one kernel splits 4 fp32 sources into bf16 hi/lo planes
__global__ void splitk4(const float* __restrict__ s0, bf16* d0, long long n0,
                        const float* __restrict__ s1, bf16* d1, long long n1,
                        const float* __restrict__ s2, bf16* d2, long long n2,
                        const float* __restrict__ s3, bf16* d3, long long n3) {
    long long i = (long long)blockIdx.x * blockDim.x + threadIdx.x;
    const float* s; bf16 *h, *l;
    if (i < n0) { s = s0; h = d0; l = d0 + n0; }
    else {
        i -= n0;
        if (i < n1) { s = s1; h = d1; l = d1 + n1; }
        else {
            i -= n1;
            if (i < n2) { s = s2; h = d2; l = d2 + n2; }
            else {
                i -= n2;
                if (i >= n3) return;
                s = s3; h = d3; l = d3 + n3;
            }
        }
    }
    wsplit(h + i, l + i, s[i]);
}

// transpose feat [b][512][4096] -> split planes [b*4096][512]
__global__ void transposeA(const float* __restrict__ feat) {
    __shared__ float t[32][33];
    int b = blockIdx.z;
    int hw0 = blockIdx.x * 32, k0 = blockIdx.y * 32;
    const float* src = feat + (long long)b * 512 * HW;
    int tx = threadIdx.x, ty = threadIdx.y;
#pragma unroll
    for (int j = 0; j < 4; j++)
        t[ty + j * 8][tx] = src[(long long)(k0 + ty + j * 8) * HW + hw0 + tx];
    __syncthreads();
#pragma unroll
    for (int j = 0; j < 4; j++) {
        long long o = (long long)(b * HW + hw0 + ty + j * 8) * 512 + k0 + tx;
        wsplit(g_xins + o, g_xins + S_XIN + o, t[tx][ty + j * 8]);
    }
}

__global__ void init_all(const float* __restrict__ qe, const float* __restrict__ qp,
                         const float* __restrict__ pbi) {
    int idx = blockIdx.x * blockDim.x + threadIdx.x;
    if (idx < 2 * NQ * D) {
        int qd = idx % (NQ * D);
        float v = qe[qd] + qp[qd];
        g_q[idx] = v;
        wsplit(g_qs + idx, g_qs + S_Q + idx, v);
    }
    if (idx < 2 * NQ * 4) g_boxes[idx] = pbi[idx];
}

// ---------------- fused boxupd(prev layer) + roref + bilinear sample ----------------
// grid 600 (one per b,q), 256 threads
__global__ void rorefsample(const float* __restrict__ w_r2, const float* __restrict__ b_r2,
                            const float* __restrict__ w_b2, const float* __restrict__ b_b2,
                            int do_box) {
    int bq = blockIdx.x;
    int tid = threadIdx.x;
    int warp = tid >> 5, lane = tid & 31;
    __shared__ float h1row[256], hbrow[256], ro[16], refs[16], boxsh[2];
    h1row[tid] = g_big[bq * 768 + 256 + tid];
    if (do_box) hbrow[tid] = g_big[bq * 768 + tid];
    else if (tid < 2) boxsh[tid] = g_boxes[bq * 4 + tid];
    __syncthreads();
    if (do_box && warp < 4) {
        float s = 0.f;
        for (int k = lane; k < 256; k += 32) s += hbrow[k] * w_b2[warp * 256 + k];
#pragma unroll
        for (int o = 16; o; o >>= 1) s += __shfl_xor_sync(0xffffffffu, s, o);
        if (lane == 0) {
            float delta = 1.f / (1.f + expf(-(s + b_b2[warp])));
            float nb = g_boxes[bq * 4 + warp] + 0.1f * tanhf(delta - 0.5f);
            nb = fminf(fmaxf(nb, 0.f), 1.f);
            g_boxes[bq * 4 + warp] = nb;
            if (warp < 2) boxsh[warp] = nb;
        }
    }
#pragma unroll
    for (int jj = 0; jj < 2; jj++) {
        int j = warp * 2 + jj;
        float s = 0.f;
        for (int k = lane; k < 256; k += 32) s += h1row[k] * w_r2[j * 256 + k];
#pragma unroll
        for (int o = 16; o; o >>= 1) s += __shfl_xor_sync(0xffffffffu, s, o);
        if (lane == 0) ro[j] = tanhf(s + b_r2[j]);
    }
    __syncthreads();
    if (tid < 8) {
        refs[2 * tid + 0] = fminf(fmaxf(boxsh[0] + 0.5f * ro[2 * tid + 0], 0.f), 1.f);
        refs[2 * tid + 1] = fminf(fmaxf(boxsh[1] + 0.5f * ro[2 * tid + 1], 0.f), 1.f);
    }
    __syncthreads();
    int b = bq / NQ;
    const float* f = g_f0 + (long long)b * HW * D;
    int c = tid;
#pragma unroll
    for (int p = 0; p < NP; p++) {
        float rx = refs[2 * p], ry = refs[2 * p + 1];
        long long base = ((long long)bq * NP + p) * KP1;
#pragma unroll
        for (int cy = 0; cy < 3; cy++) {
            float gy = ry * 2.f - 1.f + (float)(cy - 1) * (2.f / 64.f);
            float yy = fminf(fmaxf((gy + 1.f) * 0.5f * 63.f, 0.f), 63.f);
            float y0f = floorf(yy);
            int y0 = (int)y0f;
            float wy = yy - y0f;
            int y1 = min(y0 + 1, 63);
#pragma unroll
            for (int cx = 0; cx < 3; cx++) {
                float gx = rx * 2.f - 1.f + (float)(cx - 1) * (2.f / 64.f);
                float xx = fminf(fmaxf((gx + 1.f) * 0.5f * 63.f, 0.f), 63.f);
                float x0f = floorf(xx);
                int x0 = (int)x0f;
                float wx = xx - x0f;
                int x1 = min(x0 + 1, 63);
                float v00 = f[((y0 << 6) + x0) * D + c];
                float v01 = f[((y0 << 6) + x1) * D + c];
                float v10 = f[((y1 << 6) + x0) * D + c];
                float v11 = f[((y1 << 6) + x1) * D + c];
                float v = v00 * (1.f - wx) * (1.f - wy) + v01 * wx * (1.f - wy)
                        + v10 * (1.f - wx) * wy + v11 * wx * wy;
                long long o = base + (cy * 3 + cx) * D + c;
                wsplit(g_flats + o, g_flats + S_FLAT + o, v);
            }
        }
    }
}

// ---------------- fused attention ----------------
__global__ void attn_kernel() {
    __shared__ float qs[8][260];
    __shared__ float kvs[16][264];
    __shared__ float tr[8][528];
    int b = blockIdx.y, qt = blockIdx.x;
    int tid = threadIdx.x;
    int warp = tid >> 5, lane = tid & 31;
    const float* kvb = g_kv + (long long)b * NQ * D;
#pragma unroll
    for (int i = 0; i < 8; i++) {
        int idx = tid + i * 256;
        int qi = idx >> 8, c = idx & 255;
        int q = qt * 8 + qi;
        qs[qi][c] = (q < NQ) ? g_big[((long long)b * NQ + q) * 768 + 512 + c] : 0.f;
    }
    float sc[19];
#pragma unroll
    for (int kt = 0; kt < 19; kt++) {
        __syncthreads();
#pragma unroll
        for (int i = 0; i < 16; i++) {
            int idx = tid + i * 256;
            int j = idx >> 8, c = idx & 255;
            int key = kt * 16 + j;
            kvs[j][c] = (key < NQ) ? kvb[(long long)key * D + c] : 0.f;
        }
        __syncthreads();
        float p[16] = {};
#pragma unroll
        for (int i = 0; i < 8; i++) {
            float qv = qs[warp][i * 32 + lane];
#pragma unroll
            for (int j = 0; j < 16; j++) p[j] += qv * kvs[j][i * 32 + lane];
        }
#pragma unroll
        for (int j = 0; j < 16; j++) tr[warp][j * 33 + lane] = p[j];
        __syncwarp();
        if (lane < 16) {
            float s = 0.f;
#pragma unroll
            for (int x = 0; x < 32; x++) s += tr[warp][lane * 33 + x];
            sc[kt] = (kt * 16 + lane < NQ) ? s * 0.0625f : -1e30f;
        }
        __syncwarp();
    }
    float m = -1e30f;
    if (lane < 16) {
#pragma unroll
        for (int kt = 0; kt < 19; kt++) m = fmaxf(m, sc[kt]);
    }
#pragma unroll
    for (int o = 16; o; o >>= 1) m = fmaxf(m, __shfl_xor_sync(0xffffffffu, m, o));
    float sum = 0.f;
    if (lane < 16) {
#pragma unroll
        for (int kt = 0; kt < 19; kt++) {
            float e = expf(sc[kt] - m);
            sc[kt] = e;
            sum += e;
        }
    }
#pragma unroll
    for (int o = 16; o; o >>= 1) sum += __shfl_xor_sync(0xffffffffu, sum, o);
    float inv = 1.f / sum;
    if (lane < 16) {
#pragma unroll
        for (int kt = 0; kt < 19; kt++) tr[warp][kt * 16 + lane] = sc[kt] * inv;
    }
    __syncwarp();
    float out[8] = {};
#pragma unroll
    for (int kt = 0; kt < 19; kt++) {
        __syncthreads();
#pragma unroll
        for (int i = 0; i < 16; i++) {
            int idx = tid + i * 256;
            int j = idx >> 8, c = idx & 255;
            int key = kt * 16 + j;
            kvs[j][c] = (key < NQ) ? kvb[(long long)key * D + c] : 0.f;
        }
        __syncthreads();
#pragma unroll
        for (int j = 0; j < 16; j++) {
            float a = tr[warp][kt * 16 + j];
#pragma unroll
            for (int i = 0; i < 8; i++) out[i] += a * kvs[j][i * 32 + lane];
        }
    }
    int q = qt * 8 + warp;
    if (q < NQ) {
#pragma unroll
        for (int i = 0; i < 8; i++) {
            long long o = ((long long)b * NQ + q) * D + i * 32 + lane;
            wsplit(g_aos + o, g_aos + S_AO + o, out[i]);
        }
    }
}

// ---------------- final: last boxupd + cls + box copy ----------------
__global__ void final_kernel(const float* __restrict__ w_b2, const float* __restrict__ b_b2,
                             const float* __restrict__ w_cls, const float* __restrict__ b_cls,
                             float* __restrict__ out) {
    int bq = blockIdx.x;
    int tid = threadIdx.x;  // 128
    int warp = tid >> 5, lane = tid & 31;
    __shared__ float hrow[256];
    hrow[tid] = g_big[bq * 768 + tid];
    hrow[tid + 128] = g_big[bq * 768 + 128 + tid];
    __syncthreads();
    float s = 0.f;
    for (int k = lane; k < 256; k += 32) s += hrow[k] * w_b2[warp * 256 + k];
#pragma unroll
    for (int o = 16; o; o >>= 1) s += __shfl_xor_sync(0xffffffffu, s, o);
    if (lane == 0) {
        float delta = 1.f / (1.f + expf(-(s + b_b2[warp])));
        float nb = g_boxes[bq * 4 + warp] + 0.1f * tanhf(delta - 0.5f);
        out[600 + bq * 4 + warp] = fminf(fmaxf(nb, 0.f), 1.f);
    }
    if (warp == 0) {
        float s2 = 0.f;
        for (int k = lane; k < 256; k += 32) s2 += g_q[bq * 256 + k] * w_cls[k];
#pragma unroll
        for (int o = 16; o; o >>= 1) s2 += __shfl_xor_sync(0xffffffffu, s2, o);
        if (lane == 0) out[bq] = s2 + b_cls[0];
    }
}

// ---------------- host ----------------
static void gemm3(int MT, const bf16* A, long long sA, const bf16* W, long long sW,
                  const float* bias, float* C, int ldc, bf16* OS, long long sOS,
                  int M, int N, int K, int act, int accum, int mode, int pos, int epi) {
    dim3 grid((M + MT - 1) / MT, (N + 63) / 64);
    if (MT == 128)
        tc_gemm3<128><<<grid, 256>>>(A, sA, W, sW, bias, C, ldc, OS, sOS,
                                     M, N, K, act, accum, mode, pos, epi);
    else
        tc_gemm3<64><<<grid, 256>>>(A, sA, W, sW, bias, C, ldc, OS, sOS,
                                    M, N, K, act, accum, mode, pos, epi);
}

extern "C" void kernel_launch(void* const* d_in, const int* in_sizes, int n_in,
                              void* d_out, int out_size) {
    const float* feat   = (const float*)d_in[0];
    const float* pbi    = (const float*)d_in[1];
    const float* w_tf   = (const float*)d_in[2];
    const float* b_tf   = (const float*)d_in[3];
    const float* w_in   = (const float*)d_in[4];
    const float* b_in   = (const float*)d_in[5];
    const float* w_lat  = (const float*)d_in[6];
    const float* b_lat  = (const float*)d_in[7];
    const float* w_sm   = (const float*)d_in[8];
    const float* b_sm   = (const float*)d_in[9];
    const float* q_embed= (const float*)d_in[10];
    const float* q_pos  = (const float*)d_in[11];
    const float* Wq     = (const float*)d_in[12];
    const float* bqv    = (const float*)d_in[13];
    const float* Wo     = (const float*)d_in[14];
    const float* bo     = (const float*)d_in[15];
    const float* Wp1    = (const float*)d_in[16];
    const float* bp1    = (const float*)d_in[17];
    const float* Wp2    = (const float*)d_in[18];
    const float* bp2    = (const float*)d_in[19];
    const float* w_r1   = (const float*)d_in[20];
    const float* b_r1   = (const float*)d_in[21];
    const float* w_r2   = (const float*)d_in[22];
    const float* b_r2   = (const float*)d_in[23];
    const float* w_b1   = (const float*)d_in[24];
    const float* b_b1   = (const float*)d_in[25];
    const float* w_b2   = (const float*)d_in[26];
    const float* b_b2   = (const float*)d_in[27];
    const float* w_cls  = (const float*)d_in[28];
    const float* b_cls  = (const float*)d_in[29];
    float* out = (float*)d_out;

    float *p_bbig, *p_f0, *p_kv, *p_q, *p_big;
    bf16 *p_WcTs, *p_wlats, *p_W2s, *p_wts, *p_Wp1s, *p_Wp2s, *p_Wos, *p_wbigs;
    bf16 *p_xins, *p_ys, *p_flats, *p_pvms, *p_qs, *p_aos;
    cudaGetSymbolAddress((void**)&p_bbig, g_bbig);
    cudaGetSymbolAddress((void**)&p_f0, g_f0);
    cudaGetSymbolAddress((void**)&p_kv, g_kv);
    cudaGetSymbolAddress((void**)&p_q, g_q);
    cudaGetSymbolAddress((void**)&p_big, g_big);
    cudaGetSymbolAddress((void**)&p_WcTs, g_WcTs);
    cudaGetSymbolAddress((void**)&p_wlats, g_wlats);
    cudaGetSymbolAddress((void**)&p_W2s, g_W2s);
    cudaGetSymbolAddress((void**)&p_wts, g_wts);
    cudaGetSymbolAddress((void**)&p_Wp1s, g_Wp1s);
    cudaGetSymbolAddress((void**)&p_Wp2s, g_Wp2s);
    cudaGetSymbolAddress((void**)&p_Wos, g_Wos);
    cudaGetSymbolAddress((void**)&p_wbigs, g_wbigs);
    cudaGetSymbolAddress((void**)&p_xins, g_xins);
    cudaGetSymbolAddress((void**)&p_ys, g_ys);
    cudaGetSymbolAddress((void**)&p_flats, g_flats);
    cudaGetSymbolAddress((void**)&p_pvms, g_pvms);
    cudaGetSymbolAddress((void**)&p_qs, g_qs);
    cudaGetSymbolAddress((void**)&p_aos, g_aos);

    // ---- prep ----
    prep_wc<<<(4 * D * 128 + 255) / 256, 256>>>(w_tf, b_tf, w_in, b_in);
    prep_wt<<<(KP1 * D + 255) / 256, 256>>>(w_sm);
    prep_wbig<<<(NLAY * 768 * D + 255) / 256, 256>>>(w_b1, b_b1, w_r1, b_r1, Wq, bqv);
    prep_tables<<<64, 256>>>(w_lat, b_lat);
    {
        long long total = S_WP1 + S_WP2 + S_WO + S_WLAT;
        splitk4<<<(int)((total + 255) / 256), 256>>>(
            Wp1, p_Wp1s, S_WP1, Wp2, p_Wp2s, S_WP2, Wo, p_Wos, S_WO, w_lat, p_wlats, S_WLAT);
    }
    // W2 = w_lat @ WcT^T  -> split planes (epi 3)
    gemm3(64, p_wlats, S_WLAT, p_WcTs, S_WCT, nullptr, nullptr, 512, p_W2s, S_W2,
          256, 512, 256, 0, 0, 0, 0, 3);
    transposeA<<<dim3(128, 16, 2), dim3(32, 8)>>>(feat);

    // ---- backbone ----
    gemm3(128, p_xins, S_XIN, p_W2s, S_W2, nullptr, nullptr, 256, p_ys, S_Y,
          2 * HW, 256, 512, 0, 0, 0, 1, 3);
    gemm3(128, p_ys, S_Y, p_wts, S_WT, b_sm, p_f0, 256, nullptr, 0,
          2 * HW, 256, KP1, 0, 0, 1, 0, 0);

    init_all<<<(2 * NQ * D + 255) / 256, 256>>>(q_embed, q_pos, pbi);

    // pre-loop: h1,qp for layer 0 -> g_big cols 256..767 (relu only on h1)
    gemm3(64, p_qs, S_Q, p_wbigs + 256 * 256, S_WBIG, p_bbig + 256, p_big + 256, 768,
          nullptr, 0, 2 * NQ, 512, 256, 3, 0, 0, 0, 0);

    for (int l = 0; l < NLAY; l++) {
        rorefsample<<<2 * NQ, 256>>>(w_r2, b_r2, w_b2, b_b2, l > 0);
        gemm3(64, p_flats, S_FLAT, p_Wp1s + (long long)l * 256 * KP1, S_WP1, bp1 + l * D,
              nullptr, 256, p_pvms, S_PVM, 2 * NQ * NP, 256, KP1, 0, 0, 0, 0, 1);
        gemm3(64, p_pvms, S_PVM, p_Wp2s + (long long)l * 256 * 256, S_WP2, bp2 + l * D,
              p_kv, 256, nullptr, 0, 2 * NQ, 256, 256, 0, 0, 0, 0, 0);
        attn_kernel<<<dim3(38, 2), 256>>>();
        gemm3(64, p_aos, S_AO, p_Wos + (long long)l * 256 * 256, S_WO, bo + l * D,
              p_q, 256, p_qs, S_Q, 2 * NQ, 256, 256, 0, 1, 0, 0, 2);
        if (l < NLAY - 1) {
            gemm3(64, p_qs, S_Q, p_wbigs + (long long)(l + 1) * 768 * 256, S_WBIG,
                  p_bbig + (l + 1) * 768, p_big, 768, nullptr, 0,
                  2 * NQ, 768, 256, 2, 0, 0, 0, 0);
        } else {
            gemm3(64, p_qs, S_Q, p_wbigs, S_WBIG, p_bbig, p_big, 768, nullptr, 0,
                  2 * NQ, 256, 256, 1, 0, 0, 0, 0);
        }
    }

    final_kernel<<<2 * NQ, 128>>>(w_b2, b_b2, w_cls, b_cls, out);
}

// round 8
// speedup vs baseline: 1.4189x; 1.0572x over previous
#include <cuda_runtime.h>
#include <cuda_bf16.h>
#include <math.h>
#include <stdint.h>

#define D 256
#define HW 4096
#define NQ 300
#define NP 8
#define KP1 2304
#define NLAY 6

typedef __nv_bfloat16 bf16;

// plane strides
#define S_XIN ((long long)2 * HW * 512)
#define S_Y   ((long long)2 * HW * 256)
#define S_FLAT ((long long)2 * NQ * NP * KP1)
#define S_Q   ((long long)2 * NQ * 256)
#define S_AO  ((long long)2 * NQ * 256)
#define S_W2  ((long long)256 * 512)
#define S_WT  ((long long)256 * KP1)
#define S_WP1 ((long long)NLAY * 256 * KP1)
#define S_WO  ((long long)NLAY * 256 * 256)
#define S_WBIG ((long long)NLAY * 768 * 256)
#define S_WCT ((long long)512 * 256)
#define S_WLAT ((long long)256 * 256)
#define S_COEF ((long long)512 * 128)
#define S_WIN  ((long long)256 * 128)
#define S_VAL  ((long long)128 * 256)

// ---------------- scratch (device globals; no allocation) ----------------
__device__ float g_biasc[D];
__device__ float g_b2v[D];
__device__ float g_pos[128 * 256];      // rows 0..63 fh, 64..127 gw
__device__ float g_bbig[NLAY * 768];
__device__ float g_bo2[NLAY * 256];
// bf16 split planes (hi at 0, lo at +stride)
__device__ bf16 g_coeffs[2 * S_COEF];
__device__ bf16 g_w_ins[2 * S_WIN];
__device__ bf16 g_vals[2 * S_VAL];
__device__ bf16 g_WcTs[2 * S_WCT];
__device__ bf16 g_wlats[2 * S_WLAT];
__device__ bf16 g_W2s[2 * S_W2];
__device__ bf16 g_wts[2 * S_WT];
__device__ bf16 g_Wp1s[2 * S_WP1];
__device__ bf16 g_Wos[2 * S_WO];       // holds folded WoP = Wo @ Wp2
__device__ bf16 g_wbigs[2 * S_WBIG];   // [w_b1 | w_r1 | Wq2(l)]
__device__ bf16 g_xins[2 * S_XIN];
__device__ bf16 g_ys[2 * S_Y];
__device__ bf16 g_flats[2 * S_FLAT];
__device__ bf16 g_qs[2 * S_Q];
__device__ bf16 g_aos[2 * S_AO];
// fp32 tensors
__device__ float g_f0[2 * HW * D];
__device__ float g_q[2 * NQ * D];
__device__ float g_big[2 * NQ * 768];   // [hb | h1 | qp2]
__device__ float g_kv[2 * NQ * D];      // pvm means (attention operand)
__device__ float g_boxes[2 * NQ * 4];

__device__ __forceinline__ void wsplit(bf16* h, bf16* l, float v) {
    bf16 hh = __float2bfloat16(v);
    *h = hh;
    *l = __float2bfloat16(v - __bfloat162float(hh));
}

__device__ __forceinline__ void mma_bf16(float* c, const uint32_t* a, const uint32_t* b) {
    asm volatile(
        "mma.sync.aligned.m16n8k16.row.col.f32.bf16.bf16.f32 "
        "{%0,%1,%2,%3},{%4,%5,%6,%7},{%8,%9},{%0,%1,%2,%3};"
        : "+f"(c[0]), "+f"(c[1]), "+f"(c[2]), "+f"(c[3])
        : "r"(a[0]), "r"(a[1]), "r"(a[2]), "r"(a[3]), "r"(b[0]), "r"(b[1]));
}

__device__ __forceinline__ void cp16(void* dst, const void* src, int bytes) {
    uint32_t d = (uint32_t)__cvta_generic_to_shared(dst);
    asm volatile("cp.async.ca.shared.global [%0], [%1], 16, %2;\n" ::"r"(d), "l"(src), "r"(bytes));
}
__device__ __forceinline__ void cp_commit() { asm volatile("cp.async.commit_group;\n"); }
__device__ __forceinline__ void cp_wait2() { asm volatile("cp.async.wait_group 2;\n"); }
__device__ __forceinline__ void cp_wait1() { asm volatile("cp.async.wait_group 1;\n"); }
__device__ __forceinline__ void cp_wait0() { asm volatile("cp.async.wait_group 0;\n"); }

// ---------------- bf16x3 tensor-core GEMM, 3-stage cp.async pipeline ----------------
// act: 0 none, 1 relu, 2 relu n<512, 3 relu n<256.  pos: add pos tables.
// epi: 0 fp32 C; 1 relu+mean_p -> fp32 C (q rows); 2 accum C + split OS; 3 split OS only.
template <int MT>
__global__ void __launch_bounds__(256, 2)
tc_gemm3(const bf16* __restrict__ A, long long sA,
         const bf16* __restrict__ W, long long sW,
         const float* __restrict__ bias, float* __restrict__ C, int ldc,
         bf16* __restrict__ OS, long long sOS,
         int M, int N, int K, int act, int accum, int mode, int pos, int epi) {
    constexpr int MSUB = MT / 4;
    constexpr int NMT = MT / 64;
    __shared__ uint32_t sAh[3][MT][12], sAl[3][MT][12];
    __shared__ uint32_t sBh[3][64][12], sBl[3][64][12];
    int m0 = blockIdx.x * MT, n0 = blockIdx.y * 64;
    int tid = threadIdx.x;
    int warp = tid >> 5, lane = tid & 31;
    int wm = warp >> 1, wn = warp & 1;
    int g = lane >> 2, r = lane & 3;
    float acc[NMT][4][4] = {};
    int nk = K >> 4;

    auto load = [&](int s, int k0) {
        if (MT == 128) {
            int row = tid >> 1, ch = tid & 1;
            int m = m0 + row;
            long long off = 0;
            int bytes = 0;
            if (mode == 0) {
                if (m < M) { off = (long long)m * K + k0 + ch * 8; bytes = 16; }
            } else {
                int tap = k0 >> 8;
                int dy = tap / 3 - 1, dx = tap % 3 - 1;
                int h = (m >> 6) & 63, w = m & 63;
                int hh = h + dy, ww = w + dx;
                if (m < M && (unsigned)hh < 64u && (unsigned)ww < 64u) {
                    off = (long long)(m + dy * 64 + dx) * 256 + (k0 & 255) + ch * 8;
                    bytes = 16;
                }
            }
            cp16(&sAh[s][row][ch * 4], A + off, bytes);
            cp16(&sAl[s][row][ch * 4], A + sA + off, bytes);
        } else {
            int p = tid >> 7;
            int row = (tid >> 1) & 63, ch = tid & 1;
            int m = m0 + row;
            long long off = 0;
            int bytes = 0;
            if (m < M) { off = (long long)m * K + k0 + ch * 8; bytes = 16; }
            if (p) cp16(&sAl[s][row][ch * 4], A + sA + off, bytes);
            else   cp16(&sAh[s][row][ch * 4], A + off, bytes);
        }
        {
            int p = tid >> 7;
            int row = (tid >> 1) & 63, ch = tid & 1;
            int n = n0 + row;
            const bf16* src = W;
            int bytes = 0;
            if (n < N) {
                src = W + (long long)p * sW + (long long)n * K + k0 + ch * 8;
                bytes = 16;
            }
            if (p) cp16(&sBl[s][row][ch * 4], src, bytes);
            else   cp16(&sBh[s][row][ch * 4], src, bytes);
        }
        cp_commit();
    };

    load(0, 0);
    if (nk > 1) load(1, 16);
    for (int kt = 0; kt < nk; kt++) {
        int cur = kt % 3;
        if (kt + 2 < nk) { load((kt + 2) % 3, (kt + 2) << 4); cp_wait2(); }
        else if (kt + 1 < nk) cp_wait1();
        else cp_wait0();
        __syncthreads();
        uint32_t ah[NMT][4], al[NMT][4], bh[4][2], bl[4][2];
#pragma unroll
        for (int mt = 0; mt < NMT; mt++) {
            int rb = wm * MSUB + mt * 16;
            ah[mt][0] = sAh[cur][rb + g][r];
            ah[mt][1] = sAh[cur][rb + g + 8][r];
            ah[mt][2] = sAh[cur][rb + g][r + 4];
            ah[mt][3] = sAh[cur][rb + g + 8][r + 4];
            al[mt][0] = sAl[cur][rb + g][r];
            al[mt][1] = sAl[cur][rb + g + 8][r];
            al[mt][2] = sAl[cur][rb + g][r + 4];
            al[mt][3] = sAl[cur][rb + g + 8][r + 4];
        }
#pragma unroll
        for (int nt = 0; nt < 4; nt++) {
            int cb = wn * 32 + nt * 8;
            bh[nt][0] = sBh[cur][cb + g][r];
            bh[nt][1] = sBh[cur][cb + g][r + 4];
            bl[nt][0] = sBl[cur][cb + g][r];
            bl[nt][1] = sBl[cur][cb + g][r + 4];
        }
#pragma unroll
        for (int mt = 0; mt < NMT; mt++)
#pragma unroll
            for (int nt = 0; nt < 4; nt++) {
                mma_bf16(acc[mt][nt], ah[mt], bh[nt]);
                mma_bf16(acc[mt][nt], al[mt], bh[nt]);
                mma_bf16(acc[mt][nt], ah[mt], bl[nt]);
            }
        __syncthreads();
    }

    if (epi == 1) {  // relu + mean over 8 points -> fp32 C[q][256]
#pragma unroll
        for (int mt = 0; mt < NMT; mt++) {
            int rbase = m0 + wm * MSUB + mt * 16;
#pragma unroll
            for (int nt = 0; nt < 4; nt++) {
                int n = n0 + wn * 32 + nt * 8 + 2 * r;
#pragma unroll
                for (int e = 0; e < 4; e++) {
                    int nn = n + (e & 1);
                    float v = fmaxf(acc[mt][nt][e] + bias[nn], 0.f);
                    v += __shfl_xor_sync(0xffffffffu, v, 4);
                    v += __shfl_xor_sync(0xffffffffu, v, 8);
                    v += __shfl_xor_sync(0xffffffffu, v, 16);
                    if (g == 0) {
                        int q = (rbase >> 3) + ((e >= 2) ? 1 : 0);
                        if (q < 2 * NQ) C[(long long)q * 256 + nn] = v * 0.125f;
                    }
                }
            }
        }
        return;
    }
#pragma unroll
    for (int mt = 0; mt < NMT; mt++) {
        int rbase = m0 + wm * MSUB + mt * 16;
#pragma unroll
        for (int nt = 0; nt < 4; nt++) {
            int cbase = n0 + wn * 32 + nt * 8 + 2 * r;
#pragma unroll
            for (int e = 0; e < 4; e++) {
                int m = rbase + g + ((e >= 2) ? 8 : 0);
                int n = cbase + (e & 1);
                if (m < M && n < N) {
                    float v = acc[mt][nt][e];
                    if (bias) v += bias[n];
                    if (act == 1 || (act == 2 && n < 512) || (act == 3 && n < 256))
                        v = fmaxf(v, 0.f);
                    if (pos) {
                        int hw = m & 4095;
                        v += g_pos[(hw >> 6) * 256 + n] + g_pos[16384 + (hw & 63) * 256 + n]
                           + g_b2v[n];
                    }
                    if (epi == 3) {
                        long long o = (long long)m * N + n;
                        wsplit(OS + o, OS + sOS + o, v);
                    } else {
                        if (accum) v += C[(long long)m * ldc + n];
                        C[(long long)m * ldc + n] = v;
                        if (epi == 2) {
                            long long o = (long long)m * N + n;
                            wsplit(OS + o, OS + sOS + o, v);
                        }
                    }
                }
            }
        }
    }
}

// ---------------- prep kernels ----------------
// coeffA[(s*128+i)][c] = 0.25*coeff(s,c,i); also biasc and w_in split
__global__ void prep_coeff(const float* __restrict__ w_tf, const float* __restrict__ b_tf,
                           const float* __restrict__ w_in, const float* __restrict__ b_in) {
    int idx = blockIdx.x * blockDim.x + threadIdx.x;
    if (idx < 512 * 128) {
        int row = idx >> 7;
        int c = idx & 127;
        int s = row >> 7, i = row & 127;
        const float* w3 = w_tf + (c * 128 + i) * 3;
        float coeff;
        if (s == 0)      coeff = w3[0] + w3[1];
        else if (s == 3) coeff = w3[1] + w3[2];
        else             coeff = w3[0] + w3[1] + w3[2];
        wsplit(g_coeffs + idx, g_coeffs + S_COEF + idx, 0.25f * coeff);
    }
    if (idx < 256) {
        float a = b_in[idx];
        for (int c = 0; c < 128; c++) a += w_in[idx * 128 + c] * b_tf[c];
        g_biasc[idx] = a;
    }
    if (idx < 256 * 128) wsplit(g_w_ins + idx, g_w_ins + S_WIN + idx, w_in[idx]);
}

// sine values matrix for pos-table GEMM: rows 0..63 = (h, c<128), rows 64..127 = (h, c>=128)
__global__ void prep_val() {
    int idx = blockIdx.x * blockDim.x + threadIdx.x;
    if (idx >= 128 * 256) return;
    int m = idx >> 8, c = idx & 255;
    float v = 0.f;
    int h = m & 63;
    bool lowhalf = (m < 64);
    int cc = lowhalf ? c : c - 128;
    if ((lowhalf && c < 128) || (!lowhalf && c >= 128)) {
        int i = cc >> 1;
        float fl = (float)(i >> 1);
        float dimt = exp2f(fl * 0.415241011861f);
        float arg = (float)(h + 1) * (6.2831853071795864769f / (64.f + 1e-6f)) / dimt;
        v = (cc & 1) ? __cosf(arg) : __sinf(arg);
    }
    wsplit(g_vals + idx, g_vals + S_VAL + idx, v);
}

// conv weights [o][tap*256+c] split bf16
__global__ void prep_wt(const float* __restrict__ w_sm) {
    int idx = blockIdx.x * blockDim.x + threadIdx.x;
    if (idx >= KP1 * D) return;
    int o = idx / KP1;
    int rr = idx % KP1;
    float v = w_sm[(o * D + (rr & 255)) * 9 + (rr >> 8)];
    wsplit(g_wts + idx, g_wts + S_WT + idx, v);
}

// wbig rows 0..511 only (w_b1 | w_r1); rows 512.. come from fold_weights
__global__ void prep_wbig(const float* __restrict__ w_b1, const float* __restrict__ b_b1,
                          const float* __restrict__ w_r1, const float* __restrict__ b_r1) {
    int idx = blockIdx.x * blockDim.x + threadIdx.x;
    if (idx < NLAY * 512 * D) {
        int l = idx / (512 * D);
        int rr = idx % (512 * D);
        int n = rr >> 8;
        int k = rr & 255;
        float v = (n < 256) ? w_b1[n * 256 + k] : w_r1[(n - 256) * 256 + k];
        long long o = (long long)l * 768 * 256 + (long long)n * 256 + k;
        wsplit(g_wbigs + o, g_wbigs + S_WBIG + o, v);
    }
    if (idx < NLAY * 512) {
        int l = idx / 512, n = idx % 512;
        g_bbig[l * 768 + n] = (n < 256) ? b_b1[n] : b_r1[n - 256];
    }
}

// fold: mode0 Wq2[l][d][k] = sum_o Wp2[l][o][d]*Wq[l][o][k]  -> wbig rows 512+
//       mode1 WoP[l][n][d] = sum_o Wo[l][n][o]*Wp2[l][o][d]  -> g_Wos
__global__ void fold_weights(const float* __restrict__ Wp2, const float* __restrict__ Wq,
                             const float* __restrict__ Wo) {
    int l = blockIdx.z >> 1;
    int mode = blockIdx.z & 1;
    const float* P = Wp2 + (long long)l * 65536;
    __shared__ float As[32][33], Bs[32][33];
    int r0 = blockIdx.y * 32, c0 = blockIdx.x * 32;
    int tx = threadIdx.x, ty = threadIdx.y;  // 32 x 8
    float acc[4] = {};
    for (int ko = 0; ko < 256; ko += 32) {
#pragma unroll
        for (int t = 0; t < 4; t++) {
            int i = ty * 4 + t;
            Bs[i][tx] = P[(ko + i) * 256 + c0 + tx];
            if (mode == 0) {
                As[i][tx] = Wq[(long long)l * 65536 + (ko + i) * 256 + r0 + tx];
            } else {
                As[tx][i] = Wo[(long long)l * 65536 + (r0 + i) * 256 + ko + tx];
            }
        }
        __syncthreads();
#pragma unroll
        for (int i = 0; i < 32; i++) {
            float bv = Bs[i][tx];
            acc[0] += As[i][ty] * bv;
            acc[1] += As[i][ty + 8] * bv;
            acc[2] += As[i][ty + 16] * bv;
            acc[3] += As[i][ty + 24] * bv;
        }
        __syncthreads();
    }
#pragma unroll
    for (int e = 0; e < 4; e++) {
        int row = r0 + ty + 8 * e;
        int col = c0 + tx;
        if (mode == 0) {
            // C[d=row][k=col] but As held Q[o][r0+j] => acc = sum_o Q[o][row]*P[o][col]
            // that's Wq2[col?]... careful: As[i][j]=Wq[o][r0+j] so acc[e]=sum_o Wq[o][row]*P[o][col]
            // = Wq2[d=col][k=row]. Store transposed:
            long long o = (long long)l * 768 * 256 + (long long)(512 + col) * 256 + row;
            wsplit(g_wbigs + o, g_wbigs + S_WBIG + o, acc[e]);
        } else {
            // As[i][j]=Wo[n=r0+j][o], acc[e]=sum_o Wo[row][o]*P[o][col] = WoP[n=row][d=col]
            long long o = (long long)l * 65536 + (long long)row * 256 + col;
            wsplit(g_Wos + o, g_Wos + S_WO + o, acc[e]);
        }
    }
}

// folded biases + b2v
__global__ void fold_bias(const float* __restrict__ Wp2, const float* __restrict__ bq,
                          const float* __restrict__ Wo, const float* __restrict__ bp2,
                          const float* __restrict__ bo,
                          const float* __restrict__ w_lat, const float* __restrict__ b_lat) {
    int bid = blockIdx.x;
    int t = threadIdx.x;
    __shared__ float vec[256];
    if (bid == 2 * NLAY) {  // b2v
        vec[t] = g_biasc[t];
        __syncthreads();
        float s = b_lat[t];
        for (int c = 0; c < 256; c++) s += w_lat[t * 256 + c] * vec[c];
        g_b2v[t] = s;
        return;
    }
    int l = bid >> 1;
    if ((bid & 1) == 0) {
        vec[t] = bq[l * 256 + t];
        __syncthreads();
        float s = 0.f;
        for (int o = 0; o < 256; o++) s += Wp2[(long long)l * 65536 + o * 256 + t] * vec[o];
        g_bbig[l * 768 + 512 + t] = s;
    } else {
        vec[t] = bp2[l * 256 + t];
        __syncthreads();
        float s = bo[l * 256 + t];
        for (int o = 0; o < 256; o++) s += Wo[(long long)l * 65536 + t * 256 + o] * vec[o];
        g_bo2[l * 256 + t] = s;
    }
}

// split 2 fp32 sources into bf16 hi/lo planes
__global__ void splitk2(const float* __restrict__ s0, bf16* d0, long long n0,
                        const float* __restrict__ s1, bf16* d1, long long n1) {
    long long i = (long long)blockIdx.x * blockDim.x + threadIdx.x;
    if (i < n0) { wsplit(d0 + i, d0 + n0 + i, s0[i]); return; }
    i -= n0;
    if (i < n1) wsplit(d1 + i, d1 + n1 + i, s1[i]);
}

// transpose feat [b][512][4096] -> split planes [b*4096][512]
__global__ void transposeA(const float* __restrict__ feat) {
    __shared__ float t[32][33];
    int b = blockIdx.z;
    int hw0 = blockIdx.x * 32, k0 = blockIdx.y * 32;
    const float* src = feat + (long long)b * 512 * HW;
    int tx = threadIdx.x, ty = threadIdx.y;
#pragma unroll
    for (int j = 0; j < 4; j++)
        t[ty + j * 8][tx] = src[(long long)(k0 + ty + j * 8) * HW + hw0 + tx];
    __syncthreads();
#pragma unroll
    for (int j = 0; j < 4; j++) {
        long long o = (long long)(b * HW + hw0 + ty + j * 8) * 512 + k0 + tx;
        wsplit(g_xins + o, g_xins + S_XIN + o, t[tx][ty + j * 8]);
    }
}

__global__ void init_all(const float* __restrict__ qe, const float* __restrict__ qp,
                         const float* __restrict__ pbi) {
    int idx = blockIdx.x * blockDim.x + threadIdx.x;
    if (idx < 2 * NQ * D) {
        int qd = idx % (NQ * D);
        float v = qe[qd] + qp[qd];
        g_q[idx] = v;
        wsplit(g_qs + idx, g_qs + S_Q + idx, v);
    }
    if (idx < 2 * NQ * 4) g_boxes[idx] = pbi[idx];
}

// ---------------- fused boxupd(prev layer) + roref + bilinear sample ----------------
__global__ void rorefsample(const float* __restrict__ w_r2, const float* __restrict__ b_r2,
                            const float* __restrict__ w_b2, const float* __restrict__ b_b2,
                            int do_box) {
    int bq = blockIdx.x;
    int tid = threadIdx.x;
    int warp = tid >> 5, lane = tid & 31;
    __shared__ float h1row[256], hbrow[256], ro[16], refs[16], boxsh[2];
    h1row[tid] = g_big[bq * 768 + 256 + tid];
    if (do_box) hbrow[tid] = g_big[bq * 768 + tid];
    else if (tid < 2) boxsh[tid] = g_boxes[bq * 4 + tid];
    __syncthreads();
    if (do_box && warp < 4) {
        float s = 0.f;
        for (int k = lane; k < 256; k += 32) s += hbrow[k] * w_b2[warp * 256 + k];
#pragma unroll
        for (int o = 16; o; o >>= 1) s += __shfl_xor_sync(0xffffffffu, s, o);
        if (lane == 0) {
            float delta = 1.f / (1.f + expf(-(s + b_b2[warp])));
            float nb = g_boxes[bq * 4 + warp] + 0.1f * tanhf(delta - 0.5f);
            nb = fminf(fmaxf(nb, 0.f), 1.f);
            g_boxes[bq * 4 + warp] = nb;
            if (warp < 2) boxsh[warp] = nb;
        }
    }
#pragma unroll
    for (int jj = 0; jj < 2; jj++) {
        int j = warp * 2 + jj;
        float s = 0.f;
        for (int k = lane; k < 256; k += 32) s += h1row[k] * w_r2[j * 256 + k];
#pragma unroll
        for (int o = 16; o; o >>= 1) s += __shfl_xor_sync(0xffffffffu, s, o);
        if (lane == 0) ro[j] = tanhf(s + b_r2[j]);
    }
    __syncthreads();
    if (tid < 8) {
        refs[2 * tid + 0] = fminf(fmaxf(boxsh[0] + 0.5f * ro[2 * tid + 0], 0.f), 1.f);
        refs[2 * tid + 1] = fminf(fmaxf(boxsh[1] + 0.5f * ro[2 * tid + 1], 0.f), 1.f);
    }
    __syncthreads();
    int b = bq / NQ;
    const float* f = g_f0 + (long long)b * HW * D;
    int c = tid;
#pragma unroll
    for (int p = 0; p < NP; p++) {
        float rx = refs[2 * p], ry = refs[2 * p + 1];
        long long base = ((long long)bq * NP + p) * KP1;
#pragma unroll
        for (int cy = 0; cy < 3; cy++) {
            float gy = ry * 2.f - 1.f + (float)(cy - 1) * (2.f / 64.f);
            float yy = fminf(fmaxf((gy + 1.f) * 0.5f * 63.f, 0.f), 63.f);
            float y0f = floorf(yy);
            int y0 = (int)y0f;
            float wy = yy - y0f;
            int y1 = min(y0 + 1, 63);
#pragma unroll
            for (int cx = 0; cx < 3; cx++) {
                float gx = rx * 2.f - 1.f + (float)(cx - 1) * (2.f / 64.f);
                float xx = fminf(fmaxf((gx + 1.f) * 0.5f * 63.f, 0.f), 63.f);
                float x0f = floorf(xx);
                int x0 = (int)x0f;
                float wx = xx - x0f;
                int x1 = min(x0 + 1, 63);
                float v00 = f[((y0 << 6) + x0) * D + c];
                float v01 = f[((y0 << 6) + x1) * D + c];
                float v10 = f[((y1 << 6) + x0) * D + c];
                float v11 = f[((y1 << 6) + x1) * D + c];
                float v = v00 * (1.f - wx) * (1.f - wy) + v01 * wx * (1.f - wy)
                        + v10 * (1.f - wx) * wy + v11 * wx * wy;
                long long o = base + (cy * 3 + cx) * D + c;
                wsplit(g_flats + o, g_flats + S_FLAT + o, v);
            }
        }
    }
}

// ---------------- fused attention (scores on pvm with folded qp2) ----------------
__global__ void attn_kernel() {
    __shared__ float qs[8][260];
    __shared__ float kvs[16][264];
    __shared__ float tr[8][528];
    int b = blockIdx.y, qt = blockIdx.x;
    int tid = threadIdx.x;
    int warp = tid >> 5, lane = tid & 31;
    const float* kvb = g_kv + (long long)b * NQ * D;
#pragma unroll
    for (int i = 0; i < 8; i++) {
        int idx = tid + i * 256;
        int qi = idx >> 8, c = idx & 255;
        int q = qt * 8 + qi;
        qs[qi][c] = (q < NQ) ? g_big[((long long)b * NQ + q) * 768 + 512 + c] : 0.f;
    }
    float sc[19];
#pragma unroll
    for (int kt = 0; kt < 19; kt++) {
        __syncthreads();
#pragma unroll
        for (int i = 0; i < 16; i++) {
            int idx = tid + i * 256;
            int j = idx >> 8, c = idx & 255;
            int key = kt * 16 + j;
            kvs[j][c] = (key < NQ) ? kvb[(long long)key * D + c] : 0.f;
        }
        __syncthreads();
        float p[16] = {};
#pragma unroll
        for (int i = 0; i < 8; i++) {
            float qv = qs[warp][i * 32 + lane];
#pragma unroll
            for (int j = 0; j < 16; j++) p[j] += qv * kvs[j][i * 32 + lane];
        }
#pragma unroll
        for (int j = 0; j < 16; j++) tr[warp][j * 33 + lane] = p[j];
        __syncwarp();
        if (lane < 16) {
            float s = 0.f;
#pragma unroll
            for (int x = 0; x < 32; x++) s += tr[warp][lane * 33 + x];
            sc[kt] = (kt * 16 + lane < NQ) ? s * 0.0625f : -1e30f;
        }
        __syncwarp();
    }
    float m = -1e30f;
    if (lane < 16) {
#pragma unroll
        for (int kt = 0; kt < 19; kt++) m = fmaxf(m, sc[kt]);
    }
#pragma unroll
    for (int o = 16; o; o >>= 1) m = fmaxf(m, __shfl_xor_sync(0xffffffffu, m, o));
    float sum = 0.f;
    if (lane < 16) {
#pragma unroll
        for (int kt = 0; kt < 19; kt++) {
            float e = expf(sc[kt] - m);
            sc[kt] = e;
            sum += e;
        }
    }
#pragma unroll
    for (int o = 16; o; o >>= 1) sum += __shfl_xor_sync(0xffffffffu, sum, o);
    float inv = 1.f / sum;
    if (lane < 16) {
#pragma unroll
        for (int kt = 0; kt < 19; kt++) tr[warp][kt * 16 + lane] = sc[kt] * inv;
    }
    __syncwarp();
    float out[8] = {};
#pragma unroll
    for (int kt = 0; kt < 19; kt++) {
        __syncthreads();
#pragma unroll
        for (int i = 0; i < 16; i++) {
            int idx = tid + i * 256;
            int j = idx >> 8, c = idx & 255;
            int key = kt * 16 + j;
            kvs[j][c] = (key < NQ) ? kvb[(long long)key * D + c] : 0.f;
        }
        __syncthreads();
#pragma unroll
        for (int j = 0; j < 16; j++) {
            float a = tr[warp][kt * 16 + j];
#pragma unroll
            for (int i = 0; i < 8; i++) out[i] += a * kvs[j][i * 32 + lane];
        }
    }
    int q = qt * 8 + warp;
    if (q < NQ) {
#pragma unroll
        for (int i = 0; i < 8; i++) {
            long long o = ((long long)b * NQ + q) * D + i * 32 + lane;
            wsplit(g_aos + o, g_aos + S_AO + o, out[i]);
        }
    }
}

// ---------------- final: last boxupd + cls + box copy ----------------
__global__ void final_kernel(const float* __restrict__ w_b2, const float* __restrict__ b_b2,
                             const float* __restrict__ w_cls, const float* __restrict__ b_cls,
                             float* __restrict__ out) {
    int bq = blockIdx.x;
    int tid = threadIdx.x;  // 128
    int warp = tid >> 5, lane = tid & 31;
    __shared__ float hrow[256];
    hrow[tid] = g_big[bq * 768 + tid];
    hrow[tid + 128] = g_big[bq * 768 + 128 + tid];
    __syncthreads();
    float s = 0.f;
    for (int k = lane; k < 256; k += 32) s += hrow[k] * w_b2[warp * 256 + k];
#pragma unroll
    for (int o = 16; o; o >>= 1) s += __shfl_xor_sync(0xffffffffu, s, o);
    if (lane == 0) {
        float delta = 1.f / (1.f + expf(-(s + b_b2[warp])));
        float nb = g_boxes[bq * 4 + warp] + 0.1f * tanhf(delta - 0.5f);
        out[600 + bq * 4 + warp] = fminf(fmaxf(nb, 0.f), 1.f);
    }
    if (warp == 0) {
        float s2 = 0.f;
        for (int k = lane; k < 256; k += 32) s2 += g_q[bq * 256 + k] * w_cls[k];
#pragma unroll
        for (int o = 16; o; o >>= 1) s2 += __shfl_xor_sync(0xffffffffu, s2, o);
        if (lane == 0) out[bq] = s2 + b_cls[0];
    }
}

// ---------------- host ----------------
static void gemm3(int MT, const bf16* A, long long sA, const bf16* W, long long sW,
                  const float* bias, float* C, int ldc, bf16* OS, long long sOS,
                  int M, int N, int K, int act, int accum, int mode, int pos, int epi) {
    dim3 grid((M + MT - 1) / MT, (N + 63) / 64);
    if (MT == 128)
        tc_gemm3<128><<<grid, 256>>>(A, sA, W, sW, bias, C, ldc, OS, sOS,
                                     M, N, K, act, accum, mode, pos, epi);
    else
        tc_gemm3<64><<<grid, 256>>>(A, sA, W, sW, bias, C, ldc, OS, sOS,
                                    M, N, K, act, accum, mode, pos, epi);
}

extern "C" void kernel_launch(void* const* d_in, const int* in_sizes, int n_in,
                              void* d_out, int out_size) {
    const float* feat   = (const float*)d_in[0];
    const float* pbi    = (const float*)d_in[1];
    const float* w_tf   = (const float*)d_in[2];
    const float* b_tf   = (const float*)d_in[3];
    const float* w_in   = (const float*)d_in[4];
    const float* b_in   = (const float*)d_in[5];
    const float* w_lat  = (const float*)d_in[6];
    const float* b_lat  = (const float*)d_in[7];
    const float* w_sm   = (const float*)d_in[8];
    const float* b_sm   = (const float*)d_in[9];
    const float* q_embed= (const float*)d_in[10];
    const float* q_pos  = (const float*)d_in[11];
    const float* Wq     = (const float*)d_in[12];
    const float* bqv    = (const float*)d_in[13];
    const float* Wo     = (const float*)d_in[14];
    const float* bo     = (const float*)d_in[15];
    const float* Wp1    = (const float*)d_in[16];
    const float* bp1    = (const float*)d_in[17];
    const float* Wp2    = (const float*)d_in[18];
    const float* bp2    = (const float*)d_in[19];
    const float* w_r1   = (const float*)d_in[20];
    const float* b_r1   = (const float*)d_in[21];
    const float* w_r2   = (const float*)d_in[22];
    const float* b_r2   = (const float*)d_in[23];
    const float* w_b1   = (const float*)d_in[24];
    const float* b_b1   = (const float*)d_in[25];
    const float* w_b2   = (const float*)d_in[26];
    const float* b_b2   = (const float*)d_in[27];
    const float* w_cls  = (const float*)d_in[28];
    const float* b_cls  = (const float*)d_in[29];
    float* out = (float*)d_out;

    float *p_bbig, *p_bo2, *p_f0, *p_kv, *p_q, *p_big, *p_pos;
    bf16 *p_coeffs, *p_w_ins, *p_vals, *p_WcTs, *p_wlats, *p_W2s, *p_wts, *p_Wp1s, *p_Wos, *p_wbigs;
    bf16 *p_xins, *p_ys, *p_flats, *p_qs, *p_aos;
    cudaGetSymbolAddress((void**)&p_bbig, g_bbig);
    cudaGetSymbolAddress((void**)&p_bo2, g_bo2);
    cudaGetSymbolAddress((void**)&p_f0, g_f0);
    cudaGetSymbolAddress((void**)&p_kv, g_kv);
    cudaGetSymbolAddress((void**)&p_q, g_q);
    cudaGetSymbolAddress((void**)&p_big, g_big);
    cudaGetSymbolAddress((void**)&p_pos, g_pos);
    cudaGetSymbolAddress((void**)&p_coeffs, g_coeffs);
    cudaGetSymbolAddress((void**)&p_w_ins, g_w_ins);
    cudaGetSymbolAddress((void**)&p_vals, g_vals);
    cudaGetSymbolAddress((void**)&p_WcTs, g_WcTs);
    cudaGetSymbolAddress((void**)&p_wlats, g_wlats);
    cudaGetSymbolAddress((void**)&p_W2s, g_W2s);
    cudaGetSymbolAddress((void**)&p_wts, g_wts);
    cudaGetSymbolAddress((void**)&p_Wp1s, g_Wp1s);
    cudaGetSymbolAddress((void**)&p_Wos, g_Wos);
    cudaGetSymbolAddress((void**)&p_wbigs, g_wbigs);
    cudaGetSymbolAddress((void**)&p_xins, g_xins);
    cudaGetSymbolAddress((void**)&p_ys, g_ys);
    cudaGetSymbolAddress((void**)&p_flats, g_flats);
    cudaGetSymbolAddress((void**)&p_qs, g_qs);
    cudaGetSymbolAddress((void**)&p_aos, g_aos);

    // ---- prep ----
    prep_coeff<<<(512 * 128 + 255) / 256, 256>>>(w_tf, b_tf, w_in, b_in);
    prep_wt<<<(KP1 * D + 255) / 256, 256>>>(w_sm);
    prep_wbig<<<(NLAY * 512 * D + 255) / 256, 256>>>(w_b1, b_b1, w_r1, b_r1);
    prep_val<<<(128 * 256 + 255) / 256, 256>>>();
    splitk2<<<(int)((S_WP1 + S_WLAT + 255) / 256), 256>>>(Wp1, p_Wp1s, S_WP1,
                                                          w_lat, p_wlats, S_WLAT);
    fold_weights<<<dim3(8, 8, 2 * NLAY), dim3(32, 8)>>>(Wp2, Wq, Wo);
    fold_bias<<<2 * NLAY + 1, 256>>>(Wp2, bqv, Wo, bp2, bo, w_lat, b_lat);
    // WcT = coeffA @ w_in^T  (M=512, N=256, K=128) -> split planes
    gemm3(64, p_coeffs, S_COEF, p_w_ins, S_WIN, nullptr, nullptr, 256, p_WcTs, S_WCT,
          512, 256, 128, 0, 0, 0, 0, 3);
    // W2 = w_lat @ WcT^T -> split planes
    gemm3(64, p_wlats, S_WLAT, p_WcTs, S_WCT, nullptr, nullptr, 512, p_W2s, S_W2,
          256, 512, 256, 0, 0, 0, 0, 3);
    // pos tables: [fh; gw] = vals @ w_lat^T  (M=128, N=256, K=256) -> fp32 g_pos
    gemm3(64, p_vals, S_VAL, p_wlats, S_WLAT, nullptr, p_pos, 256, nullptr, 0,
          128, 256, 256, 0, 0, 0, 0, 0);
    transposeA<<<dim3(128, 16, 2), dim3(32, 8)>>>(feat);

    // ---- backbone ----
    gemm3(128, p_xins, S_XIN, p_W2s, S_W2, nullptr, nullptr, 256, p_ys, S_Y,
          2 * HW, 256, 512, 0, 0, 0, 1, 3);
    gemm3(128, p_ys, S_Y, p_wts, S_WT, b_sm, p_f0, 256, nullptr, 0,
          2 * HW, 256, KP1, 0, 0, 1, 0, 0);

    init_all<<<(2 * NQ * D + 255) / 256, 256>>>(q_embed, q_pos, pbi);

    // pre-loop: h1,qp2 for layer 0 -> g_big cols 256..767 (relu only on h1)
    gemm3(64, p_qs, S_Q, p_wbigs + 256 * 256, S_WBIG, p_bbig + 256, p_big + 256, 768,
          nullptr, 0, 2 * NQ, 512, 256, 3, 0, 0, 0, 0);

    for (int l = 0; l < NLAY; l++) {
        rorefsample<<<2 * NQ, 256>>>(w_r2, b_r2, w_b2, b_b2, l > 0);
        // Wp1 + relu + mean_p -> fp32 pvm means in g_kv
        gemm3(64, p_flats, S_FLAT, p_Wp1s + (long long)l * 256 * KP1, S_WP1, bp1 + l * D,
              p_kv, 256, nullptr, 0, 2 * NQ * NP, 256, KP1, 0, 0, 0, 0, 1);
        attn_kernel<<<dim3(38, 2), 256>>>();
        // queries += WoP @ ao + bo2  (folded Wo@Wp2)
        gemm3(64, p_aos, S_AO, p_Wos + (long long)l * 256 * 256, S_WO, p_bo2 + l * 256,
              p_q, 256, p_qs, S_Q, 2 * NQ, 256, 256, 0, 1, 0, 0, 2);
        if (l < NLAY - 1) {
            gemm3(64, p_qs, S_Q, p_wbigs + (long long)(l + 1) * 768 * 256, S_WBIG,
                  p_bbig + (l + 1) * 768, p_big, 768, nullptr, 0,
                  2 * NQ, 768, 256, 2, 0, 0, 0, 0);
        } else {
            gemm3(64, p_qs, S_Q, p_wbigs, S_WBIG, p_bbig, p_big, 768, nullptr, 0,
                  2 * NQ, 256, 256, 1, 0, 0, 0, 0);
        }
    }

    final_kernel<<<2 * NQ, 128>>>(w_b2, b_b2, w_cls, b_cls, out);
}

// round 9
// speedup vs baseline: 1.4968x; 1.0548x over previous
#include <cuda_runtime.h>
#include <cuda_bf16.h>
#include <math.h>
#include <stdint.h>

#define D 256
#define HW 4096
#define NQ 300
#define NP 8
#define KP1 2304
#define NLAY 6

typedef __nv_bfloat16 bf16;

// plane strides
#define S_XIN ((long long)2 * HW * 512)
#define S_Y   ((long long)2 * HW * 256)
#define S_FLAT ((long long)2 * NQ * NP * KP1)
#define S_Q   ((long long)2 * NQ * 256)
#define S_W2  ((long long)256 * 512)
#define S_WT  ((long long)256 * KP1)
#define S_WP1 ((long long)NLAY * 256 * KP1)
#define S_WBIG ((long long)NLAY * 768 * 256)
#define S_WCT ((long long)512 * 256)
#define S_WLAT ((long long)256 * 256)
#define S_COEF ((long long)512 * 128)
#define S_WIN  ((long long)256 * 128)
#define S_VAL  ((long long)128 * 256)

// ---------------- scratch (device globals; no allocation) ----------------
__device__ float g_b2v[D];
__device__ float g_pos[128 * 256];      // rows 0..63 fh, 64..127 gw
__device__ float g_bbig[NLAY * 768];
__device__ float g_bo2[NLAY * 256];
__device__ float g_WoP[NLAY * 256 * 256];   // folded Wo@Wp2, fp32 [n][d]
// bf16 split planes (hi at 0, lo at +stride)
__device__ bf16 g_coeffs[2 * S_COEF];
__device__ bf16 g_w_ins[2 * S_WIN];
__device__ bf16 g_vals[2 * S_VAL];
__device__ bf16 g_WcTs[2 * S_WCT];
__device__ bf16 g_wlats[2 * S_WLAT];
__device__ bf16 g_W2s[2 * S_W2];
__device__ bf16 g_wts[2 * S_WT];
__device__ bf16 g_Wp1s[2 * S_WP1];
__device__ bf16 g_wbigs[2 * S_WBIG];   // [w_b1 | w_r1 | Wq2(l)]
__device__ bf16 g_xins[2 * S_XIN];
__device__ bf16 g_ys[2 * S_Y];
__device__ bf16 g_flats[2 * S_FLAT];
__device__ bf16 g_qs[2 * S_Q];
// fp32 tensors
__device__ float g_f0[2 * HW * D];
__device__ float g_q[2 * NQ * D];
__device__ float g_big[2 * NQ * 768];   // [hb | h1 | qp2]
__device__ float g_kv[2 * NQ * D];      // pvm means (attention operand)
__device__ float g_boxes[2 * NQ * 4];

__device__ __forceinline__ void wsplit(bf16* h, bf16* l, float v) {
    bf16 hh = __float2bfloat16(v);
    *h = hh;
    *l = __float2bfloat16(v - __bfloat162float(hh));
}
__device__ __forceinline__ uint32_t pack2(float x, float y) {
    __nv_bfloat162 t = __floats2bfloat162_rn(x, y);
    return *(uint32_t*)&t;
}

__device__ __forceinline__ void mma_bf16(float* c, const uint32_t* a, const uint32_t* b) {
    asm volatile(
        "mma.sync.aligned.m16n8k16.row.col.f32.bf16.bf16.f32 "
        "{%0,%1,%2,%3},{%4,%5,%6,%7},{%8,%9},{%0,%1,%2,%3};"
        : "+f"(c[0]), "+f"(c[1]), "+f"(c[2]), "+f"(c[3])
        : "r"(a[0]), "r"(a[1]), "r"(a[2]), "r"(a[3]), "r"(b[0]), "r"(b[1]));
}

__device__ __forceinline__ void cp16(void* dst, const void* src, int bytes) {
    uint32_t d = (uint32_t)__cvta_generic_to_shared(dst);
    asm volatile("cp.async.ca.shared.global [%0], [%1], 16, %2;\n" ::"r"(d), "l"(src), "r"(bytes));
}
__device__ __forceinline__ void cp_commit() { asm volatile("cp.async.commit_group;\n"); }
__device__ __forceinline__ void cp_wait2() { asm volatile("cp.async.wait_group 2;\n"); }
__device__ __forceinline__ void cp_wait1() { asm volatile("cp.async.wait_group 1;\n"); }
__device__ __forceinline__ void cp_wait0() { asm volatile("cp.async.wait_group 0;\n"); }

// ---------------- bf16x3 tensor-core GEMM, 3-stage cp.async pipeline ----------------
// act: 0 none, 1 relu, 2 relu n<512, 3 relu n<256.  pos: add pos tables.
// epi: 0 fp32 C; 1 relu+mean_p -> fp32 C (q rows); 3 split OS only.
template <int MT>
__global__ void __launch_bounds__(256, 2)
tc_gemm3(const bf16* __restrict__ A, long long sA,
         const bf16* __restrict__ W, long long sW,
         const float* __restrict__ bias, float* __restrict__ C, int ldc,
         bf16* __restrict__ OS, long long sOS,
         int M, int N, int K, int act, int accum, int mode, int pos, int epi) {
    constexpr int MSUB = MT / 4;
    constexpr int NMT = MT / 64;
    __shared__ uint32_t sAh[3][MT][12], sAl[3][MT][12];
    __shared__ uint32_t sBh[3][64][12], sBl[3][64][12];
    int m0 = blockIdx.x * MT, n0 = blockIdx.y * 64;
    int tid = threadIdx.x;
    int warp = tid >> 5, lane = tid & 31;
    int wm = warp >> 1, wn = warp & 1;
    int g = lane >> 2, r = lane & 3;
    float acc[NMT][4][4] = {};
    int nk = K >> 4;

    auto load = [&](int s, int k0) {
        if (MT == 128) {
            int row = tid >> 1, ch = tid & 1;
            int m = m0 + row;
            long long off = 0;
            int bytes = 0;
            if (mode == 0) {
                if (m < M) { off = (long long)m * K + k0 + ch * 8; bytes = 16; }
            } else {
                int tap = k0 >> 8;
                int dy = tap / 3 - 1, dx = tap % 3 - 1;
                int h = (m >> 6) & 63, w = m & 63;
                int hh = h + dy, ww = w + dx;
                if (m < M && (unsigned)hh < 64u && (unsigned)ww < 64u) {
                    off = (long long)(m + dy * 64 + dx) * 256 + (k0 & 255) + ch * 8;
                    bytes = 16;
                }
            }
            cp16(&sAh[s][row][ch * 4], A + off, bytes);
            cp16(&sAl[s][row][ch * 4], A + sA + off, bytes);
        } else {
            int p = tid >> 7;
            int row = (tid >> 1) & 63, ch = tid & 1;
            int m = m0 + row;
            long long off = 0;
            int bytes = 0;
            if (m < M) { off = (long long)m * K + k0 + ch * 8; bytes = 16; }
            if (p) cp16(&sAl[s][row][ch * 4], A + sA + off, bytes);
            else   cp16(&sAh[s][row][ch * 4], A + off, bytes);
        }
        {
            int p = tid >> 7;
            int row = (tid >> 1) & 63, ch = tid & 1;
            int n = n0 + row;
            const bf16* src = W;
            int bytes = 0;
            if (n < N) {
                src = W + (long long)p * sW + (long long)n * K + k0 + ch * 8;
                bytes = 16;
            }
            if (p) cp16(&sBl[s][row][ch * 4], src, bytes);
            else   cp16(&sBh[s][row][ch * 4], src, bytes);
        }
        cp_commit();
    };

    load(0, 0);
    if (nk > 1) load(1, 16);
    for (int kt = 0; kt < nk; kt++) {
        int cur = kt % 3;
        if (kt + 2 < nk) { load((kt + 2) % 3, (kt + 2) << 4); cp_wait2(); }
        else if (kt + 1 < nk) cp_wait1();
        else cp_wait0();
        __syncthreads();
        uint32_t ah[NMT][4], al[NMT][4], bh[4][2], bl[4][2];
#pragma unroll
        for (int mt = 0; mt < NMT; mt++) {
            int rb = wm * MSUB + mt * 16;
            ah[mt][0] = sAh[cur][rb + g][r];
            ah[mt][1] = sAh[cur][rb + g + 8][r];
            ah[mt][2] = sAh[cur][rb + g][r + 4];
            ah[mt][3] = sAh[cur][rb + g + 8][r + 4];
            al[mt][0] = sAl[cur][rb + g][r];
            al[mt][1] = sAl[cur][rb + g + 8][r];
            al[mt][2] = sAl[cur][rb + g][r + 4];
            al[mt][3] = sAl[cur][rb + g + 8][r + 4];
        }
#pragma unroll
        for (int nt = 0; nt < 4; nt++) {
            int cb = wn * 32 + nt * 8;
            bh[nt][0] = sBh[cur][cb + g][r];
            bh[nt][1] = sBh[cur][cb + g][r + 4];
            bl[nt][0] = sBl[cur][cb + g][r];
            bl[nt][1] = sBl[cur][cb + g][r + 4];
        }
#pragma unroll
        for (int mt = 0; mt < NMT; mt++)
#pragma unroll
            for (int nt = 0; nt < 4; nt++) {
                mma_bf16(acc[mt][nt], ah[mt], bh[nt]);
                mma_bf16(acc[mt][nt], al[mt], bh[nt]);
                mma_bf16(acc[mt][nt], ah[mt], bl[nt]);
            }
        __syncthreads();
    }

    if (epi == 1) {  // relu + mean over 8 points -> fp32 C[q][256]
#pragma unroll
        for (int mt = 0; mt < NMT; mt++) {
            int rbase = m0 + wm * MSUB + mt * 16;
#pragma unroll
            for (int nt = 0; nt < 4; nt++) {
                int n = n0 + wn * 32 + nt * 8 + 2 * r;
#pragma unroll
                for (int e = 0; e < 4; e++) {
                    int nn = n + (e & 1);
                    float v = fmaxf(acc[mt][nt][e] + bias[nn], 0.f);
                    v += __shfl_xor_sync(0xffffffffu, v, 4);
                    v += __shfl_xor_sync(0xffffffffu, v, 8);
                    v += __shfl_xor_sync(0xffffffffu, v, 16);
                    if (g == 0) {
                        int q = (rbase >> 3) + ((e >= 2) ? 1 : 0);
                        if (q < 2 * NQ) C[(long long)q * 256 + nn] = v * 0.125f;
                    }
                }
            }
        }
        return;
    }
#pragma unroll
    for (int mt = 0; mt < NMT; mt++) {
        int rbase = m0 + wm * MSUB + mt * 16;
#pragma unroll
        for (int nt = 0; nt < 4; nt++) {
            int cbase = n0 + wn * 32 + nt * 8 + 2 * r;
#pragma unroll
            for (int e = 0; e < 4; e++) {
                int m = rbase + g + ((e >= 2) ? 8 : 0);
                int n = cbase + (e & 1);
                if (m < M && n < N) {
                    float v = acc[mt][nt][e];
                    if (bias) v += bias[n];
                    if (act == 1 || (act == 2 && n < 512) || (act == 3 && n < 256))
                        v = fmaxf(v, 0.f);
                    if (pos) {
                        int hw = m & 4095;
                        v += g_pos[(hw >> 6) * 256 + n] + g_pos[16384 + (hw & 63) * 256 + n]
                           + g_b2v[n];
                    }
                    if (epi == 3) {
                        long long o = (long long)m * N + n;
                        wsplit(OS + o, OS + sOS + o, v);
                    } else {
                        if (accum) v += C[(long long)m * ldc + n];
                        C[(long long)m * ldc + n] = v;
                    }
                }
            }
        }
    }
}

// ---------------- MEGA-PREP: all independent prep work in one kernel ----------------
#define B0 256   // coeff split
#define B0C 128  // w_in split
#define B1 128   // val
#define B2 2304  // wt
#define B3 3072  // wbig rows 0..511
#define B3B 12   // wbig bias
#define B4 14080 // splitk Wp1+wlat
#define B5 768   // fold weights
#define B6 13    // fold bias
#define B7 600   // init q/boxes
#define NBLK (B0 + B0C + B1 + B2 + B3 + B3B + B4 + B5 + B6 + B7)

__global__ void megaprep(
    const float* __restrict__ w_tf, const float* __restrict__ b_tf,
    const float* __restrict__ w_in, const float* __restrict__ b_in,
    const float* __restrict__ w_sm,
    const float* __restrict__ w_b1, const float* __restrict__ b_b1,
    const float* __restrict__ w_r1, const float* __restrict__ b_r1,
    const float* __restrict__ Wp1, const float* __restrict__ w_lat,
    const float* __restrict__ Wp2, const float* __restrict__ Wq,
    const float* __restrict__ Wo,
    const float* __restrict__ bq, const float* __restrict__ bp2,
    const float* __restrict__ bo, const float* __restrict__ b_lat,
    const float* __restrict__ qe, const float* __restrict__ qp,
    const float* __restrict__ pbi) {
    __shared__ float As[32][33], Bs[32][33];
    int bb = blockIdx.x;
    int tid = threadIdx.x;

    if (bb < B0) {  // coeff split
        int idx = bb * 256 + tid;
        int row = idx >> 7, c = idx & 127;
        int s = row >> 7, i = row & 127;
        const float* w3 = w_tf + (c * 128 + i) * 3;
        float coeff;
        if (s == 0)      coeff = w3[0] + w3[1];
        else if (s == 3) coeff = w3[1] + w3[2];
        else             coeff = w3[0] + w3[1] + w3[2];
        wsplit(g_coeffs + idx, g_coeffs + S_COEF + idx, 0.25f * coeff);
        return;
    }
    bb -= B0;
    if (bb < B0C) {  // w_in split
        int idx = bb * 256 + tid;
        wsplit(g_w_ins + idx, g_w_ins + S_WIN + idx, w_in[idx]);
        return;
    }
    bb -= B0C;
    if (bb < B1) {  // sine value matrix
        int idx = bb * 256 + tid;
        int m = idx >> 8, c = idx & 255;
        float v = 0.f;
        int h = m & 63;
        bool lowhalf = (m < 64);
        int cc = lowhalf ? c : c - 128;
        if ((lowhalf && c < 128) || (!lowhalf && c >= 128)) {
            int i = cc >> 1;
            float fl = (float)(i >> 1);
            float dimt = exp2f(fl * 0.415241011861f);
            float arg = (float)(h + 1) * (6.2831853071795864769f / (64.f + 1e-6f)) / dimt;
            v = (cc & 1) ? __cosf(arg) : __sinf(arg);
        }
        wsplit(g_vals + idx, g_vals + S_VAL + idx, v);
        return;
    }
    bb -= B1;
    if (bb < B2) {  // conv weight repack+split
        int idx = bb * 256 + tid;
        int o = idx / KP1;
        int rr = idx % KP1;
        float v = w_sm[(o * D + (rr & 255)) * 9 + (rr >> 8)];
        wsplit(g_wts + idx, g_wts + S_WT + idx, v);
        return;
    }
    bb -= B2;
    if (bb < B3) {  // wbig rows 0..511
        int idx = bb * 256 + tid;
        int l = idx / (512 * D);
        int rr = idx % (512 * D);
        int n = rr >> 8;
        int k = rr & 255;
        float v = (n < 256) ? w_b1[n * 256 + k] : w_r1[(n - 256) * 256 + k];
        long long o = (long long)l * 768 * 256 + (long long)n * 256 + k;
        wsplit(g_wbigs + o, g_wbigs + S_WBIG + o, v);
        return;
    }
    bb -= B3;
    if (bb < B3B) {  // wbig biases rows 0..511
        int idx = bb * 256 + tid;
        int l = idx / 512, n = idx % 512;
        g_bbig[l * 768 + n] = (n < 256) ? b_b1[n] : b_r1[n - 256];
        return;
    }
    bb -= B3B;
    if (bb < B4) {  // split Wp1 then wlat
        long long i = (long long)bb * 256 + tid;
        if (i < S_WP1) { wsplit(g_Wp1s + i, g_Wp1s + S_WP1 + i, Wp1[i]); return; }
        i -= S_WP1;
        if (i < S_WLAT) wsplit(g_wlats + i, g_wlats + S_WLAT + i, w_lat[i]);
        return;
    }
    bb -= B4;
    if (bb < B5) {  // fold weights (32x8 layout)
        int l = bb / 64;
        int rem = bb % 64;
        int mode = l & 1;  // careful: original z = 2l+mode; here bb = z*64+rem
        // decode: z in 0..11, z = bb/64
        int z = bb / 64;
        l = z >> 1;
        mode = z & 1;
        int c0 = (rem & 7) * 32, r0 = (rem >> 3) * 32;
        int tx = tid & 31, ty = tid >> 5;
        const float* P = Wp2 + (long long)l * 65536;
        float acc[4] = {};
        for (int ko = 0; ko < 256; ko += 32) {
#pragma unroll
            for (int t = 0; t < 4; t++) {
                int i = ty * 4 + t;
                Bs[i][tx] = P[(ko + i) * 256 + c0 + tx];
                if (mode == 0) As[i][tx] = Wq[(long long)l * 65536 + (ko + i) * 256 + r0 + tx];
                else           As[tx][i] = Wo[(long long)l * 65536 + (r0 + i) * 256 + ko + tx];
            }
            __syncthreads();
#pragma unroll
            for (int i = 0; i < 32; i++) {
                float bv = Bs[i][tx];
                acc[0] += As[i][ty] * bv;
                acc[1] += As[i][ty + 8] * bv;
                acc[2] += As[i][ty + 16] * bv;
                acc[3] += As[i][ty + 24] * bv;
            }
            __syncthreads();
        }
#pragma unroll
        for (int e = 0; e < 4; e++) {
            int row = r0 + ty + 8 * e;
            int col = c0 + tx;
            if (mode == 0) {
                long long o = (long long)l * 768 * 256 + (long long)(512 + col) * 256 + row;
                wsplit(g_wbigs + o, g_wbigs + S_WBIG + o, acc[e]);
            } else {
                g_WoP[(long long)l * 65536 + (long long)row * 256 + col] = acc[e];
            }
        }
        return;
    }
    bb -= B5;
    if (bb < B6) {  // fold biases
        float* vec = &Bs[0][0];     // 256 floats
        float* loc = &As[0][0];
        int t = tid;
        if (bb == 2 * NLAY) {  // b2v (recompute biasc locally)
            float a = b_in[t];
            for (int c = 0; c < 128; c++) a += w_in[t * 128 + c] * b_tf[c];
            loc[t] = a;
            __syncthreads();
            float s = b_lat[t];
            for (int c = 0; c < 256; c++) s += w_lat[t * 256 + c] * loc[c];
            g_b2v[t] = s;
            return;
        }
        int l = bb >> 1;
        if ((bb & 1) == 0) {
            vec[t] = bq[l * 256 + t];
            __syncthreads();
            float s = 0.f;
            for (int o = 0; o < 256; o++) s += Wp2[(long long)l * 65536 + o * 256 + t] * vec[o];
            g_bbig[l * 768 + 512 + t] = s;
        } else {
            vec[t] = bp2[l * 256 + t];
            __syncthreads();
            float s = bo[l * 256 + t];
            for (int o = 0; o < 256; o++) s += Wo[(long long)l * 65536 + t * 256 + o] * vec[o];
            g_bo2[l * 256 + t] = s;
        }
        return;
    }
    bb -= B6;
    {  // init q + boxes
        int idx = bb * 256 + tid;
        if (idx < 2 * NQ * D) {
            int qd = idx % (NQ * D);
            float v = qe[qd] + qp[qd];
            g_q[idx] = v;
            wsplit(g_qs + idx, g_qs + S_Q + idx, v);
        }
        if (idx < 2 * NQ * 4) g_boxes[idx] = pbi[idx];
    }
}

// transpose feat [b][512][4096] -> split planes [b*4096][512]
__global__ void transposeA(const float* __restrict__ feat) {
    __shared__ float t[32][33];
    int b = blockIdx.z;
    int hw0 = blockIdx.x * 32, k0 = blockIdx.y * 32;
    const float* src = feat + (long long)b * 512 * HW;
    int tx = threadIdx.x, ty = threadIdx.y;
#pragma unroll
    for (int j = 0; j < 4; j++)
        t[ty + j * 8][tx] = src[(long long)(k0 + ty + j * 8) * HW + hw0 + tx];
    __syncthreads();
#pragma unroll
    for (int j = 0; j < 4; j++) {
        long long o = (long long)(b * HW + hw0 + ty + j * 8) * 512 + k0 + tx;
        wsplit(g_xins + o, g_xins + S_XIN + o, t[tx][ty + j * 8]);
    }
}

// ---------------- fused boxupd + roref + vectorized bilinear sample ----------------
__global__ void rorefsample(const float* __restrict__ w_r2, const float* __restrict__ b_r2,
                            const float* __restrict__ w_b2, const float* __restrict__ b_b2,
                            int do_box) {
    int bq = blockIdx.x;
    int tid = threadIdx.x;
    int warp = tid >> 5, lane = tid & 31;
    __shared__ float h1row[256], hbrow[256], ro[16], refs[16], boxsh[2];
    __shared__ int   soff[72][4];
    __shared__ float swgt[72][4];
    h1row[tid] = g_big[bq * 768 + 256 + tid];
    if (do_box) hbrow[tid] = g_big[bq * 768 + tid];
    else if (tid < 2) boxsh[tid] = g_boxes[bq * 4 + tid];
    __syncthreads();
    if (do_box && warp < 4) {
        float s = 0.f;
        for (int k = lane; k < 256; k += 32) s += hbrow[k] * w_b2[warp * 256 + k];
#pragma unroll
        for (int o = 16; o; o >>= 1) s += __shfl_xor_sync(0xffffffffu, s, o);
        if (lane == 0) {
            float delta = 1.f / (1.f + expf(-(s + b_b2[warp])));
            float nb = g_boxes[bq * 4 + warp] + 0.1f * tanhf(delta - 0.5f);
            nb = fminf(fmaxf(nb, 0.f), 1.f);
            g_boxes[bq * 4 + warp] = nb;
            if (warp < 2) boxsh[warp] = nb;
        }
    }
#pragma unroll
    for (int jj = 0; jj < 2; jj++) {
        int j = warp * 2 + jj;
        float s = 0.f;
        for (int k = lane; k < 256; k += 32) s += h1row[k] * w_r2[j * 256 + k];
#pragma unroll
        for (int o = 16; o; o >>= 1) s += __shfl_xor_sync(0xffffffffu, s, o);
        if (lane == 0) ro[j] = tanhf(s + b_r2[j]);
    }
    __syncthreads();
    if (tid < 8) {
        refs[2 * tid + 0] = fminf(fmaxf(boxsh[0] + 0.5f * ro[2 * tid + 0], 0.f), 1.f);
        refs[2 * tid + 1] = fminf(fmaxf(boxsh[1] + 0.5f * ro[2 * tid + 1], 0.f), 1.f);
    }
    __syncthreads();
    // precompute 72 (p, tap) bilinear coords
    if (tid < 72) {
        int p = tid / 9, tap = tid % 9;
        int cy = tap / 3, cx = tap % 3;
        float ry = refs[2 * p + 1], rx = refs[2 * p];
        float gy = ry * 2.f - 1.f + (float)(cy - 1) * (2.f / 64.f);
        float yy = fminf(fmaxf((gy + 1.f) * 0.5f * 63.f, 0.f), 63.f);
        float y0f = floorf(yy);
        int y0 = (int)y0f;
        float wy = yy - y0f;
        int y1 = min(y0 + 1, 63);
        float gx = rx * 2.f - 1.f + (float)(cx - 1) * (2.f / 64.f);
        float xx = fminf(fmaxf((gx + 1.f) * 0.5f * 63.f, 0.f), 63.f);
        float x0f = floorf(xx);
        int x0 = (int)x0f;
        float wx = xx - x0f;
        int x1 = min(x0 + 1, 63);
        soff[tid][0] = ((y0 << 6) + x0) << 7;   // float2 index base (pos*256/2)
        soff[tid][1] = ((y0 << 6) + x1) << 7;
        soff[tid][2] = ((y1 << 6) + x0) << 7;
        soff[tid][3] = ((y1 << 6) + x1) << 7;
        swgt[tid][0] = (1.f - wx) * (1.f - wy);
        swgt[tid][1] = wx * (1.f - wy);
        swgt[tid][2] = (1.f - wx) * wy;
        swgt[tid][3] = wx * wy;
    }
    __syncthreads();
    int b = bq / NQ;
    const float2* f2 = (const float2*)(g_f0 + (long long)b * HW * D);
    long long qbase = (long long)bq * NP * KP1;
#pragma unroll
    for (int it = 0; it < 36; it++) {
        int idx = tid + it * 256;         // 0..9215
        int t72 = idx >> 7, c2 = idx & 127;
        float w00 = swgt[t72][0], w01 = swgt[t72][1], w10 = swgt[t72][2], w11 = swgt[t72][3];
        float2 v00 = f2[soff[t72][0] + c2];
        float2 v01 = f2[soff[t72][1] + c2];
        float2 v10 = f2[soff[t72][2] + c2];
        float2 v11 = f2[soff[t72][3] + c2];
        float vx = v00.x * w00 + v01.x * w01 + v10.x * w10 + v11.x * w11;
        float vy = v00.y * w00 + v01.y * w01 + v10.y * w10 + v11.y * w11;
        int p = t72 / 9, tap = t72 % 9;
        long long o = qbase + (long long)p * KP1 + tap * 256 + 2 * c2;
        bf16 hx = __float2bfloat16(vx), hy = __float2bfloat16(vy);
        *(uint32_t*)(g_flats + o) = pack2(vx, vy);
        float rxl = vx - __bfloat162float(hx), ryl = vy - __bfloat162float(hy);
        *(uint32_t*)(g_flats + S_FLAT + o) = pack2(rxl, ryl);
    }
}

// ---------------- fused attention + Wo projection ----------------
__global__ void attn_kernel(const float* __restrict__ WoP, const float* __restrict__ bo2) {
    __shared__ float qs[8][260];
    __shared__ float kvs[16][264];
    __shared__ float tr[8][528];
    int b = blockIdx.y, qt = blockIdx.x;
    int tid = threadIdx.x;
    int warp = tid >> 5, lane = tid & 31;
    const float* kvb = g_kv + (long long)b * NQ * D;
#pragma unroll
    for (int i = 0; i < 8; i++) {
        int idx = tid + i * 256;
        int qi = idx >> 8, c = idx & 255;
        int q = qt * 8 + qi;
        qs[qi][c] = (q < NQ) ? g_big[((long long)b * NQ + q) * 768 + 512 + c] : 0.f;
    }
    float sc[19];
#pragma unroll
    for (int kt = 0; kt < 19; kt++) {
        __syncthreads();
#pragma unroll
        for (int i = 0; i < 4; i++) {
            int lin = tid + i * 256;        // 0..1023 float4s
            int j = lin >> 6, c4 = (lin & 63) * 4;
            int key = kt * 16 + j;
            float4 v = make_float4(0.f, 0.f, 0.f, 0.f);
            if (key < NQ) v = *(const float4*)(kvb + (long long)key * D + c4);
            kvs[j][c4] = v.x; kvs[j][c4 + 1] = v.y; kvs[j][c4 + 2] = v.z; kvs[j][c4 + 3] = v.w;
        }
        __syncthreads();
        float p[16] = {};
#pragma unroll
        for (int i = 0; i < 8; i++) {
            float qv = qs[warp][i * 32 + lane];
#pragma unroll
            for (int j = 0; j < 16; j++) p[j] += qv * kvs[j][i * 32 + lane];
        }
#pragma unroll
        for (int j = 0; j < 16; j++) tr[warp][j * 33 + lane] = p[j];
        __syncwarp();
        if (lane < 16) {
            float s = 0.f;
#pragma unroll
            for (int x = 0; x < 32; x++) s += tr[warp][lane * 33 + x];
            sc[kt] = (kt * 16 + lane < NQ) ? s * 0.0625f : -1e30f;
        }
        __syncwarp();
    }
    float m = -1e30f;
    if (lane < 16) {
#pragma unroll
        for (int kt = 0; kt < 19; kt++) m = fmaxf(m, sc[kt]);
    }
#pragma unroll
    for (int o = 16; o; o >>= 1) m = fmaxf(m, __shfl_xor_sync(0xffffffffu, m, o));
    float sum = 0.f;
    if (lane < 16) {
#pragma unroll
        for (int kt = 0; kt < 19; kt++) {
            float e = expf(sc[kt] - m);
            sc[kt] = e;
            sum += e;
        }
    }
#pragma unroll
    for (int o = 16; o; o >>= 1) sum += __shfl_xor_sync(0xffffffffu, sum, o);
    float inv = 1.f / sum;
    if (lane < 16) {
#pragma unroll
        for (int kt = 0; kt < 19; kt++) tr[warp][kt * 16 + lane] = sc[kt] * inv;
    }
    __syncwarp();
    float out[8] = {};
#pragma unroll
    for (int kt = 0; kt < 19; kt++) {
        __syncthreads();
#pragma unroll
        for (int i = 0; i < 4; i++) {
            int lin = tid + i * 256;
            int j = lin >> 6, c4 = (lin & 63) * 4;
            int key = kt * 16 + j;
            float4 v = make_float4(0.f, 0.f, 0.f, 0.f);
            if (key < NQ) v = *(const float4*)(kvb + (long long)key * D + c4);
            kvs[j][c4] = v.x; kvs[j][c4 + 1] = v.y; kvs[j][c4 + 2] = v.z; kvs[j][c4 + 3] = v.w;
        }
        __syncthreads();
#pragma unroll
        for (int j = 0; j < 16; j++) {
            float a = tr[warp][kt * 16 + j];
#pragma unroll
            for (int i = 0; i < 8; i++) out[i] += a * kvs[j][i * 32 + lane];
        }
    }
    // ao -> smem (reuse qs), then Delta q = WoP @ ao, q += Dq + bo2
#pragma unroll
    for (int i = 0; i < 8; i++) qs[warp][i * 32 + lane] = out[i];
    float dq[8] = {};
#pragma unroll
    for (int kt = 0; kt < 16; kt++) {
        __syncthreads();
#pragma unroll
        for (int i = 0; i < 4; i++) {
            int lin = tid + i * 256;      // 0..1023
            int n = lin >> 2, qd = lin & 3;
            float4 v = *(const float4*)(WoP + (long long)n * 256 + kt * 16 + qd * 4);
            kvs[qd * 4 + 0][n] = v.x;
            kvs[qd * 4 + 1][n] = v.y;
            kvs[qd * 4 + 2][n] = v.z;
            kvs[qd * 4 + 3][n] = v.w;
        }
        __syncthreads();
#pragma unroll
        for (int k = 0; k < 16; k++) {
            float a = qs[warp][kt * 16 + k];
#pragma unroll
            for (int j = 0; j < 8; j++) dq[j] += a * kvs[k][lane + j * 32];
        }
    }
    int q = qt * 8 + warp;
    if (q < NQ) {
#pragma unroll
        for (int j = 0; j < 8; j++) {
            int n = lane + j * 32;
            long long o = ((long long)b * NQ + q) * D + n;
            float v = g_q[o] + dq[j] + bo2[n];
            g_q[o] = v;
            wsplit(g_qs + o, g_qs + S_Q + o, v);
        }
    }
}

// ---------------- final: last boxupd + cls + box copy ----------------
__global__ void final_kernel(const float* __restrict__ w_b2, const float* __restrict__ b_b2,
                             const float* __restrict__ w_cls, const float* __restrict__ b_cls,
                             float* __restrict__ out) {
    int bq = blockIdx.x;
    int tid = threadIdx.x;  // 128
    int warp = tid >> 5, lane = tid & 31;
    __shared__ float hrow[256];
    hrow[tid] = g_big[bq * 768 + tid];
    hrow[tid + 128] = g_big[bq * 768 + 128 + tid];
    __syncthreads();
    float s = 0.f;
    for (int k = lane; k < 256; k += 32) s += hrow[k] * w_b2[warp * 256 + k];
#pragma unroll
    for (int o = 16; o; o >>= 1) s += __shfl_xor_sync(0xffffffffu, s, o);
    if (lane == 0) {
        float delta = 1.f / (1.f + expf(-(s + b_b2[warp])));
        float nb = g_boxes[bq * 4 + warp] + 0.1f * tanhf(delta - 0.5f);
        out[600 + bq * 4 + warp] = fminf(fmaxf(nb, 0.f), 1.f);
    }
    if (warp == 0) {
        float s2 = 0.f;
        for (int k = lane; k < 256; k += 32) s2 += g_q[bq * 256 + k] * w_cls[k];
#pragma unroll
        for (int o = 16; o; o >>= 1) s2 += __shfl_xor_sync(0xffffffffu, s2, o);
        if (lane == 0) out[bq] = s2 + b_cls[0];
    }
}

// ---------------- host ----------------
static void gemm3(int MT, const bf16* A, long long sA, const bf16* W, long long sW,
                  const float* bias, float* C, int ldc, bf16* OS, long long sOS,
                  int M, int N, int K, int act, int accum, int mode, int pos, int epi) {
    dim3 grid((M + MT - 1) / MT, (N + 63) / 64);
    if (MT == 128)
        tc_gemm3<128><<<grid, 256>>>(A, sA, W, sW, bias, C, ldc, OS, sOS,
                                     M, N, K, act, accum, mode, pos, epi);
    else
        tc_gemm3<64><<<grid, 256>>>(A, sA, W, sW, bias, C, ldc, OS, sOS,
                                    M, N, K, act, accum, mode, pos, epi);
}

extern "C" void kernel_launch(void* const* d_in, const int* in_sizes, int n_in,
                              void* d_out, int out_size) {
    const float* feat   = (const float*)d_in[0];
    const float* pbi    = (const float*)d_in[1];
    const float* w_tf   = (const float*)d_in[2];
    const float* b_tf   = (const float*)d_in[3];
    const float* w_in   = (const float*)d_in[4];
    const float* b_in   = (const float*)d_in[5];
    const float* w_lat  = (const float*)d_in[6];
    const float* b_lat  = (const float*)d_in[7];
    const float* w_sm   = (const float*)d_in[8];
    const float* b_sm   = (const float*)d_in[9];
    const float* q_embed= (const float*)d_in[10];
    const float* q_pos  = (const float*)d_in[11];
    const float* Wq     = (const float*)d_in[12];
    const float* bqv    = (const float*)d_in[13];
    const float* Wo     = (const float*)d_in[14];
    const float* bo     = (const float*)d_in[15];
    const float* Wp1    = (const float*)d_in[16];
    const float* bp1    = (const float*)d_in[17];
    const float* Wp2    = (const float*)d_in[18];
    const float* bp2    = (const float*)d_in[19];
    const float* w_r1   = (const float*)d_in[20];
    const float* b_r1   = (const float*)d_in[21];
    const float* w_r2   = (const float*)d_in[22];
    const float* b_r2   = (const float*)d_in[23];
    const float* w_b1   = (const float*)d_in[24];
    const float* b_b1   = (const float*)d_in[25];
    const float* w_b2   = (const float*)d_in[26];
    const float* b_b2   = (const float*)d_in[27];
    const float* w_cls  = (const float*)d_in[28];
    const float* b_cls  = (const float*)d_in[29];
    float* out = (float*)d_out;

    float *p_bbig, *p_bo2, *p_f0, *p_kv, *p_q, *p_big, *p_pos, *p_WoP;
    bf16 *p_coeffs, *p_w_ins, *p_vals, *p_WcTs, *p_wlats, *p_W2s, *p_wts, *p_Wp1s, *p_wbigs;
    bf16 *p_xins, *p_ys, *p_flats, *p_qs;
    cudaGetSymbolAddress((void**)&p_bbig, g_bbig);
    cudaGetSymbolAddress((void**)&p_bo2, g_bo2);
    cudaGetSymbolAddress((void**)&p_f0, g_f0);
    cudaGetSymbolAddress((void**)&p_kv, g_kv);
    cudaGetSymbolAddress((void**)&p_q, g_q);
    cudaGetSymbolAddress((void**)&p_big, g_big);
    cudaGetSymbolAddress((void**)&p_pos, g_pos);
    cudaGetSymbolAddress((void**)&p_WoP, g_WoP);
    cudaGetSymbolAddress((void**)&p_coeffs, g_coeffs);
    cudaGetSymbolAddress((void**)&p_w_ins, g_w_ins);
    cudaGetSymbolAddress((void**)&p_vals, g_vals);
    cudaGetSymbolAddress((void**)&p_WcTs, g_WcTs);
    cudaGetSymbolAddress((void**)&p_wlats, g_wlats);
    cudaGetSymbolAddress((void**)&p_W2s, g_W2s);
    cudaGetSymbolAddress((void**)&p_wts, g_wts);
    cudaGetSymbolAddress((void**)&p_Wp1s, g_Wp1s);
    cudaGetSymbolAddress((void**)&p_wbigs, g_wbigs);
    cudaGetSymbolAddress((void**)&p_xins, g_xins);
    cudaGetSymbolAddress((void**)&p_ys, g_ys);
    cudaGetSymbolAddress((void**)&p_flats, g_flats);
    cudaGetSymbolAddress((void**)&p_qs, g_qs);

    // ---- prep ----
    transposeA<<<dim3(128, 16, 2), dim3(32, 8)>>>(feat);
    megaprep<<<NBLK, 256>>>(w_tf, b_tf, w_in, b_in, w_sm, w_b1, b_b1, w_r1, b_r1,
                            Wp1, w_lat, Wp2, Wq, Wo, bqv, bp2, bo, b_lat,
                            q_embed, q_pos, pbi);
    // pre-loop: h1,qp2 for layer 0 (needs qs + wbigs from megaprep)
    gemm3(64, p_qs, S_Q, p_wbigs + 256 * 256, S_WBIG, p_bbig + 256, p_big + 256, 768,
          nullptr, 0, 2 * NQ, 512, 256, 3, 0, 0, 0, 0);
    // WcT = coeffA @ w_in^T
    gemm3(64, p_coeffs, S_COEF, p_w_ins, S_WIN, nullptr, nullptr, 256, p_WcTs, S_WCT,
          512, 256, 128, 0, 0, 0, 0, 3);
    // W2 = w_lat @ WcT^T
    gemm3(64, p_wlats, S_WLAT, p_WcTs, S_WCT, nullptr, nullptr, 512, p_W2s, S_W2,
          256, 512, 256, 0, 0, 0, 0, 3);
    // pos tables
    gemm3(64, p_vals, S_VAL, p_wlats, S_WLAT, nullptr, p_pos, 256, nullptr, 0,
          128, 256, 256, 0, 0, 0, 0, 0);

    // ---- backbone ----
    gemm3(128, p_xins, S_XIN, p_W2s, S_W2, nullptr, nullptr, 256, p_ys, S_Y,
          2 * HW, 256, 512, 0, 0, 0, 1, 3);
    gemm3(128, p_ys, S_Y, p_wts, S_WT, b_sm, p_f0, 256, nullptr, 0,
          2 * HW, 256, KP1, 0, 0, 1, 0, 0);

    for (int l = 0; l < NLAY; l++) {
        rorefsample<<<2 * NQ, 256>>>(w_r2, b_r2, w_b2, b_b2, l > 0);
        // Wp1 + relu + mean_p -> fp32 pvm means in g_kv
        gemm3(128, p_flats, S_FLAT, p_Wp1s + (long long)l * 256 * KP1, S_WP1, bp1 + l * D,
              p_kv, 256, nullptr, 0, 2 * NQ * NP, 256, KP1, 0, 0, 0, 0, 1);
        // attention + folded Wo projection: q += WoP@ao + bo2
        attn_kernel<<<dim3(38, 2), 256>>>(p_WoP + (long long)l * 65536, p_bo2 + l * 256);
        if (l < NLAY - 1) {
            gemm3(64, p_qs, S_Q, p_wbigs + (long long)(l + 1) * 768 * 256, S_WBIG,
                  p_bbig + (l + 1) * 768, p_big, 768, nullptr, 0,
                  2 * NQ, 768, 256, 2, 0, 0, 0, 0);
        } else {
            gemm3(64, p_qs, S_Q, p_wbigs, S_WBIG, p_bbig, p_big, 768, nullptr, 0,
                  2 * NQ, 256, 256, 1, 0, 0, 0, 0);
        }
    }

    final_kernel<<<2 * NQ, 128>>>(w_b2, b_b2, w_cls, b_cls, out);
}